// round 3
// baseline (speedup 1.0000x reference)
#include <cuda_runtime.h>

#define BB 8
#define DD 128
#define TT 32768
#define CC 64

typedef unsigned long long ull;

// ---------------- f32x2 packed-FMA helpers (sm_103a FFMA2 path) ----------------
__device__ __forceinline__ void ffma2(ull& d, ull a, ull b) {
    asm("fma.rn.f32x2 %0, %1, %2, %0;" : "+l"(d) : "l"(a), "l"(b));
}
__device__ __forceinline__ ull pk2(float lo, float hi) {
    ull r; asm("mov.b64 %0, {%1, %2};" : "=l"(r) : "f"(lo), "f"(hi)); return r;
}
__device__ __forceinline__ float2 upk(ull v) {
    float2 r; asm("mov.b64 {%0, %1}, %2;" : "=f"(r.x), "=f"(r.y) : "l"(v)); return r;
}

// ---------------- scratch (static device globals; no allocation) ----------------
__device__ float g_G[BB * DD * DD];     // per-batch Gram (UPPER 8x8 tiles valid)
__device__ float g_s[BB * DD];          // per-batch row sums of x over t
__device__ float g_Bm[CC * DD];         // we @ wk
__device__ float g_F[CC * DD];          // wf @ wv
__device__ float g_k0[CC];              // we @ bk + be
__device__ float g_v0[CC];              // wf @ bv + bf
__device__ float g_wot[CC * DD];        // wo transposed: [c][o]
__device__ float g_Mt[BB * DD * CC];    // M_b transposed: [b][d][c]
__device__ float g_cv[BB * CC];         // P_b @ v0

// ================= K1: symmetric Gram (upper-tri 8x8 tiles) + row sums =================
// grid (32, 8), 288 threads. 272 active = 136 upper tiles x 2 k-halves.
// xs: [t][d] for b-frags (paired); xsd: [t][2d] duplicated for a-frags (LDS.64 dups).
__global__ __launch_bounds__(288, 2) void k1_gram(const float* __restrict__ x) {
    extern __shared__ float sm1[];
    float* xs  = sm1;               // 32 x 132
    float* xsd = sm1 + 32 * 132;    // 32 x 264
    const int b   = blockIdx.y;
    const int t0  = blockIdx.x * 1024;
    const int tid = threadIdx.x;
    const float* xb = x + (size_t)b * DD * TT;

    // unrank tile pair index p -> (ti, tj), ti <= tj, among 16x16 tiles
    const int  p   = tid >> 1;
    const int  h   = tid & 1;
    const bool act = (tid < 272);
    int ti = 0, tj = 0;
    {
        int rem = act ? p : 0;
        for (int r = 0; r < 16; r++) {
            int w = 16 - r;
            if (rem >= w) rem -= w;
            else { ti = r; tj = r + rem; break; }
        }
    }
    const int a0 = ti * 8, b0 = tj * 8;

    // loader assignments (fixed across chunks)
    int  dmv[4], tlv[4]; bool val[4];
#pragma unroll
    for (int m = 0; m < 4; m++) {
        int i = tid + 288 * m;
        val[m] = (i < 1024);
        dmv[m] = val[m] ? (i >> 3) : 0;
        tlv[m] = (i & 7) << 2;
    }

    ull acc[8][4];
#pragma unroll
    for (int i = 0; i < 8; i++)
#pragma unroll
        for (int j = 0; j < 4; j++) acc[i][j] = 0ull;
    float srow[4] = {0.f, 0.f, 0.f, 0.f};

    for (int kt = 0; kt < 32; kt++) {
        const int tb = t0 + kt * 32;
#pragma unroll
        for (int m = 0; m < 4; m++) {
            if (val[m]) {
                int d = dmv[m], tl = tlv[m];
                float4 v = *reinterpret_cast<const float4*>(xb + (size_t)d * TT + tb + tl);
                srow[m] += (v.x + v.y) + (v.z + v.w);
                xs[(tl + 0) * 132 + d] = v.x;
                xs[(tl + 1) * 132 + d] = v.y;
                xs[(tl + 2) * 132 + d] = v.z;
                xs[(tl + 3) * 132 + d] = v.w;
                *reinterpret_cast<ull*>(&xsd[(tl + 0) * 264 + 2 * d]) = pk2(v.x, v.x);
                *reinterpret_cast<ull*>(&xsd[(tl + 1) * 264 + 2 * d]) = pk2(v.y, v.y);
                *reinterpret_cast<ull*>(&xsd[(tl + 2) * 264 + 2 * d]) = pk2(v.z, v.z);
                *reinterpret_cast<ull*>(&xsd[(tl + 3) * 264 + 2 * d]) = pk2(v.w, v.w);
            }
        }
        __syncthreads();
        if (act) {
            const int kbase = h * 16;
#pragma unroll
            for (int kk = 0; kk < 16; kk++) {
                const int k = kbase + kk;
                ull ad[8];
#pragma unroll
                for (int i = 0; i < 8; i++)
                    ad[i] = *reinterpret_cast<const ull*>(&xsd[k * 264 + 2 * (a0 + i)]);
                float4 q0 = *reinterpret_cast<const float4*>(&xs[k * 132 + b0]);
                float4 q1 = *reinterpret_cast<const float4*>(&xs[k * 132 + b0 + 4]);
                ull bp0 = pk2(q0.x, q0.y), bp1 = pk2(q0.z, q0.w);
                ull bp2 = pk2(q1.x, q1.y), bp3 = pk2(q1.z, q1.w);
#pragma unroll
                for (int i = 0; i < 8; i++) {
                    ffma2(acc[i][0], ad[i], bp0);
                    ffma2(acc[i][1], ad[i], bp1);
                    ffma2(acc[i][2], ad[i], bp2);
                    ffma2(acc[i][3], ad[i], bp3);
                }
            }
        }
        __syncthreads();
    }

    if (act) {
        float* Gb = g_G + b * DD * DD;
#pragma unroll
        for (int i = 0; i < 8; i++)
#pragma unroll
            for (int j = 0; j < 4; j++) {
                float2 v = upk(acc[i][j]);
                atomicAdd(&Gb[(a0 + i) * DD + b0 + 2 * j],     v.x);
                atomicAdd(&Gb[(a0 + i) * DD + b0 + 2 * j + 1], v.y);
            }
    }
#pragma unroll
    for (int m = 0; m < 4; m++)
        if (val[m]) atomicAdd(&g_s[b * DD + dmv[m]], srow[m]);
}

// ============ K2a: batch-independent weight products (grid 16) ============
__global__ void k2a_weights(const float* __restrict__ we, const float* __restrict__ wk,
                            const float* __restrict__ bk, const float* __restrict__ be,
                            const float* __restrict__ wf, const float* __restrict__ wv,
                            const float* __restrict__ bv, const float* __restrict__ bf,
                            const float* __restrict__ wo) {
    const int j = blockIdx.x, tid = threadIdx.x;
    if (j < 8) {
#pragma unroll
        for (int it = 0; it < 4; it++) {
            int idx = tid + 256 * it;
            int o = j * 8 + (idx >> 7);
            int d = idx & 127;
            float acc = 0.f;
            for (int c = 0; c < CC; c++) acc = fmaf(we[o * CC + c], wk[c * DD + d], acc);
            g_Bm[o * DD + d] = acc;
        }
        if (j == 0 && tid < CC) {
            float acc = be[tid];
            for (int c = 0; c < CC; c++) acc = fmaf(we[tid * CC + c], bk[c], acc);
            g_k0[tid] = acc;
        }
        if (j == 1) {
#pragma unroll
            for (int it = 0; it < 32; it++) {
                int idx = tid + 256 * it;
                int c = idx >> 7, o = idx & 127;
                g_wot[c * DD + o] = wo[o * CC + c];
            }
        }
    } else {
        int jj = j - 8;
#pragma unroll
        for (int it = 0; it < 4; it++) {
            int idx = tid + 256 * it;
            int o = jj * 8 + (idx >> 7);
            int d = idx & 127;
            float acc = 0.f;
            for (int c = 0; c < CC; c++) acc = fmaf(wf[o * CC + c], wv[c * DD + d], acc);
            g_F[o * DD + d] = acc;
        }
        if (j == 8 && tid < CC) {
            float acc = bf[tid];
            for (int c = 0; c < CC; c++) acc = fmaf(wf[tid * CC + c], bv[c], acc);
            g_v0[tid] = acc;
        }
    }
}

// ============ K2c: AG + S + softmax + M + cv, fused. grid (8 c-groups, 8 b) ============
#define KPAD 132
__global__ void k2c_attn(const float* __restrict__ wq, const float* __restrict__ bq) {
    extern __shared__ float sm2[];
    float* Gs  = sm2;                  // 128 x KPAD
    float* Bms = Gs  + DD * KPAD;      //  64 x KPAD
    float* Fs  = Bms + CC * KPAD;      //  64 x KPAD
    float* wqs = Fs  + CC * KPAD;      //   8 x KPAD
    float* AGs = wqs + 8 * KPAD;       //   8 x KPAD
    float* Ps  = AGs + 8 * KPAD;       //   8 x 64
    float* ss  = Ps  + 8 * CC;         // 128
    float* bs  = ss  + DD;             //  64
    float* k0s = bs  + CC;             //  64
    float* v0s = k0s + CC;             //  64
    float* qs  = v0s + CC;             //   8
    float* bqs = qs  + 8;              //   8
    const int cg = blockIdx.x, b = blockIdx.y, tid = threadIdx.x;

    // ---- Gs: mirror-on-load (g_G holds upper triangle only) ----
    const float* Gb = g_G + b * DD * DD;
    for (int i = tid; i < DD * DD; i += 256) {
        int r = i >> 7, c = i & 127;
        int rr = r < c ? r : c, cc = r < c ? c : r;
        Gs[r * KPAD + c] = Gb[rr * DD + cc];
    }
    for (int i = tid; i < CC * 32; i += 256) {
        int r = i >> 5, c4 = (i & 31) << 2;
        *reinterpret_cast<float4*>(&Bms[r * KPAD + c4]) =
            *reinterpret_cast<const float4*>(&g_Bm[r * DD + c4]);
        *reinterpret_cast<float4*>(&Fs[r * KPAD + c4]) =
            *reinterpret_cast<const float4*>(&g_F[r * DD + c4]);
    }
    for (int i = tid; i < 8 * 32; i += 256) {
        int r = i >> 5, c4 = (i & 31) << 2;
        *reinterpret_cast<float4*>(&wqs[r * KPAD + c4]) =
            *reinterpret_cast<const float4*>(&wq[(cg * 8 + r) * DD + c4]);
    }
    if (tid < DD) ss[tid] = g_s[b * DD + tid];
    if (tid < CC) { k0s[tid] = g_k0[tid]; v0s[tid] = g_v0[tid]; }
    if (tid < 8)  bqs[tid] = bq[cg * 8 + tid];
    __syncthreads();

    // ---- bs[k] = Bm_row_k . s ; qs[ci] = wq_row_c . s ----
    if (tid < CC) {
        float a = 0.f;
        const float* r = &Bms[tid * KPAD];
        for (int d = 0; d < DD; d++) a = fmaf(r[d], ss[d], a);
        bs[tid] = a;
    } else if (tid < CC + 8) {
        int ci = tid - CC;
        float a = 0.f;
        const float* r = &wqs[ci * KPAD];
        for (int d = 0; d < DD; d++) a = fmaf(r[d], ss[d], a);
        qs[ci] = a;
    }
    // ---- AG rows: AGs[ci][d] = sum_d1 Gs[d1][d] * wqs[ci][d1] (G symmetric) ----
    {
        const int d = tid >> 1, cb = (tid & 1) * 4;
        float a0 = 0.f, a1 = 0.f, a2 = 0.f, a3 = 0.f;
        for (int d1 = 0; d1 < DD; d1++) {
            float g = Gs[d1 * KPAD + d];
            a0 = fmaf(g, wqs[(cb + 0) * KPAD + d1], a0);
            a1 = fmaf(g, wqs[(cb + 1) * KPAD + d1], a1);
            a2 = fmaf(g, wqs[(cb + 2) * KPAD + d1], a2);
            a3 = fmaf(g, wqs[(cb + 3) * KPAD + d1], a3);
        }
        AGs[(cb + 0) * KPAD + d] = a0;
        AGs[(cb + 1) * KPAD + d] = a1;
        AGs[(cb + 2) * KPAD + d] = a2;
        AGs[(cb + 3) * KPAD + d] = a3;
    }
    __syncthreads();

    // ---- S logits (scaled) ----
    {
        const int ci = tid >> 5, k = tid & 31;
#pragma unroll
        for (int rep = 0; rep < 2; rep++) {
            int kk = k + rep * 32;
            float acc = 0.f;
            for (int d4 = 0; d4 < 32; d4++) {
                float4 ag = *reinterpret_cast<const float4*>(&AGs[ci * KPAD + d4 * 4]);
                float4 bm = *reinterpret_cast<const float4*>(&Bms[kk * KPAD + d4 * 4]);
                acc = fmaf(ag.x, bm.x, acc); acc = fmaf(ag.y, bm.y, acc);
                acc = fmaf(ag.z, bm.z, acc); acc = fmaf(ag.w, bm.w, acc);
            }
            acc += qs[ci] * k0s[kk] + bqs[ci] * bs[kk] + (float)TT * bqs[ci] * k0s[kk];
            Ps[ci * CC + kk] = acc * 0.125f;  // /sqrt(64)
        }
    }
    __syncthreads();

    // ---- softmax per row (warp w owns row w) ----
    {
        const int w = tid >> 5, lane = tid & 31;
        float v0 = Ps[w * CC + lane], v1 = Ps[w * CC + lane + 32];
        float m = fmaxf(v0, v1);
#pragma unroll
        for (int off = 16; off; off >>= 1) m = fmaxf(m, __shfl_xor_sync(~0u, m, off));
        float e0 = expf(v0 - m), e1 = expf(v1 - m);
        float sum = e0 + e1;
#pragma unroll
        for (int off = 16; off; off >>= 1) sum += __shfl_xor_sync(~0u, sum, off);
        float inv = 1.f / sum;
        Ps[w * CC + lane]      = e0 * inv;
        Ps[w * CC + lane + 32] = e1 * inv;
    }
    __syncthreads();

    // ---- Mt[d][c] = sum_k P[c][k] F[k][d];  cv[c] = sum_k P[c][k] v0[k] ----
    {
        const int d = tid >> 1, cb = (tid & 1) * 4;
        float a0 = 0.f, a1 = 0.f, a2 = 0.f, a3 = 0.f;
        for (int k = 0; k < CC; k++) {
            float f = Fs[k * KPAD + d];
            a0 = fmaf(Ps[(cb + 0) * CC + k], f, a0);
            a1 = fmaf(Ps[(cb + 1) * CC + k], f, a1);
            a2 = fmaf(Ps[(cb + 2) * CC + k], f, a2);
            a3 = fmaf(Ps[(cb + 3) * CC + k], f, a3);
        }
        float4 o = {a0, a1, a2, a3};
        *reinterpret_cast<float4*>(&g_Mt[b * DD * CC + d * CC + cg * 8 + cb]) = o;
    }
    if (tid < 8) {
        float acc = 0.f;
        for (int k = 0; k < CC; k++) acc = fmaf(Ps[tid * CC + k], v0s[k], acc);
        g_cv[b * CC + cg * 8 + tid] = acc;
    }
}

// ============ K3: y = mask * (wo @ relu(M x + c) + bo)  (grid (256,8), 256 thr, 2 CTA/SM) ============
#define UP 132
__global__ __launch_bounds__(256, 2) void k3_out(const float* __restrict__ x,
                                                 const float* __restrict__ mask,
                                                 const float* __restrict__ bo,
                                                 float* __restrict__ y) {
    extern __shared__ float sm3[];
    float* Mts = sm3;               // 128 x 64   (M transposed: [d][c])
    float* Wts = Mts + DD * CC;     //  64 x 128  (wo transposed: [c][o])
    float* Us  = Wts + CC * DD;     //  64 x UP   (relu(Mx+c))
    const int b   = blockIdx.y;
    const int t0  = blockIdx.x * 128;
    const int tid = threadIdx.x;

    {
        const float4* src = reinterpret_cast<const float4*>(g_Mt + b * DD * CC);
        float4* dst = reinterpret_cast<float4*>(Mts);
#pragma unroll
        for (int i = 0; i < 8; i++) dst[tid + 256 * i] = src[tid + 256 * i];
    }
    {
        const float4* src = reinterpret_cast<const float4*>(g_wot);
        float4* dst = reinterpret_cast<float4*>(Wts);
#pragma unroll
        for (int i = 0; i < 8; i++) dst[tid + 256 * i] = src[tid + 256 * i];
    }
    __syncthreads();

    // Step A: U = relu(M X + c). cbi = tid&7 (c-block of 8), tb = tid>>3 (t-block of 4).
    // X read straight from global: 8 lanes of each warp share an address (broadcast).
    {
        const int c0  = (tid & 7) * 8;
        const int tb4 = (tid >> 3) * 4;
        const float* xp = x + (size_t)b * DD * TT + t0 + tb4;
        ull acc[4][4];
#pragma unroll
        for (int i = 0; i < 4; i++)
#pragma unroll
            for (int j = 0; j < 4; j++) acc[i][j] = 0ull;
#pragma unroll 8
        for (int k = 0; k < DD; k++) {
            float4 xv = *reinterpret_cast<const float4*>(xp + (size_t)k * TT);
            float4 m0 = *reinterpret_cast<const float4*>(&Mts[k * CC + c0]);
            float4 m1 = *reinterpret_cast<const float4*>(&Mts[k * CC + c0 + 4]);
            ull mp0 = pk2(m0.x, m0.y), mp1 = pk2(m0.z, m0.w);
            ull mp2 = pk2(m1.x, m1.y), mp3 = pk2(m1.z, m1.w);
            float xa[4] = {xv.x, xv.y, xv.z, xv.w};
#pragma unroll
            for (int j = 0; j < 4; j++) {
                ull xd = pk2(xa[j], xa[j]);
                ffma2(acc[0][j], mp0, xd);
                ffma2(acc[1][j], mp1, xd);
                ffma2(acc[2][j], mp2, xd);
                ffma2(acc[3][j], mp3, xd);
            }
        }
#pragma unroll
        for (int cp = 0; cp < 4; cp++) {
            int c = c0 + 2 * cp;
            float cv0 = g_cv[b * CC + c], cv1 = g_cv[b * CC + c + 1];
#pragma unroll
            for (int j = 0; j < 4; j++) {
                float2 v = upk(acc[cp][j]);
                Us[c * UP + tb4 + j]       = fmaxf(v.x + cv0, 0.f);
                Us[(c + 1) * UP + tb4 + j] = fmaxf(v.y + cv1, 0.f);
            }
        }
    }
    __syncthreads();

    // Step B: Y = wo U + bo, masked. obi = tid&15 (o-block of 8), tbb = tid>>4; 2 t-passes.
    {
        const int o0 = (tid & 15) * 8;
#pragma unroll
        for (int pass = 0; pass < 2; pass++) {
            const int tB = (tid >> 4) * 4 + 64 * pass;
            ull acc[4][4];
#pragma unroll
            for (int i = 0; i < 4; i++)
#pragma unroll
                for (int j = 0; j < 4; j++) acc[i][j] = 0ull;
#pragma unroll 4
            for (int k = 0; k < CC; k++) {
                float4 u  = *reinterpret_cast<const float4*>(&Us[k * UP + tB]);
                float4 w0 = *reinterpret_cast<const float4*>(&Wts[k * DD + o0]);
                float4 w1 = *reinterpret_cast<const float4*>(&Wts[k * DD + o0 + 4]);
                ull wp0 = pk2(w0.x, w0.y), wp1 = pk2(w0.z, w0.w);
                ull wp2 = pk2(w1.x, w1.y), wp3 = pk2(w1.z, w1.w);
                float ua[4] = {u.x, u.y, u.z, u.w};
#pragma unroll
                for (int j = 0; j < 4; j++) {
                    ull ud = pk2(ua[j], ua[j]);
                    ffma2(acc[0][j], wp0, ud);
                    ffma2(acc[1][j], wp1, ud);
                    ffma2(acc[2][j], wp2, ud);
                    ffma2(acc[3][j], wp3, ud);
                }
            }
            const float* mb = mask + (size_t)b * TT + t0 + tB;
            float4 mv4 = *reinterpret_cast<const float4*>(mb);
            float mv[4] = {mv4.x, mv4.y, mv4.z, mv4.w};
            float* yb = y + (size_t)b * DD * TT + t0 + tB;
#pragma unroll
            for (int op = 0; op < 4; op++) {
                int o = o0 + 2 * op;
                float bo0 = bo[o], bo1 = bo[o + 1];
                float r0[4], r1[4];
#pragma unroll
                for (int j = 0; j < 4; j++) {
                    float2 v = upk(acc[op][j]);
                    r0[j] = (v.x + bo0) * mv[j];
                    r1[j] = (v.y + bo1) * mv[j];
                }
                float4 q0 = {r0[0], r0[1], r0[2], r0[3]};
                float4 q1 = {r1[0], r1[1], r1[2], r1[3]};
                *reinterpret_cast<float4*>(&yb[(size_t)o * TT])       = q0;
                *reinterpret_cast<float4*>(&yb[(size_t)(o + 1) * TT]) = q1;
            }
        }
    }
}

static const int SMEM_K1  = (32 * 132 + 32 * 264) * (int)sizeof(float);
static const int SMEM_K2C = (DD * KPAD + CC * KPAD * 2 + 8 * KPAD * 2 + 8 * CC +
                             DD + 3 * CC + 16) * (int)sizeof(float);
static const int SMEM_K3  = (DD * CC + CC * DD + CC * UP) * (int)sizeof(float);

extern "C" void kernel_launch(void* const* d_in, const int* in_sizes, int n_in,
                              void* d_out, int out_size) {
    const float* x1   = (const float*)d_in[0];
    // d_in[1] = x2 (unused in encoder stage)
    const float* mask = (const float*)d_in[2];
    const float* wq   = (const float*)d_in[3];
    const float* bq   = (const float*)d_in[4];
    const float* wk   = (const float*)d_in[5];
    const float* bk   = (const float*)d_in[6];
    const float* wv   = (const float*)d_in[7];
    const float* bv   = (const float*)d_in[8];
    const float* we   = (const float*)d_in[9];
    const float* be   = (const float*)d_in[10];
    const float* wf   = (const float*)d_in[11];
    const float* bf   = (const float*)d_in[12];
    const float* wo   = (const float*)d_in[13];
    const float* bo   = (const float*)d_in[14];
    float* y = (float*)d_out;

    cudaFuncSetAttribute(k1_gram,  cudaFuncAttributeMaxDynamicSharedMemorySize, SMEM_K1);
    cudaFuncSetAttribute(k2c_attn, cudaFuncAttributeMaxDynamicSharedMemorySize, SMEM_K2C);
    cudaFuncSetAttribute(k3_out,   cudaFuncAttributeMaxDynamicSharedMemorySize, SMEM_K3);

    void *pG = nullptr, *ps = nullptr;
    cudaGetSymbolAddress(&pG, g_G);
    cudaGetSymbolAddress(&ps, g_s);
    cudaMemsetAsync(pG, 0, BB * DD * DD * sizeof(float));
    cudaMemsetAsync(ps, 0, BB * DD * sizeof(float));

    k2a_weights<<<16, 256>>>(we, wk, bk, be, wf, wv, bv, bf, wo);
    k1_gram<<<dim3(32, 8), 288, SMEM_K1>>>(x1);
    k2c_attn<<<dim3(8, 8), 256, SMEM_K2C>>>(wq, bq);
    k3_out<<<dim3(256, 8), 256, SMEM_K3>>>(x1, mask, bo, y);
}

// round 4
// speedup vs baseline: 1.6062x; 1.6062x over previous
#include <cuda_runtime.h>

#define BB 8
#define DD 128
#define TT 32768
#define CC 64

typedef unsigned long long ull;

// ---------------- f32x2 packed-FMA helpers (sm_103a FFMA2 path) ----------------
__device__ __forceinline__ void ffma2(ull& d, ull a, ull b) {
    asm("fma.rn.f32x2 %0, %1, %2, %0;" : "+l"(d) : "l"(a), "l"(b));
}
__device__ __forceinline__ ull pk2(float lo, float hi) {
    ull r; asm("mov.b64 %0, {%1, %2};" : "=l"(r) : "f"(lo), "f"(hi)); return r;
}
__device__ __forceinline__ float2 upk(ull v) {
    float2 r; asm("mov.b64 {%0, %1}, %2;" : "=f"(r.x), "=f"(r.y) : "l"(v)); return r;
}

// ---------------- scratch (static device globals; no allocation) ----------------
__device__ float g_G[BB * DD * DD];     // per-batch Gram (full, symmetric)
__device__ float g_s[BB * DD];          // per-batch row sums of x over t
__device__ float g_Bm[CC * DD];         // we @ wk
__device__ float g_F[CC * DD];          // wf @ wv
__device__ float g_k0[CC];              // we @ bk + be
__device__ float g_v0[CC];              // wf @ bv + bf
__device__ float g_wot[CC * DD];        // wo transposed: [c][o]
__device__ float g_Mt[BB * DD * CC];    // M_b transposed: [b][d][c]
__device__ float g_cv[BB * CC];         // P_b @ v0
__device__ float g_U[BB * CC * TT];     // relu(M x + c) staging

// ================= K1: per-batch Gram + row sums, double-buffered =================
// grid (32, 8), 256 threads, 2 CTA/SM. Each block: 1024 t-columns in 32 chunks of 32.
__global__ __launch_bounds__(256, 2) void k1_gram(const float* __restrict__ x) {
    __shared__ float xs[2][32][132];
    const int b   = blockIdx.y;
    const int t0  = blockIdx.x * 1024;
    const int tid = threadIdx.x;
    const int ty  = tid >> 4;   // 0..15
    const int tx  = tid & 15;   // 0..15
    const float* xb = x + (size_t)b * DD * TT;

    // loader coords (fixed): m=0..3 -> d = (tid+256m)>>3, tl = ((tid+256m)&7)*4
    int dmv[4], tlv[4];
#pragma unroll
    for (int m = 0; m < 4; m++) {
        int i = tid + 256 * m;
        dmv[m] = i >> 3;
        tlv[m] = (i & 7) << 2;
    }

    ull acc[8][4];
#pragma unroll
    for (int i = 0; i < 8; i++)
#pragma unroll
        for (int j = 0; j < 4; j++) acc[i][j] = 0ull;
    float srow[4] = {0.f, 0.f, 0.f, 0.f};

    // preload chunk 0
    float4 v[4];
#pragma unroll
    for (int m = 0; m < 4; m++)
        v[m] = *reinterpret_cast<const float4*>(xb + (size_t)dmv[m] * TT + t0 + tlv[m]);

    for (int kt = 0; kt < 32; kt++) {
        const int buf = kt & 1;
#pragma unroll
        for (int m = 0; m < 4; m++) {
            srow[m] += (v[m].x + v[m].y) + (v[m].z + v[m].w);
            xs[buf][tlv[m] + 0][dmv[m]] = v[m].x;
            xs[buf][tlv[m] + 1][dmv[m]] = v[m].y;
            xs[buf][tlv[m] + 2][dmv[m]] = v[m].z;
            xs[buf][tlv[m] + 3][dmv[m]] = v[m].w;
        }
        __syncthreads();
        if (kt < 31) {
            const int tb = t0 + (kt + 1) * 32;
#pragma unroll
            for (int m = 0; m < 4; m++)
                v[m] = *reinterpret_cast<const float4*>(xb + (size_t)dmv[m] * TT + tb + tlv[m]);
        }
#pragma unroll 8
        for (int k = 0; k < 32; k++) {
            float4 a0 = *reinterpret_cast<const float4*>(&xs[buf][k][ty * 8]);
            float4 a1 = *reinterpret_cast<const float4*>(&xs[buf][k][ty * 8 + 4]);
            float4 b0 = *reinterpret_cast<const float4*>(&xs[buf][k][tx * 8]);
            float4 b1 = *reinterpret_cast<const float4*>(&xs[buf][k][tx * 8 + 4]);
            ull bp0 = pk2(b0.x, b0.y), bp1 = pk2(b0.z, b0.w);
            ull bp2 = pk2(b1.x, b1.y), bp3 = pk2(b1.z, b1.w);
            float av[8] = {a0.x, a0.y, a0.z, a0.w, a1.x, a1.y, a1.z, a1.w};
#pragma unroll
            for (int i = 0; i < 8; i++) {
                ull ad = pk2(av[i], av[i]);
                ffma2(acc[i][0], ad, bp0);
                ffma2(acc[i][1], ad, bp1);
                ffma2(acc[i][2], ad, bp2);
                ffma2(acc[i][3], ad, bp3);
            }
        }
    }

    float* Gb = g_G + b * DD * DD;
#pragma unroll
    for (int i = 0; i < 8; i++)
#pragma unroll
        for (int j = 0; j < 4; j++) {
            float2 w = upk(acc[i][j]);
            atomicAdd(&Gb[(ty * 8 + i) * DD + tx * 8 + 2 * j],     w.x);
            atomicAdd(&Gb[(ty * 8 + i) * DD + tx * 8 + 2 * j + 1], w.y);
        }
#pragma unroll
    for (int m = 0; m < 4; m++)
        atomicAdd(&g_s[b * DD + dmv[m]], srow[m]);
}

// ============ K2a: batch-independent weight products (grid 16) ============
__global__ void k2a_weights(const float* __restrict__ we, const float* __restrict__ wk,
                            const float* __restrict__ bk, const float* __restrict__ be,
                            const float* __restrict__ wf, const float* __restrict__ wv,
                            const float* __restrict__ bv, const float* __restrict__ bf,
                            const float* __restrict__ wo) {
    const int j = blockIdx.x, tid = threadIdx.x;
    if (j < 8) {
#pragma unroll
        for (int it = 0; it < 4; it++) {
            int idx = tid + 256 * it;
            int o = j * 8 + (idx >> 7);
            int d = idx & 127;
            float acc = 0.f;
            for (int c = 0; c < CC; c++) acc = fmaf(we[o * CC + c], wk[c * DD + d], acc);
            g_Bm[o * DD + d] = acc;
        }
        if (j == 0 && tid < CC) {
            float acc = be[tid];
            for (int c = 0; c < CC; c++) acc = fmaf(we[tid * CC + c], bk[c], acc);
            g_k0[tid] = acc;
        }
        if (j == 1) {
#pragma unroll
            for (int it = 0; it < 32; it++) {
                int idx = tid + 256 * it;
                int c = idx >> 7, o = idx & 127;
                g_wot[c * DD + o] = wo[o * CC + c];
            }
        }
    } else {
        int jj = j - 8;
#pragma unroll
        for (int it = 0; it < 4; it++) {
            int idx = tid + 256 * it;
            int o = jj * 8 + (idx >> 7);
            int d = idx & 127;
            float acc = 0.f;
            for (int c = 0; c < CC; c++) acc = fmaf(wf[o * CC + c], wv[c * DD + d], acc);
            g_F[o * DD + d] = acc;
        }
        if (j == 8 && tid < CC) {
            float acc = bf[tid];
            for (int c = 0; c < CC; c++) acc = fmaf(wf[tid * CC + c], bv[c], acc);
            g_v0[tid] = acc;
        }
    }
}

// ============ K2c: AG + S + softmax + M + cv, fused. grid (8 c-groups, 8 b) ============
#define KPAD 132
__global__ void k2c_attn(const float* __restrict__ wq, const float* __restrict__ bq) {
    extern __shared__ float sm2[];
    float* Gs  = sm2;                  // 128 x KPAD
    float* Bms = Gs  + DD * KPAD;      //  64 x KPAD
    float* Fs  = Bms + CC * KPAD;      //  64 x KPAD
    float* wqs = Fs  + CC * KPAD;      //   8 x KPAD
    float* AGs = wqs + 8 * KPAD;       //   8 x KPAD
    float* Ps  = AGs + 8 * KPAD;       //   8 x 64
    float* ss  = Ps  + 8 * CC;         // 128
    float* bs  = ss  + DD;             //  64
    float* k0s = bs  + CC;             //  64
    float* v0s = k0s + CC;             //  64
    float* qs  = v0s + CC;             //   8
    float* bqs = qs  + 8;              //   8
    const int cg = blockIdx.x, b = blockIdx.y, tid = threadIdx.x;

    const float* Gb = g_G + b * DD * DD;
    for (int i = tid; i < DD * 32; i += 256) {
        int r = i >> 5, c4 = (i & 31) << 2;
        *reinterpret_cast<float4*>(&Gs[r * KPAD + c4]) =
            *reinterpret_cast<const float4*>(&Gb[r * DD + c4]);
    }
    for (int i = tid; i < CC * 32; i += 256) {
        int r = i >> 5, c4 = (i & 31) << 2;
        *reinterpret_cast<float4*>(&Bms[r * KPAD + c4]) =
            *reinterpret_cast<const float4*>(&g_Bm[r * DD + c4]);
        *reinterpret_cast<float4*>(&Fs[r * KPAD + c4]) =
            *reinterpret_cast<const float4*>(&g_F[r * DD + c4]);
    }
    for (int i = tid; i < 8 * 32; i += 256) {
        int r = i >> 5, c4 = (i & 31) << 2;
        *reinterpret_cast<float4*>(&wqs[r * KPAD + c4]) =
            *reinterpret_cast<const float4*>(&wq[(cg * 8 + r) * DD + c4]);
    }
    if (tid < DD) ss[tid] = g_s[b * DD + tid];
    if (tid < CC) { k0s[tid] = g_k0[tid]; v0s[tid] = g_v0[tid]; }
    if (tid < 8)  bqs[tid] = bq[cg * 8 + tid];
    __syncthreads();

    if (tid < CC) {
        float a = 0.f;
        const float* r = &Bms[tid * KPAD];
        for (int d = 0; d < DD; d++) a = fmaf(r[d], ss[d], a);
        bs[tid] = a;
    } else if (tid < CC + 8) {
        int ci = tid - CC;
        float a = 0.f;
        const float* r = &wqs[ci * KPAD];
        for (int d = 0; d < DD; d++) a = fmaf(r[d], ss[d], a);
        qs[ci] = a;
    }
    {
        const int d = tid >> 1, cb = (tid & 1) * 4;
        float a0 = 0.f, a1 = 0.f, a2 = 0.f, a3 = 0.f;
        for (int d1 = 0; d1 < DD; d1++) {
            float g = Gs[d1 * KPAD + d];
            a0 = fmaf(g, wqs[(cb + 0) * KPAD + d1], a0);
            a1 = fmaf(g, wqs[(cb + 1) * KPAD + d1], a1);
            a2 = fmaf(g, wqs[(cb + 2) * KPAD + d1], a2);
            a3 = fmaf(g, wqs[(cb + 3) * KPAD + d1], a3);
        }
        AGs[(cb + 0) * KPAD + d] = a0;
        AGs[(cb + 1) * KPAD + d] = a1;
        AGs[(cb + 2) * KPAD + d] = a2;
        AGs[(cb + 3) * KPAD + d] = a3;
    }
    __syncthreads();

    {
        const int ci = tid >> 5, k = tid & 31;
#pragma unroll
        for (int rep = 0; rep < 2; rep++) {
            int kk = k + rep * 32;
            float acc = 0.f;
            for (int d4 = 0; d4 < 32; d4++) {
                float4 ag = *reinterpret_cast<const float4*>(&AGs[ci * KPAD + d4 * 4]);
                float4 bm = *reinterpret_cast<const float4*>(&Bms[kk * KPAD + d4 * 4]);
                acc = fmaf(ag.x, bm.x, acc); acc = fmaf(ag.y, bm.y, acc);
                acc = fmaf(ag.z, bm.z, acc); acc = fmaf(ag.w, bm.w, acc);
            }
            acc += qs[ci] * k0s[kk] + bqs[ci] * bs[kk] + (float)TT * bqs[ci] * k0s[kk];
            Ps[ci * CC + kk] = acc * 0.125f;  // /sqrt(64)
        }
    }
    __syncthreads();

    {
        const int w = tid >> 5, lane = tid & 31;
        float v0 = Ps[w * CC + lane], v1 = Ps[w * CC + lane + 32];
        float m = fmaxf(v0, v1);
#pragma unroll
        for (int off = 16; off; off >>= 1) m = fmaxf(m, __shfl_xor_sync(~0u, m, off));
        float e0 = expf(v0 - m), e1 = expf(v1 - m);
        float sum = e0 + e1;
#pragma unroll
        for (int off = 16; off; off >>= 1) sum += __shfl_xor_sync(~0u, sum, off);
        float inv = 1.f / sum;
        Ps[w * CC + lane]      = e0 * inv;
        Ps[w * CC + lane + 32] = e1 * inv;
    }
    __syncthreads();

    {
        const int d = tid >> 1, cb = (tid & 1) * 4;
        float a0 = 0.f, a1 = 0.f, a2 = 0.f, a3 = 0.f;
        for (int k = 0; k < CC; k++) {
            float f = Fs[k * KPAD + d];
            a0 = fmaf(Ps[(cb + 0) * CC + k], f, a0);
            a1 = fmaf(Ps[(cb + 1) * CC + k], f, a1);
            a2 = fmaf(Ps[(cb + 2) * CC + k], f, a2);
            a3 = fmaf(Ps[(cb + 3) * CC + k], f, a3);
        }
        float4 o = {a0, a1, a2, a3};
        *reinterpret_cast<float4*>(&g_Mt[b * DD * CC + d * CC + cg * 8 + cb]) = o;
    }
    if (tid < 8) {
        float acc = 0.f;
        for (int k = 0; k < CC; k++) acc = fmaf(Ps[tid * CC + k], v0s[k], acc);
        g_cv[b * CC + cg * 8 + tid] = acc;
    }
}

// ============ K3a: U = relu(M X + c). grid (256, 8), 256 thr, 2 CTA/SM ============
__global__ __launch_bounds__(256, 2) void k3a_u(const float* __restrict__ x) {
    extern __shared__ float sma[];
    float* Xs  = sma;               // 128 x 128 (X[d][t])
    float* Mts = Xs + DD * 128;     // 128 x 64  (M transposed: [d][c])
    const int b   = blockIdx.y;
    const int t0  = blockIdx.x * 128;
    const int tid = threadIdx.x;

    {
        const float4* src = reinterpret_cast<const float4*>(g_Mt + b * DD * CC);
        float4* dst = reinterpret_cast<float4*>(Mts);
#pragma unroll
        for (int i = 0; i < 8; i++) dst[tid + 256 * i] = src[tid + 256 * i];
    }
    {
        const float* xb = x + (size_t)b * DD * TT + t0;
#pragma unroll
        for (int i = 0; i < 16; i++) {
            int f4 = tid + 256 * i;
            int d  = f4 >> 5;
            int tl = (f4 & 31) << 2;
            *reinterpret_cast<float4*>(&Xs[d * 128 + tl]) =
                *reinterpret_cast<const float4*>(xb + (size_t)d * TT + tl);
        }
    }
    __syncthreads();

    // 8c x 4t per thread: cy = tid>>5 -> c0 = cy*8; cx = tid&31 -> t0l = cx*4
    const int c0  = (tid >> 5) * 8;
    const int tl0 = (tid & 31) * 4;
    ull acc[4][4];
#pragma unroll
    for (int i = 0; i < 4; i++)
#pragma unroll
        for (int j = 0; j < 4; j++) acc[i][j] = 0ull;
#pragma unroll 8
    for (int k = 0; k < DD; k++) {
        float4 m0 = *reinterpret_cast<const float4*>(&Mts[k * CC + c0]);
        float4 m1 = *reinterpret_cast<const float4*>(&Mts[k * CC + c0 + 4]);
        float4 xv = *reinterpret_cast<const float4*>(&Xs[k * 128 + tl0]);
        ull mp0 = pk2(m0.x, m0.y), mp1 = pk2(m0.z, m0.w);
        ull mp2 = pk2(m1.x, m1.y), mp3 = pk2(m1.z, m1.w);
        float xa[4] = {xv.x, xv.y, xv.z, xv.w};
#pragma unroll
        for (int j = 0; j < 4; j++) {
            ull xd = pk2(xa[j], xa[j]);
            ffma2(acc[0][j], mp0, xd);
            ffma2(acc[1][j], mp1, xd);
            ffma2(acc[2][j], mp2, xd);
            ffma2(acc[3][j], mp3, xd);
        }
    }
    float* ub = g_U + (size_t)b * CC * TT + t0 + tl0;
#pragma unroll
    for (int cp = 0; cp < 4; cp++) {
        int c = c0 + 2 * cp;
        float cv0 = g_cv[b * CC + c], cv1 = g_cv[b * CC + c + 1];
        float4 r0, r1;
        float2 v0 = upk(acc[cp][0]), v1 = upk(acc[cp][1]);
        float2 v2 = upk(acc[cp][2]), v3 = upk(acc[cp][3]);
        r0.x = fmaxf(v0.x + cv0, 0.f); r1.x = fmaxf(v0.y + cv1, 0.f);
        r0.y = fmaxf(v1.x + cv0, 0.f); r1.y = fmaxf(v1.y + cv1, 0.f);
        r0.z = fmaxf(v2.x + cv0, 0.f); r1.z = fmaxf(v2.y + cv1, 0.f);
        r0.w = fmaxf(v3.x + cv0, 0.f); r1.w = fmaxf(v3.y + cv1, 0.f);
        *reinterpret_cast<float4*>(ub + (size_t)c * TT)       = r0;
        *reinterpret_cast<float4*>(ub + (size_t)(c + 1) * TT) = r1;
    }
}

// ============ K3b: y = mask * (wo @ U + bo). grid (256, 8), 256 thr, 2 CTA/SM ============
__global__ __launch_bounds__(256, 2) void k3b_y(const float* __restrict__ mask,
                                                const float* __restrict__ bo,
                                                float* __restrict__ y) {
    extern __shared__ float smb[];
    float* Us  = smb;               // 64 x 128 (U[c][t])
    float* Wts = Us + CC * 128;     // 64 x 128 (wo transposed: [c][o])
    const int b   = blockIdx.y;
    const int t0  = blockIdx.x * 128;
    const int tid = threadIdx.x;

    {
        const float4* src = reinterpret_cast<const float4*>(g_wot);
        float4* dst = reinterpret_cast<float4*>(Wts);
#pragma unroll
        for (int i = 0; i < 8; i++) dst[tid + 256 * i] = src[tid + 256 * i];
    }
    {
        const float* ub = g_U + (size_t)b * CC * TT + t0;
#pragma unroll
        for (int i = 0; i < 8; i++) {
            int f4 = tid + 256 * i;
            int c  = f4 >> 5;
            int tl = (f4 & 31) << 2;
            *reinterpret_cast<float4*>(&Us[c * 128 + tl]) =
                *reinterpret_cast<const float4*>(ub + (size_t)c * TT + tl);
        }
    }
    __syncthreads();

    // 8o x 8t per thread: oy = tid>>4 -> o0 = oy*8; tx = tid&15 -> tl0 = tx*8
    const int o0  = (tid >> 4) * 8;
    const int tl0 = (tid & 15) * 8;
    ull acc[4][8];
#pragma unroll
    for (int i = 0; i < 4; i++)
#pragma unroll
        for (int j = 0; j < 8; j++) acc[i][j] = 0ull;
#pragma unroll 4
    for (int k = 0; k < CC; k++) {
        float4 w0 = *reinterpret_cast<const float4*>(&Wts[k * DD + o0]);
        float4 w1 = *reinterpret_cast<const float4*>(&Wts[k * DD + o0 + 4]);
        float4 u0 = *reinterpret_cast<const float4*>(&Us[k * 128 + tl0]);
        float4 u1 = *reinterpret_cast<const float4*>(&Us[k * 128 + tl0 + 4]);
        ull wp0 = pk2(w0.x, w0.y), wp1 = pk2(w0.z, w0.w);
        ull wp2 = pk2(w1.x, w1.y), wp3 = pk2(w1.z, w1.w);
        float ua[8] = {u0.x, u0.y, u0.z, u0.w, u1.x, u1.y, u1.z, u1.w};
#pragma unroll
        for (int j = 0; j < 8; j++) {
            ull ud = pk2(ua[j], ua[j]);
            ffma2(acc[0][j], wp0, ud);
            ffma2(acc[1][j], wp1, ud);
            ffma2(acc[2][j], wp2, ud);
            ffma2(acc[3][j], wp3, ud);
        }
    }
    const float* mb = mask + (size_t)b * TT + t0 + tl0;
    float4 mq0 = *reinterpret_cast<const float4*>(mb);
    float4 mq1 = *reinterpret_cast<const float4*>(mb + 4);
    float mv[8] = {mq0.x, mq0.y, mq0.z, mq0.w, mq1.x, mq1.y, mq1.z, mq1.w};
    float* yb = y + (size_t)b * DD * TT + t0 + tl0;
#pragma unroll
    for (int op = 0; op < 4; op++) {
        int o = o0 + 2 * op;
        float bo0 = bo[o], bo1 = bo[o + 1];
        float r0[8], r1[8];
#pragma unroll
        for (int j = 0; j < 8; j++) {
            float2 v = upk(acc[op][j]);
            r0[j] = (v.x + bo0) * mv[j];
            r1[j] = (v.y + bo1) * mv[j];
        }
        float* row0 = yb + (size_t)o * TT;
        float* row1 = yb + (size_t)(o + 1) * TT;
        *reinterpret_cast<float4*>(row0)     = make_float4(r0[0], r0[1], r0[2], r0[3]);
        *reinterpret_cast<float4*>(row0 + 4) = make_float4(r0[4], r0[5], r0[6], r0[7]);
        *reinterpret_cast<float4*>(row1)     = make_float4(r1[0], r1[1], r1[2], r1[3]);
        *reinterpret_cast<float4*>(row1 + 4) = make_float4(r1[4], r1[5], r1[6], r1[7]);
    }
}

static const int SMEM_K2C = (DD * KPAD + CC * KPAD * 2 + 8 * KPAD * 2 + 8 * CC +
                             DD + 3 * CC + 16) * (int)sizeof(float);
static const int SMEM_K3A = (DD * 128 + DD * CC) * (int)sizeof(float);   // 96 KB
static const int SMEM_K3B = (CC * 128 + CC * DD) * (int)sizeof(float);   // 64 KB

extern "C" void kernel_launch(void* const* d_in, const int* in_sizes, int n_in,
                              void* d_out, int out_size) {
    const float* x1   = (const float*)d_in[0];
    // d_in[1] = x2 (unused in encoder stage)
    const float* mask = (const float*)d_in[2];
    const float* wq   = (const float*)d_in[3];
    const float* bq   = (const float*)d_in[4];
    const float* wk   = (const float*)d_in[5];
    const float* bk   = (const float*)d_in[6];
    const float* wv   = (const float*)d_in[7];
    const float* bv   = (const float*)d_in[8];
    const float* we   = (const float*)d_in[9];
    const float* be   = (const float*)d_in[10];
    const float* wf   = (const float*)d_in[11];
    const float* bf   = (const float*)d_in[12];
    const float* wo   = (const float*)d_in[13];
    const float* bo   = (const float*)d_in[14];
    float* y = (float*)d_out;

    cudaFuncSetAttribute(k2c_attn, cudaFuncAttributeMaxDynamicSharedMemorySize, SMEM_K2C);
    cudaFuncSetAttribute(k3a_u,    cudaFuncAttributeMaxDynamicSharedMemorySize, SMEM_K3A);
    cudaFuncSetAttribute(k3b_y,    cudaFuncAttributeMaxDynamicSharedMemorySize, SMEM_K3B);

    void *pG = nullptr, *ps = nullptr;
    cudaGetSymbolAddress(&pG, g_G);
    cudaGetSymbolAddress(&ps, g_s);
    cudaMemsetAsync(pG, 0, BB * DD * DD * sizeof(float));
    cudaMemsetAsync(ps, 0, BB * DD * sizeof(float));

    k2a_weights<<<16, 256>>>(we, wk, bk, be, wf, wv, bv, bf, wo);
    k1_gram<<<dim3(32, 8), 256>>>(x1);
    k2c_attn<<<dim3(8, 8), 256, SMEM_K2C>>>(wq, bq);
    k3a_u<<<dim3(256, 8), 256, SMEM_K3A>>>(x1);
    k3b_y<<<dim3(256, 8), 256, SMEM_K3B>>>(mask, bo, y);
}

// round 6
// speedup vs baseline: 2.0833x; 1.2970x over previous
#include <cuda_runtime.h>
#include <cuda_bf16.h>
#include <cstdint>

#define BB 8
#define DD 128
#define TT 32768
#define CC 64

typedef unsigned long long ull;

// ---------------- f32x2 packed-FMA helpers ----------------
__device__ __forceinline__ void ffma2(ull& d, ull a, ull b) {
    asm("fma.rn.f32x2 %0, %1, %2, %0;" : "+l"(d) : "l"(a), "l"(b));
}
__device__ __forceinline__ ull pk2(float lo, float hi) {
    ull r; asm("mov.b64 %0, {%1, %2};" : "=l"(r) : "f"(lo), "f"(hi)); return r;
}
__device__ __forceinline__ float2 upk(ull v) {
    float2 r; asm("mov.b64 {%0, %1}, %2;" : "=f"(r.x), "=f"(r.y) : "l"(v)); return r;
}

// ---------------- warp-level bf16 MMA (sm_80+ path; works on base sm_103) ----------------
__device__ __forceinline__ void mma_bf16(float* d, const uint32_t* a, const uint32_t* b) {
    asm volatile(
        "mma.sync.aligned.m16n8k16.row.col.f32.bf16.bf16.f32 "
        "{%0,%1,%2,%3}, {%4,%5,%6,%7}, {%8,%9}, {%0,%1,%2,%3};"
        : "+f"(d[0]), "+f"(d[1]), "+f"(d[2]), "+f"(d[3])
        : "r"(a[0]), "r"(a[1]), "r"(a[2]), "r"(a[3]), "r"(b[0]), "r"(b[1]));
}
// pack two fp32 -> bf16x2 (v0 low, v1 high)
__device__ __forceinline__ uint32_t pkbf(float v0, float v1) {
    uint32_t r; asm("cvt.rn.bf16x2.f32 %0, %1, %2;" : "=r"(r) : "f"(v1), "f"(v0)); return r;
}

// ---------------- scratch (static device globals) ----------------
__device__ float g_G[BB * DD * DD];     // per-batch Gram (full, symmetric)
__device__ float g_s[BB * DD];          // per-batch row sums
__device__ float g_Bm[CC * DD];         // we @ wk
__device__ float g_F[CC * DD];          // wf @ wv
__device__ float g_k0[CC];
__device__ float g_v0[CC];
__device__ float g_wot[CC * DD];        // wo transposed
__device__ float g_Mt[BB * DD * CC];    // M transposed [b][d][c]
__device__ float g_cv[BB * CC];
__device__ float g_U[BB * CC * TT];     // relu(M x + c) staging

// ================= K1 (mma.sync bf16 split): per-batch Gram + row sums =================
// grid (16, 8), 256 thr (8 warps). Each CTA: 2048 t in 32 chunks of 64.
// G += Xh Xh^T + Xh Xl^T + Xl Xh^T, fp32 register accumulators, atomicAdd epilogue.
#define TSEG 2048
#define TCH  64
#define NCH  (TSEG / TCH)
#define KSTR 72   // smem row stride (bf16 elems)

__global__ __launch_bounds__(256, 1) void k1_mma(const float* __restrict__ x) {
    __shared__ unsigned short sh_hi[DD][KSTR];
    __shared__ unsigned short sh_lo[DD][KSTR];
    const int tid = threadIdx.x;
    const int w   = tid >> 5, l = tid & 31;
    const int g   = l >> 2, tg = l & 3;
    const int b   = blockIdx.y;
    const int tseg = blockIdx.x * TSEG;
    const int d   = tid >> 1;
    const int kh  = (tid & 1) * 32;
    const float* xp = x + ((size_t)b * DD + d) * TT + tseg + kh;

    float acc[16][4];
#pragma unroll
    for (int j = 0; j < 16; j++)
#pragma unroll
        for (int q = 0; q < 4; q++) acc[j][q] = 0.f;
    float srow = 0.f;

    float4 r[8], r2[8];
#pragma unroll
    for (int i = 0; i < 8; i++) r[i] = *reinterpret_cast<const float4*>(xp + 4 * i);

    const int m0 = w * 16;

    for (int c = 0; c < NCH; c++) {
        if (c + 1 < NCH) {
            const float* xn = xp + (c + 1) * TCH;
#pragma unroll
            for (int i = 0; i < 8; i++) r2[i] = *reinterpret_cast<const float4*>(xn + 4 * i);
        }
        // ---- convert fp32 -> bf16 hi/lo, store K-major tiles ----
#pragma unroll
        for (int it = 0; it < 8; it++) {
            float4 v = r[it];
            srow += (v.x + v.y) + (v.z + v.w);
            uint32_t hp0 = pkbf(v.x, v.y), hp1 = pkbf(v.z, v.w);
            float h0 = __uint_as_float(hp0 << 16);
            float h1 = __uint_as_float(hp0 & 0xFFFF0000u);
            float h2 = __uint_as_float(hp1 << 16);
            float h3 = __uint_as_float(hp1 & 0xFFFF0000u);
            uint32_t lp0 = pkbf(v.x - h0, v.y - h1);
            uint32_t lp1 = pkbf(v.z - h2, v.w - h3);
            *reinterpret_cast<uint2*>(&sh_hi[d][kh + it * 4]) = make_uint2(hp0, hp1);
            *reinterpret_cast<uint2*>(&sh_lo[d][kh + it * 4]) = make_uint2(lp0, lp1);
        }
        __syncthreads();
        // ---- mma over 4 k-steps of 16 ----
#pragma unroll
        for (int ks = 0; ks < 4; ks++) {
            const int k0 = ks * 16;
            const int ca = k0 + tg * 2;
            uint32_t ah[4], al[4];
            ah[0] = *reinterpret_cast<const uint32_t*>(&sh_hi[m0 + g][ca]);
            ah[1] = *reinterpret_cast<const uint32_t*>(&sh_hi[m0 + g + 8][ca]);
            ah[2] = *reinterpret_cast<const uint32_t*>(&sh_hi[m0 + g][ca + 8]);
            ah[3] = *reinterpret_cast<const uint32_t*>(&sh_hi[m0 + g + 8][ca + 8]);
            al[0] = *reinterpret_cast<const uint32_t*>(&sh_lo[m0 + g][ca]);
            al[1] = *reinterpret_cast<const uint32_t*>(&sh_lo[m0 + g + 8][ca]);
            al[2] = *reinterpret_cast<const uint32_t*>(&sh_lo[m0 + g][ca + 8]);
            al[3] = *reinterpret_cast<const uint32_t*>(&sh_lo[m0 + g + 8][ca + 8]);
#pragma unroll
            for (int j = 0; j < 16; j++) {
                const int n = j * 8 + g;
                uint32_t bh[2], bl[2];
                bh[0] = *reinterpret_cast<const uint32_t*>(&sh_hi[n][ca]);
                bh[1] = *reinterpret_cast<const uint32_t*>(&sh_hi[n][ca + 8]);
                bl[0] = *reinterpret_cast<const uint32_t*>(&sh_lo[n][ca]);
                bl[1] = *reinterpret_cast<const uint32_t*>(&sh_lo[n][ca + 8]);
                mma_bf16(acc[j], ah, bh);
                mma_bf16(acc[j], ah, bl);
                mma_bf16(acc[j], al, bh);
            }
        }
        __syncthreads();
#pragma unroll
        for (int i = 0; i < 8; i++) r[i] = r2[i];
    }

    // ---- epilogue: lane map of m16n8 acc -> atomicAdd into g_G ----
    float* Gb = g_G + b * DD * DD;
#pragma unroll
    for (int j = 0; j < 16; j++) {
        const int row = m0 + g;
        const int col = j * 8 + tg * 2;
        atomicAdd(&Gb[row * DD + col],           acc[j][0]);
        atomicAdd(&Gb[row * DD + col + 1],       acc[j][1]);
        atomicAdd(&Gb[(row + 8) * DD + col],     acc[j][2]);
        atomicAdd(&Gb[(row + 8) * DD + col + 1], acc[j][3]);
    }
    atomicAdd(&g_s[b * DD + d], srow);
}

// ============ K2a: batch-independent weight products (grid 16) ============
__global__ void k2a_weights(const float* __restrict__ we, const float* __restrict__ wk,
                            const float* __restrict__ bk, const float* __restrict__ be,
                            const float* __restrict__ wf, const float* __restrict__ wv,
                            const float* __restrict__ bv, const float* __restrict__ bf,
                            const float* __restrict__ wo) {
    const int j = blockIdx.x, tid = threadIdx.x;
    if (j < 8) {
#pragma unroll
        for (int it = 0; it < 4; it++) {
            int idx = tid + 256 * it;
            int o = j * 8 + (idx >> 7);
            int d = idx & 127;
            float acc = 0.f;
            for (int c = 0; c < CC; c++) acc = fmaf(we[o * CC + c], wk[c * DD + d], acc);
            g_Bm[o * DD + d] = acc;
        }
        if (j == 0 && tid < CC) {
            float acc = be[tid];
            for (int c = 0; c < CC; c++) acc = fmaf(we[tid * CC + c], bk[c], acc);
            g_k0[tid] = acc;
        }
        if (j == 1) {
#pragma unroll
            for (int it = 0; it < 32; it++) {
                int idx = tid + 256 * it;
                int c = idx >> 7, o = idx & 127;
                g_wot[c * DD + o] = wo[o * CC + c];
            }
        }
    } else {
        int jj = j - 8;
#pragma unroll
        for (int it = 0; it < 4; it++) {
            int idx = tid + 256 * it;
            int o = jj * 8 + (idx >> 7);
            int d = idx & 127;
            float acc = 0.f;
            for (int c = 0; c < CC; c++) acc = fmaf(wf[o * CC + c], wv[c * DD + d], acc);
            g_F[o * DD + d] = acc;
        }
        if (j == 8 && tid < CC) {
            float acc = bf[tid];
            for (int c = 0; c < CC; c++) acc = fmaf(wf[tid * CC + c], bv[c], acc);
            g_v0[tid] = acc;
        }
    }
}

// ============ K2c: AG + S + softmax + M + cv, fused. grid (8 c-groups, 8 b) ============
#define KPAD 132
__global__ void k2c_attn(const float* __restrict__ wq, const float* __restrict__ bq) {
    extern __shared__ float sm2[];
    float* Gs  = sm2;                  // 128 x KPAD
    float* Bms = Gs  + DD * KPAD;      //  64 x KPAD
    float* Fs  = Bms + CC * KPAD;      //  64 x KPAD
    float* wqs = Fs  + CC * KPAD;      //   8 x KPAD
    float* AGs = wqs + 8 * KPAD;       //   8 x KPAD
    float* Ps  = AGs + 8 * KPAD;       //   8 x 64
    float* ss  = Ps  + 8 * CC;         // 128
    float* bs  = ss  + DD;             //  64
    float* k0s = bs  + CC;             //  64
    float* v0s = k0s + CC;             //  64
    float* qs  = v0s + CC;             //   8
    float* bqs = qs  + 8;              //   8
    const int cg = blockIdx.x, b = blockIdx.y, tid = threadIdx.x;

    const float* Gb = g_G + b * DD * DD;
    for (int i = tid; i < DD * 32; i += 256) {
        int r = i >> 5, c4 = (i & 31) << 2;
        *reinterpret_cast<float4*>(&Gs[r * KPAD + c4]) =
            *reinterpret_cast<const float4*>(&Gb[r * DD + c4]);
    }
    for (int i = tid; i < CC * 32; i += 256) {
        int r = i >> 5, c4 = (i & 31) << 2;
        *reinterpret_cast<float4*>(&Bms[r * KPAD + c4]) =
            *reinterpret_cast<const float4*>(&g_Bm[r * DD + c4]);
        *reinterpret_cast<float4*>(&Fs[r * KPAD + c4]) =
            *reinterpret_cast<const float4*>(&g_F[r * DD + c4]);
    }
    for (int i = tid; i < 8 * 32; i += 256) {
        int r = i >> 5, c4 = (i & 31) << 2;
        *reinterpret_cast<float4*>(&wqs[r * KPAD + c4]) =
            *reinterpret_cast<const float4*>(&wq[(cg * 8 + r) * DD + c4]);
    }
    if (tid < DD) ss[tid] = g_s[b * DD + tid];
    if (tid < CC) { k0s[tid] = g_k0[tid]; v0s[tid] = g_v0[tid]; }
    if (tid < 8)  bqs[tid] = bq[cg * 8 + tid];
    __syncthreads();

    if (tid < CC) {
        float a = 0.f;
        const float* r = &Bms[tid * KPAD];
        for (int d = 0; d < DD; d++) a = fmaf(r[d], ss[d], a);
        bs[tid] = a;
    } else if (tid < CC + 8) {
        int ci = tid - CC;
        float a = 0.f;
        const float* r = &wqs[ci * KPAD];
        for (int d = 0; d < DD; d++) a = fmaf(r[d], ss[d], a);
        qs[ci] = a;
    }
    {
        const int d = tid >> 1, cb = (tid & 1) * 4;
        float a0 = 0.f, a1 = 0.f, a2 = 0.f, a3 = 0.f;
        for (int d1 = 0; d1 < DD; d1++) {
            float g = Gs[d1 * KPAD + d];
            a0 = fmaf(g, wqs[(cb + 0) * KPAD + d1], a0);
            a1 = fmaf(g, wqs[(cb + 1) * KPAD + d1], a1);
            a2 = fmaf(g, wqs[(cb + 2) * KPAD + d1], a2);
            a3 = fmaf(g, wqs[(cb + 3) * KPAD + d1], a3);
        }
        AGs[(cb + 0) * KPAD + d] = a0;
        AGs[(cb + 1) * KPAD + d] = a1;
        AGs[(cb + 2) * KPAD + d] = a2;
        AGs[(cb + 3) * KPAD + d] = a3;
    }
    __syncthreads();

    {
        const int ci = tid >> 5, k = tid & 31;
#pragma unroll
        for (int rep = 0; rep < 2; rep++) {
            int kk = k + rep * 32;
            float acc = 0.f;
            for (int d4 = 0; d4 < 32; d4++) {
                float4 ag = *reinterpret_cast<const float4*>(&AGs[ci * KPAD + d4 * 4]);
                float4 bm = *reinterpret_cast<const float4*>(&Bms[kk * KPAD + d4 * 4]);
                acc = fmaf(ag.x, bm.x, acc); acc = fmaf(ag.y, bm.y, acc);
                acc = fmaf(ag.z, bm.z, acc); acc = fmaf(ag.w, bm.w, acc);
            }
            acc += qs[ci] * k0s[kk] + bqs[ci] * bs[kk] + (float)TT * bqs[ci] * k0s[kk];
            Ps[ci * CC + kk] = acc * 0.125f;  // /sqrt(64)
        }
    }
    __syncthreads();

    {
        const int w = tid >> 5, lane = tid & 31;
        float v0 = Ps[w * CC + lane], v1 = Ps[w * CC + lane + 32];
        float m = fmaxf(v0, v1);
#pragma unroll
        for (int off = 16; off; off >>= 1) m = fmaxf(m, __shfl_xor_sync(~0u, m, off));
        float e0 = expf(v0 - m), e1 = expf(v1 - m);
        float sum = e0 + e1;
#pragma unroll
        for (int off = 16; off; off >>= 1) sum += __shfl_xor_sync(~0u, sum, off);
        float inv = 1.f / sum;
        Ps[w * CC + lane]      = e0 * inv;
        Ps[w * CC + lane + 32] = e1 * inv;
    }
    __syncthreads();

    {
        const int d = tid >> 1, cb = (tid & 1) * 4;
        float a0 = 0.f, a1 = 0.f, a2 = 0.f, a3 = 0.f;
        for (int k = 0; k < CC; k++) {
            float f = Fs[k * KPAD + d];
            a0 = fmaf(Ps[(cb + 0) * CC + k], f, a0);
            a1 = fmaf(Ps[(cb + 1) * CC + k], f, a1);
            a2 = fmaf(Ps[(cb + 2) * CC + k], f, a2);
            a3 = fmaf(Ps[(cb + 3) * CC + k], f, a3);
        }
        float4 o = {a0, a1, a2, a3};
        *reinterpret_cast<float4*>(&g_Mt[b * DD * CC + d * CC + cg * 8 + cb]) = o;
    }
    if (tid < 8) {
        float acc = 0.f;
        for (int k = 0; k < CC; k++) acc = fmaf(Ps[tid * CC + k], v0s[k], acc);
        g_cv[b * CC + cg * 8 + tid] = acc;
    }
}

// ============ K3a: U = relu(M X + c). grid (256, 8), 256 thr, 2 CTA/SM ============
__global__ __launch_bounds__(256, 2) void k3a_u(const float* __restrict__ x) {
    extern __shared__ float sma[];
    float* Xs  = sma;               // 128 x 128 (X[d][t])
    float* Mts = Xs + DD * 128;     // 128 x 64  (M transposed)
    const int b   = blockIdx.y;
    const int t0  = blockIdx.x * 128;
    const int tid = threadIdx.x;

    {
        const float4* src = reinterpret_cast<const float4*>(g_Mt + b * DD * CC);
        float4* dst = reinterpret_cast<float4*>(Mts);
#pragma unroll
        for (int i = 0; i < 8; i++) dst[tid + 256 * i] = src[tid + 256 * i];
    }
    {
        const float* xb = x + (size_t)b * DD * TT + t0;
#pragma unroll
        for (int i = 0; i < 16; i++) {
            int f4 = tid + 256 * i;
            int d  = f4 >> 5;
            int tl = (f4 & 31) << 2;
            *reinterpret_cast<float4*>(&Xs[d * 128 + tl]) =
                *reinterpret_cast<const float4*>(xb + (size_t)d * TT + tl);
        }
    }
    __syncthreads();

    const int c0  = (tid >> 5) * 8;
    const int tl0 = (tid & 31) * 4;
    ull acc[4][4];
#pragma unroll
    for (int i = 0; i < 4; i++)
#pragma unroll
        for (int j = 0; j < 4; j++) acc[i][j] = 0ull;
#pragma unroll 8
    for (int k = 0; k < DD; k++) {
        float4 m0 = *reinterpret_cast<const float4*>(&Mts[k * CC + c0]);
        float4 m1 = *reinterpret_cast<const float4*>(&Mts[k * CC + c0 + 4]);
        float4 xv = *reinterpret_cast<const float4*>(&Xs[k * 128 + tl0]);
        ull mp0 = pk2(m0.x, m0.y), mp1 = pk2(m0.z, m0.w);
        ull mp2 = pk2(m1.x, m1.y), mp3 = pk2(m1.z, m1.w);
        float xa[4] = {xv.x, xv.y, xv.z, xv.w};
#pragma unroll
        for (int j = 0; j < 4; j++) {
            ull xd = pk2(xa[j], xa[j]);
            ffma2(acc[0][j], mp0, xd);
            ffma2(acc[1][j], mp1, xd);
            ffma2(acc[2][j], mp2, xd);
            ffma2(acc[3][j], mp3, xd);
        }
    }
    float* ub = g_U + (size_t)b * CC * TT + t0 + tl0;
#pragma unroll
    for (int cp = 0; cp < 4; cp++) {
        int c = c0 + 2 * cp;
        float cv0 = g_cv[b * CC + c], cv1 = g_cv[b * CC + c + 1];
        float4 r0, r1;
        float2 v0 = upk(acc[cp][0]), v1 = upk(acc[cp][1]);
        float2 v2 = upk(acc[cp][2]), v3 = upk(acc[cp][3]);
        r0.x = fmaxf(v0.x + cv0, 0.f); r1.x = fmaxf(v0.y + cv1, 0.f);
        r0.y = fmaxf(v1.x + cv0, 0.f); r1.y = fmaxf(v1.y + cv1, 0.f);
        r0.z = fmaxf(v2.x + cv0, 0.f); r1.z = fmaxf(v2.y + cv1, 0.f);
        r0.w = fmaxf(v3.x + cv0, 0.f); r1.w = fmaxf(v3.y + cv1, 0.f);
        *reinterpret_cast<float4*>(ub + (size_t)c * TT)       = r0;
        *reinterpret_cast<float4*>(ub + (size_t)(c + 1) * TT) = r1;
    }
}

// ============ K3b: y = mask * (wo @ U + bo). grid (256, 8), 256 thr, 2 CTA/SM ============
__global__ __launch_bounds__(256, 2) void k3b_y(const float* __restrict__ mask,
                                                const float* __restrict__ bo,
                                                float* __restrict__ y) {
    extern __shared__ float smb[];
    float* Us  = smb;               // 64 x 128
    float* Wts = Us + CC * 128;     // 64 x 128
    const int b   = blockIdx.y;
    const int t0  = blockIdx.x * 128;
    const int tid = threadIdx.x;

    {
        const float4* src = reinterpret_cast<const float4*>(g_wot);
        float4* dst = reinterpret_cast<float4*>(Wts);
#pragma unroll
        for (int i = 0; i < 8; i++) dst[tid + 256 * i] = src[tid + 256 * i];
    }
    {
        const float* ub = g_U + (size_t)b * CC * TT + t0;
#pragma unroll
        for (int i = 0; i < 8; i++) {
            int f4 = tid + 256 * i;
            int c  = f4 >> 5;
            int tl = (f4 & 31) << 2;
            *reinterpret_cast<float4*>(&Us[c * 128 + tl]) =
                *reinterpret_cast<const float4*>(ub + (size_t)c * TT + tl);
        }
    }
    __syncthreads();

    const int o0  = (tid >> 4) * 8;
    const int tl0 = (tid & 15) * 8;
    ull acc[4][8];
#pragma unroll
    for (int i = 0; i < 4; i++)
#pragma unroll
        for (int j = 0; j < 8; j++) acc[i][j] = 0ull;
#pragma unroll 4
    for (int k = 0; k < CC; k++) {
        float4 w0 = *reinterpret_cast<const float4*>(&Wts[k * DD + o0]);
        float4 w1 = *reinterpret_cast<const float4*>(&Wts[k * DD + o0 + 4]);
        float4 u0 = *reinterpret_cast<const float4*>(&Us[k * 128 + tl0]);
        float4 u1 = *reinterpret_cast<const float4*>(&Us[k * 128 + tl0 + 4]);
        ull wp0 = pk2(w0.x, w0.y), wp1 = pk2(w0.z, w0.w);
        ull wp2 = pk2(w1.x, w1.y), wp3 = pk2(w1.z, w1.w);
        float ua[8] = {u0.x, u0.y, u0.z, u0.w, u1.x, u1.y, u1.z, u1.w};
#pragma unroll
        for (int j = 0; j < 8; j++) {
            ull ud = pk2(ua[j], ua[j]);
            ffma2(acc[0][j], wp0, ud);
            ffma2(acc[1][j], wp1, ud);
            ffma2(acc[2][j], wp2, ud);
            ffma2(acc[3][j], wp3, ud);
        }
    }
    const float* mb = mask + (size_t)b * TT + t0 + tl0;
    float4 mq0 = *reinterpret_cast<const float4*>(mb);
    float4 mq1 = *reinterpret_cast<const float4*>(mb + 4);
    float mv[8] = {mq0.x, mq0.y, mq0.z, mq0.w, mq1.x, mq1.y, mq1.z, mq1.w};
    float* yb = y + (size_t)b * DD * TT + t0 + tl0;
#pragma unroll
    for (int op = 0; op < 4; op++) {
        int o = o0 + 2 * op;
        float bo0 = bo[o], bo1 = bo[o + 1];
        float r0[8], r1[8];
#pragma unroll
        for (int j = 0; j < 8; j++) {
            float2 v = upk(acc[op][j]);
            r0[j] = (v.x + bo0) * mv[j];
            r1[j] = (v.y + bo1) * mv[j];
        }
        float* row0 = yb + (size_t)o * TT;
        float* row1 = yb + (size_t)(o + 1) * TT;
        *reinterpret_cast<float4*>(row0)     = make_float4(r0[0], r0[1], r0[2], r0[3]);
        *reinterpret_cast<float4*>(row0 + 4) = make_float4(r0[4], r0[5], r0[6], r0[7]);
        *reinterpret_cast<float4*>(row1)     = make_float4(r1[0], r1[1], r1[2], r1[3]);
        *reinterpret_cast<float4*>(row1 + 4) = make_float4(r1[4], r1[5], r1[6], r1[7]);
    }
}

static const int SMEM_K2C = (DD * KPAD + CC * KPAD * 2 + 8 * KPAD * 2 + 8 * CC +
                             DD + 3 * CC + 16) * (int)sizeof(float);
static const int SMEM_K3A = (DD * 128 + DD * CC) * (int)sizeof(float);   // 96 KB
static const int SMEM_K3B = (CC * 128 + CC * DD) * (int)sizeof(float);   // 64 KB

extern "C" void kernel_launch(void* const* d_in, const int* in_sizes, int n_in,
                              void* d_out, int out_size) {
    const float* x1   = (const float*)d_in[0];
    const float* mask = (const float*)d_in[2];
    const float* wq   = (const float*)d_in[3];
    const float* bq   = (const float*)d_in[4];
    const float* wk   = (const float*)d_in[5];
    const float* bk   = (const float*)d_in[6];
    const float* wv   = (const float*)d_in[7];
    const float* bv   = (const float*)d_in[8];
    const float* we   = (const float*)d_in[9];
    const float* be   = (const float*)d_in[10];
    const float* wf   = (const float*)d_in[11];
    const float* bf   = (const float*)d_in[12];
    const float* wo   = (const float*)d_in[13];
    const float* bo   = (const float*)d_in[14];
    float* y = (float*)d_out;

    cudaFuncSetAttribute(k2c_attn, cudaFuncAttributeMaxDynamicSharedMemorySize, SMEM_K2C);
    cudaFuncSetAttribute(k3a_u,    cudaFuncAttributeMaxDynamicSharedMemorySize, SMEM_K3A);
    cudaFuncSetAttribute(k3b_y,    cudaFuncAttributeMaxDynamicSharedMemorySize, SMEM_K3B);

    void *pG = nullptr, *ps = nullptr;
    cudaGetSymbolAddress(&pG, g_G);
    cudaGetSymbolAddress(&ps, g_s);
    cudaMemsetAsync(pG, 0, BB * DD * DD * sizeof(float));
    cudaMemsetAsync(ps, 0, BB * DD * sizeof(float));

    k2a_weights<<<16, 256>>>(we, wk, bk, be, wf, wv, bv, bf, wo);
    k1_mma<<<dim3(16, 8), 256>>>(x1);
    k2c_attn<<<dim3(8, 8), 256, SMEM_K2C>>>(wq, bq);
    k3a_u<<<dim3(256, 8), 256, SMEM_K3A>>>(x1);
    k3b_y<<<dim3(256, 8), 256, SMEM_K3B>>>(mask, bo, y);
}

// round 7
// speedup vs baseline: 2.1349x; 1.0247x over previous
#include <cuda_runtime.h>
#include <cuda_bf16.h>
#include <cstdint>

#define BB 8
#define DD 128
#define TT 32768
#define CC 64

typedef unsigned long long ull;

// ---------------- f32x2 packed-FMA helpers ----------------
__device__ __forceinline__ void ffma2(ull& d, ull a, ull b) {
    asm("fma.rn.f32x2 %0, %1, %2, %0;" : "+l"(d) : "l"(a), "l"(b));
}
__device__ __forceinline__ ull pk2(float lo, float hi) {
    ull r; asm("mov.b64 %0, {%1, %2};" : "=l"(r) : "f"(lo), "f"(hi)); return r;
}
__device__ __forceinline__ float2 upk(ull v) {
    float2 r; asm("mov.b64 {%0, %1}, %2;" : "=f"(r.x), "=f"(r.y) : "l"(v)); return r;
}

// ---------------- warp-level bf16 MMA + ldmatrix ----------------
__device__ __forceinline__ void mma_bf16(float* d, const uint32_t* a, const uint32_t* b) {
    asm volatile(
        "mma.sync.aligned.m16n8k16.row.col.f32.bf16.bf16.f32 "
        "{%0,%1,%2,%3}, {%4,%5,%6,%7}, {%8,%9}, {%0,%1,%2,%3};"
        : "+f"(d[0]), "+f"(d[1]), "+f"(d[2]), "+f"(d[3])
        : "r"(a[0]), "r"(a[1]), "r"(a[2]), "r"(a[3]), "r"(b[0]), "r"(b[1]));
}
__device__ __forceinline__ void ldm_x4(uint32_t* r, uint32_t addr) {
    asm volatile("ldmatrix.sync.aligned.m8n8.x4.shared.b16 {%0,%1,%2,%3}, [%4];"
        : "=r"(r[0]), "=r"(r[1]), "=r"(r[2]), "=r"(r[3]) : "r"(addr));
}
__device__ __forceinline__ uint32_t pkbf(float v0, float v1) {
    uint32_t r; asm("cvt.rn.bf16x2.f32 %0, %1, %2;" : "=r"(r) : "f"(v1), "f"(v0)); return r;
}
__device__ __forceinline__ uint32_t smem_u32(const void* p) {
    uint32_t a;
    asm("{ .reg .u64 t; cvta.to.shared.u64 t, %1; cvt.u32.u64 %0, t; }" : "=r"(a) : "l"(p));
    return a;
}

// ---------------- scratch (static device globals) ----------------
__device__ float g_G[BB * DD * DD];     // per-batch Gram (full, symmetric)
__device__ float g_s[BB * DD];          // per-batch row sums
__device__ float g_Bm[CC * DD];         // we @ wk
__device__ float g_F[CC * DD];          // wf @ wv
__device__ float g_k0[CC];
__device__ float g_v0[CC];
__device__ float g_wot[CC * DD];        // wo transposed
__device__ float g_Mt[BB * DD * CC];    // M transposed [b][d][c]
__device__ float g_cv[BB * CC];
__device__ float g_U[BB * CC * TT];     // relu(M x + c) staging

// ================= K1 (mma.sync bf16 split, 2-product): Gram + row sums =================
// G = P + C + C^T with P = Xh Xh^T, C = Xh Xl^T (Xl Xh^T folded via transpose).
// grid (16, 8), 256 thr (8 warps). Each CTA: 2048 t in 32 chunks of 64.
#define TSEG 2048
#define TCH  64
#define NCH  (TSEG / TCH)
#define KSTR 72   // smem row stride (bf16 elems); 144 B, 16B-aligned

__global__ __launch_bounds__(256, 1) void k1_mma(const float* __restrict__ x) {
    __shared__ __align__(16) unsigned short sh_hi[DD][KSTR];
    __shared__ __align__(16) unsigned short sh_lo[DD][KSTR];
    const int tid = threadIdx.x;
    const int w   = tid >> 5, l = tid & 31;
    const int g   = l >> 2, tg = l & 3;
    const int q   = l >> 3, i5 = l & 7;
    const int b   = blockIdx.y;
    const int tseg = blockIdx.x * TSEG;
    const int d   = tid >> 1;
    const int kh  = (tid & 1) * 32;
    const float* xp = x + ((size_t)b * DD + d) * TT + tseg + kh;

    float accP[16][4], accC[16][4];
#pragma unroll
    for (int j = 0; j < 16; j++)
#pragma unroll
        for (int qq = 0; qq < 4; qq++) { accP[j][qq] = 0.f; accC[j][qq] = 0.f; }
    float srow = 0.f;

    const int m0 = w * 16;
    // ldmatrix lane base addresses
    const uint32_t sbh = smem_u32(sh_hi);
    const uint32_t sbl = smem_u32(sh_lo);
    // A(hi): q0:(m0+i,0) q1:(m0+8+i,0) q2:(m0+i,8) q3:(m0+8+i,8)
    const uint32_t pa  = sbh + (uint32_t)(((m0 + (q & 1) * 8 + i5) * KSTR + (q >> 1) * 8) * 2);
    // B: q0:(n0+i,0) q1:(n0+i,8) q2:(n0+8+i,0) q3:(n0+8+i,8)
    const uint32_t rb  = (uint32_t)((((q >> 1) * 8 + i5) * KSTR + (q & 1) * 8) * 2);
    const uint32_t pbh = sbh + rb;
    const uint32_t pbl = sbl + rb;

    float4 r[8], r2[8];
#pragma unroll
    for (int ii = 0; ii < 8; ii++) r[ii] = *reinterpret_cast<const float4*>(xp + 4 * ii);

    for (int c = 0; c < NCH; c++) {
        if (c + 1 < NCH) {
            const float* xn = xp + (c + 1) * TCH;
#pragma unroll
            for (int ii = 0; ii < 8; ii++) r2[ii] = *reinterpret_cast<const float4*>(xn + 4 * ii);
        }
        // ---- convert fp32 -> bf16 hi/lo, store K-major tiles ----
#pragma unroll
        for (int it = 0; it < 8; it++) {
            float4 v = r[it];
            srow += (v.x + v.y) + (v.z + v.w);
            uint32_t hp0 = pkbf(v.x, v.y), hp1 = pkbf(v.z, v.w);
            float h0 = __uint_as_float(hp0 << 16);
            float h1 = __uint_as_float(hp0 & 0xFFFF0000u);
            float h2 = __uint_as_float(hp1 << 16);
            float h3 = __uint_as_float(hp1 & 0xFFFF0000u);
            uint32_t lp0 = pkbf(v.x - h0, v.y - h1);
            uint32_t lp1 = pkbf(v.z - h2, v.w - h3);
            *reinterpret_cast<uint2*>(&sh_hi[d][kh + it * 4]) = make_uint2(hp0, hp1);
            *reinterpret_cast<uint2*>(&sh_lo[d][kh + it * 4]) = make_uint2(lp0, lp1);
        }
        __syncthreads();
        // ---- mma: P += Ah Bh^T, C += Ah Bl^T over 4 k-steps ----
#pragma unroll
        for (int ks = 0; ks < 4; ks++) {
            uint32_t ah[4];
            ldm_x4(ah, pa + ks * 32);
#pragma unroll
            for (int jp = 0; jp < 8; jp++) {
                const uint32_t boff = (uint32_t)(jp * 16 * KSTR * 2 + ks * 32);
                uint32_t bh[4], bl[4];
                ldm_x4(bh, pbh + boff);
                ldm_x4(bl, pbl + boff);
                mma_bf16(accP[2 * jp],     ah, bh);
                mma_bf16(accP[2 * jp + 1], ah, bh + 2);
                mma_bf16(accC[2 * jp],     ah, bl);
                mma_bf16(accC[2 * jp + 1], ah, bl + 2);
            }
        }
        __syncthreads();
#pragma unroll
        for (int ii = 0; ii < 8; ii++) r[ii] = r2[ii];
    }

    // ---- epilogue: G[r][c] += P+C ; G[c][r] += C ----
    float* Gb = g_G + b * DD * DD;
    const int row = m0 + g;
#pragma unroll
    for (int j = 0; j < 16; j++) {
        const int col = j * 8 + tg * 2;
        atomicAdd(&Gb[row * DD + col],           accP[j][0] + accC[j][0]);
        atomicAdd(&Gb[row * DD + col + 1],       accP[j][1] + accC[j][1]);
        atomicAdd(&Gb[(row + 8) * DD + col],     accP[j][2] + accC[j][2]);
        atomicAdd(&Gb[(row + 8) * DD + col + 1], accP[j][3] + accC[j][3]);
        atomicAdd(&Gb[col * DD + row],           accC[j][0]);
        atomicAdd(&Gb[(col + 1) * DD + row],     accC[j][1]);
        atomicAdd(&Gb[col * DD + row + 8],       accC[j][2]);
        atomicAdd(&Gb[(col + 1) * DD + row + 8], accC[j][3]);
    }
    atomicAdd(&g_s[b * DD + d], srow);
}

// ============ K2a: batch-independent weight products (grid 16) ============
__global__ void k2a_weights(const float* __restrict__ we, const float* __restrict__ wk,
                            const float* __restrict__ bk, const float* __restrict__ be,
                            const float* __restrict__ wf, const float* __restrict__ wv,
                            const float* __restrict__ bv, const float* __restrict__ bf,
                            const float* __restrict__ wo) {
    const int j = blockIdx.x, tid = threadIdx.x;
    if (j < 8) {
#pragma unroll
        for (int it = 0; it < 4; it++) {
            int idx = tid + 256 * it;
            int o = j * 8 + (idx >> 7);
            int d = idx & 127;
            float acc = 0.f;
            for (int c = 0; c < CC; c++) acc = fmaf(we[o * CC + c], wk[c * DD + d], acc);
            g_Bm[o * DD + d] = acc;
        }
        if (j == 0 && tid < CC) {
            float acc = be[tid];
            for (int c = 0; c < CC; c++) acc = fmaf(we[tid * CC + c], bk[c], acc);
            g_k0[tid] = acc;
        }
        if (j == 1) {
#pragma unroll
            for (int it = 0; it < 32; it++) {
                int idx = tid + 256 * it;
                int c = idx >> 7, o = idx & 127;
                g_wot[c * DD + o] = wo[o * CC + c];
            }
        }
    } else {
        int jj = j - 8;
#pragma unroll
        for (int it = 0; it < 4; it++) {
            int idx = tid + 256 * it;
            int o = jj * 8 + (idx >> 7);
            int d = idx & 127;
            float acc = 0.f;
            for (int c = 0; c < CC; c++) acc = fmaf(wf[o * CC + c], wv[c * DD + d], acc);
            g_F[o * DD + d] = acc;
        }
        if (j == 8 && tid < CC) {
            float acc = bf[tid];
            for (int c = 0; c < CC; c++) acc = fmaf(wf[tid * CC + c], bv[c], acc);
            g_v0[tid] = acc;
        }
    }
}

// ============ K2c: AG + S + softmax + M + cv, fused. grid (8 c-groups, 8 b) ============
#define KPAD 132
__global__ void k2c_attn(const float* __restrict__ wq, const float* __restrict__ bq) {
    extern __shared__ float sm2[];
    float* Gs  = sm2;                  // 128 x KPAD
    float* Bms = Gs  + DD * KPAD;      //  64 x KPAD
    float* Fs  = Bms + CC * KPAD;      //  64 x KPAD
    float* wqs = Fs  + CC * KPAD;      //   8 x KPAD
    float* AGs = wqs + 8 * KPAD;       //   8 x KPAD
    float* Ps  = AGs + 8 * KPAD;       //   8 x 64
    float* ss  = Ps  + 8 * CC;         // 128
    float* bs  = ss  + DD;             //  64
    float* k0s = bs  + CC;             //  64
    float* v0s = k0s + CC;             //  64
    float* qs  = v0s + CC;             //   8
    float* bqs = qs  + 8;              //   8
    const int cg = blockIdx.x, b = blockIdx.y, tid = threadIdx.x;

    const float* Gb = g_G + b * DD * DD;
    for (int i = tid; i < DD * 32; i += 256) {
        int r = i >> 5, c4 = (i & 31) << 2;
        *reinterpret_cast<float4*>(&Gs[r * KPAD + c4]) =
            *reinterpret_cast<const float4*>(&Gb[r * DD + c4]);
    }
    for (int i = tid; i < CC * 32; i += 256) {
        int r = i >> 5, c4 = (i & 31) << 2;
        *reinterpret_cast<float4*>(&Bms[r * KPAD + c4]) =
            *reinterpret_cast<const float4*>(&g_Bm[r * DD + c4]);
        *reinterpret_cast<float4*>(&Fs[r * KPAD + c4]) =
            *reinterpret_cast<const float4*>(&g_F[r * DD + c4]);
    }
    for (int i = tid; i < 8 * 32; i += 256) {
        int r = i >> 5, c4 = (i & 31) << 2;
        *reinterpret_cast<float4*>(&wqs[r * KPAD + c4]) =
            *reinterpret_cast<const float4*>(&wq[(cg * 8 + r) * DD + c4]);
    }
    if (tid < DD) ss[tid] = g_s[b * DD + tid];
    if (tid < CC) { k0s[tid] = g_k0[tid]; v0s[tid] = g_v0[tid]; }
    if (tid < 8)  bqs[tid] = bq[cg * 8 + tid];
    __syncthreads();

    if (tid < CC) {
        float a = 0.f;
        const float* r = &Bms[tid * KPAD];
        for (int d = 0; d < DD; d++) a = fmaf(r[d], ss[d], a);
        bs[tid] = a;
    } else if (tid < CC + 8) {
        int ci = tid - CC;
        float a = 0.f;
        const float* r = &wqs[ci * KPAD];
        for (int d = 0; d < DD; d++) a = fmaf(r[d], ss[d], a);
        qs[ci] = a;
    }
    {
        const int d = tid >> 1, cb = (tid & 1) * 4;
        float a0 = 0.f, a1 = 0.f, a2 = 0.f, a3 = 0.f;
        for (int d1 = 0; d1 < DD; d1++) {
            float g = Gs[d1 * KPAD + d];
            a0 = fmaf(g, wqs[(cb + 0) * KPAD + d1], a0);
            a1 = fmaf(g, wqs[(cb + 1) * KPAD + d1], a1);
            a2 = fmaf(g, wqs[(cb + 2) * KPAD + d1], a2);
            a3 = fmaf(g, wqs[(cb + 3) * KPAD + d1], a3);
        }
        AGs[(cb + 0) * KPAD + d] = a0;
        AGs[(cb + 1) * KPAD + d] = a1;
        AGs[(cb + 2) * KPAD + d] = a2;
        AGs[(cb + 3) * KPAD + d] = a3;
    }
    __syncthreads();

    {
        const int ci = tid >> 5, k = tid & 31;
#pragma unroll
        for (int rep = 0; rep < 2; rep++) {
            int kk = k + rep * 32;
            float acc = 0.f;
            for (int d4 = 0; d4 < 32; d4++) {
                float4 ag = *reinterpret_cast<const float4*>(&AGs[ci * KPAD + d4 * 4]);
                float4 bm = *reinterpret_cast<const float4*>(&Bms[kk * KPAD + d4 * 4]);
                acc = fmaf(ag.x, bm.x, acc); acc = fmaf(ag.y, bm.y, acc);
                acc = fmaf(ag.z, bm.z, acc); acc = fmaf(ag.w, bm.w, acc);
            }
            acc += qs[ci] * k0s[kk] + bqs[ci] * bs[kk] + (float)TT * bqs[ci] * k0s[kk];
            Ps[ci * CC + kk] = acc * 0.125f;  // /sqrt(64)
        }
    }
    __syncthreads();

    {
        const int w = tid >> 5, lane = tid & 31;
        float v0 = Ps[w * CC + lane], v1 = Ps[w * CC + lane + 32];
        float m = fmaxf(v0, v1);
#pragma unroll
        for (int off = 16; off; off >>= 1) m = fmaxf(m, __shfl_xor_sync(~0u, m, off));
        float e0 = expf(v0 - m), e1 = expf(v1 - m);
        float sum = e0 + e1;
#pragma unroll
        for (int off = 16; off; off >>= 1) sum += __shfl_xor_sync(~0u, sum, off);
        float inv = 1.f / sum;
        Ps[w * CC + lane]      = e0 * inv;
        Ps[w * CC + lane + 32] = e1 * inv;
    }
    __syncthreads();

    {
        const int d = tid >> 1, cb = (tid & 1) * 4;
        float a0 = 0.f, a1 = 0.f, a2 = 0.f, a3 = 0.f;
        for (int k = 0; k < CC; k++) {
            float f = Fs[k * KPAD + d];
            a0 = fmaf(Ps[(cb + 0) * CC + k], f, a0);
            a1 = fmaf(Ps[(cb + 1) * CC + k], f, a1);
            a2 = fmaf(Ps[(cb + 2) * CC + k], f, a2);
            a3 = fmaf(Ps[(cb + 3) * CC + k], f, a3);
        }
        float4 o = {a0, a1, a2, a3};
        *reinterpret_cast<float4*>(&g_Mt[b * DD * CC + d * CC + cg * 8 + cb]) = o;
    }
    if (tid < 8) {
        float acc = 0.f;
        for (int k = 0; k < CC; k++) acc = fmaf(Ps[tid * CC + k], v0s[k], acc);
        g_cv[b * CC + cg * 8 + tid] = acc;
    }
}

// ============ K3a: U = relu(M X + c). grid (256, 8), 256 thr, 2 CTA/SM ============
__global__ __launch_bounds__(256, 2) void k3a_u(const float* __restrict__ x) {
    extern __shared__ float sma[];
    float* Xs  = sma;               // 128 x 128 (X[d][t])
    float* Mts = Xs + DD * 128;     // 128 x 64  (M transposed)
    const int b   = blockIdx.y;
    const int t0  = blockIdx.x * 128;
    const int tid = threadIdx.x;

    {
        const float4* src = reinterpret_cast<const float4*>(g_Mt + b * DD * CC);
        float4* dst = reinterpret_cast<float4*>(Mts);
#pragma unroll
        for (int i = 0; i < 8; i++) dst[tid + 256 * i] = src[tid + 256 * i];
    }
    {
        const float* xb = x + (size_t)b * DD * TT + t0;
#pragma unroll
        for (int i = 0; i < 16; i++) {
            int f4 = tid + 256 * i;
            int d  = f4 >> 5;
            int tl = (f4 & 31) << 2;
            *reinterpret_cast<float4*>(&Xs[d * 128 + tl]) =
                *reinterpret_cast<const float4*>(xb + (size_t)d * TT + tl);
        }
    }
    __syncthreads();

    const int c0  = (tid >> 5) * 8;
    const int tl0 = (tid & 31) * 4;
    ull acc[4][4];
#pragma unroll
    for (int i = 0; i < 4; i++)
#pragma unroll
        for (int j = 0; j < 4; j++) acc[i][j] = 0ull;
#pragma unroll 8
    for (int k = 0; k < DD; k++) {
        float4 m0 = *reinterpret_cast<const float4*>(&Mts[k * CC + c0]);
        float4 m1 = *reinterpret_cast<const float4*>(&Mts[k * CC + c0 + 4]);
        float4 xv = *reinterpret_cast<const float4*>(&Xs[k * 128 + tl0]);
        ull mp0 = pk2(m0.x, m0.y), mp1 = pk2(m0.z, m0.w);
        ull mp2 = pk2(m1.x, m1.y), mp3 = pk2(m1.z, m1.w);
        float xa[4] = {xv.x, xv.y, xv.z, xv.w};
#pragma unroll
        for (int j = 0; j < 4; j++) {
            ull xd = pk2(xa[j], xa[j]);
            ffma2(acc[0][j], mp0, xd);
            ffma2(acc[1][j], mp1, xd);
            ffma2(acc[2][j], mp2, xd);
            ffma2(acc[3][j], mp3, xd);
        }
    }
    float* ub = g_U + (size_t)b * CC * TT + t0 + tl0;
#pragma unroll
    for (int cp = 0; cp < 4; cp++) {
        int c = c0 + 2 * cp;
        float cv0 = g_cv[b * CC + c], cv1 = g_cv[b * CC + c + 1];
        float4 r0, r1;
        float2 v0 = upk(acc[cp][0]), v1 = upk(acc[cp][1]);
        float2 v2 = upk(acc[cp][2]), v3 = upk(acc[cp][3]);
        r0.x = fmaxf(v0.x + cv0, 0.f); r1.x = fmaxf(v0.y + cv1, 0.f);
        r0.y = fmaxf(v1.x + cv0, 0.f); r1.y = fmaxf(v1.y + cv1, 0.f);
        r0.z = fmaxf(v2.x + cv0, 0.f); r1.z = fmaxf(v2.y + cv1, 0.f);
        r0.w = fmaxf(v3.x + cv0, 0.f); r1.w = fmaxf(v3.y + cv1, 0.f);
        *reinterpret_cast<float4*>(ub + (size_t)c * TT)       = r0;
        *reinterpret_cast<float4*>(ub + (size_t)(c + 1) * TT) = r1;
    }
}

// ============ K3b: y = mask * (wo @ U + bo). grid (256, 8), 256 thr, 2 CTA/SM ============
__global__ __launch_bounds__(256, 2) void k3b_y(const float* __restrict__ mask,
                                                const float* __restrict__ bo,
                                                float* __restrict__ y) {
    extern __shared__ float smb[];
    float* Us  = smb;               // 64 x 128
    float* Wts = Us + CC * 128;     // 64 x 128
    const int b   = blockIdx.y;
    const int t0  = blockIdx.x * 128;
    const int tid = threadIdx.x;

    {
        const float4* src = reinterpret_cast<const float4*>(g_wot);
        float4* dst = reinterpret_cast<float4*>(Wts);
#pragma unroll
        for (int i = 0; i < 8; i++) dst[tid + 256 * i] = src[tid + 256 * i];
    }
    {
        const float* ub = g_U + (size_t)b * CC * TT + t0;
#pragma unroll
        for (int i = 0; i < 8; i++) {
            int f4 = tid + 256 * i;
            int c  = f4 >> 5;
            int tl = (f4 & 31) << 2;
            *reinterpret_cast<float4*>(&Us[c * 128 + tl]) =
                *reinterpret_cast<const float4*>(ub + (size_t)c * TT + tl);
        }
    }
    __syncthreads();

    const int o0  = (tid >> 4) * 8;
    const int tl0 = (tid & 15) * 8;
    ull acc[4][8];
#pragma unroll
    for (int i = 0; i < 4; i++)
#pragma unroll
        for (int j = 0; j < 8; j++) acc[i][j] = 0ull;
#pragma unroll 4
    for (int k = 0; k < CC; k++) {
        float4 w0 = *reinterpret_cast<const float4*>(&Wts[k * DD + o0]);
        float4 w1 = *reinterpret_cast<const float4*>(&Wts[k * DD + o0 + 4]);
        float4 u0 = *reinterpret_cast<const float4*>(&Us[k * 128 + tl0]);
        float4 u1 = *reinterpret_cast<const float4*>(&Us[k * 128 + tl0 + 4]);
        ull wp0 = pk2(w0.x, w0.y), wp1 = pk2(w0.z, w0.w);
        ull wp2 = pk2(w1.x, w1.y), wp3 = pk2(w1.z, w1.w);
        float ua[8] = {u0.x, u0.y, u0.z, u0.w, u1.x, u1.y, u1.z, u1.w};
#pragma unroll
        for (int j = 0; j < 8; j++) {
            ull ud = pk2(ua[j], ua[j]);
            ffma2(acc[0][j], wp0, ud);
            ffma2(acc[1][j], wp1, ud);
            ffma2(acc[2][j], wp2, ud);
            ffma2(acc[3][j], wp3, ud);
        }
    }
    const float* mb = mask + (size_t)b * TT + t0 + tl0;
    float4 mq0 = *reinterpret_cast<const float4*>(mb);
    float4 mq1 = *reinterpret_cast<const float4*>(mb + 4);
    float mv[8] = {mq0.x, mq0.y, mq0.z, mq0.w, mq1.x, mq1.y, mq1.z, mq1.w};
    float* yb = y + (size_t)b * DD * TT + t0 + tl0;
#pragma unroll
    for (int op = 0; op < 4; op++) {
        int o = o0 + 2 * op;
        float bo0 = bo[o], bo1 = bo[o + 1];
        float r0[8], r1[8];
#pragma unroll
        for (int j = 0; j < 8; j++) {
            float2 v = upk(acc[op][j]);
            r0[j] = (v.x + bo0) * mv[j];
            r1[j] = (v.y + bo1) * mv[j];
        }
        float* row0 = yb + (size_t)o * TT;
        float* row1 = yb + (size_t)(o + 1) * TT;
        *reinterpret_cast<float4*>(row0)     = make_float4(r0[0], r0[1], r0[2], r0[3]);
        *reinterpret_cast<float4*>(row0 + 4) = make_float4(r0[4], r0[5], r0[6], r0[7]);
        *reinterpret_cast<float4*>(row1)     = make_float4(r1[0], r1[1], r1[2], r1[3]);
        *reinterpret_cast<float4*>(row1 + 4) = make_float4(r1[4], r1[5], r1[6], r1[7]);
    }
}

static const int SMEM_K2C = (DD * KPAD + CC * KPAD * 2 + 8 * KPAD * 2 + 8 * CC +
                             DD + 3 * CC + 16) * (int)sizeof(float);
static const int SMEM_K3A = (DD * 128 + DD * CC) * (int)sizeof(float);   // 96 KB
static const int SMEM_K3B = (CC * 128 + CC * DD) * (int)sizeof(float);   // 64 KB

extern "C" void kernel_launch(void* const* d_in, const int* in_sizes, int n_in,
                              void* d_out, int out_size) {
    const float* x1   = (const float*)d_in[0];
    const float* mask = (const float*)d_in[2];
    const float* wq   = (const float*)d_in[3];
    const float* bq   = (const float*)d_in[4];
    const float* wk   = (const float*)d_in[5];
    const float* bk   = (const float*)d_in[6];
    const float* wv   = (const float*)d_in[7];
    const float* bv   = (const float*)d_in[8];
    const float* we   = (const float*)d_in[9];
    const float* be   = (const float*)d_in[10];
    const float* wf   = (const float*)d_in[11];
    const float* bf   = (const float*)d_in[12];
    const float* wo   = (const float*)d_in[13];
    const float* bo   = (const float*)d_in[14];
    float* y = (float*)d_out;

    cudaFuncSetAttribute(k2c_attn, cudaFuncAttributeMaxDynamicSharedMemorySize, SMEM_K2C);
    cudaFuncSetAttribute(k3a_u,    cudaFuncAttributeMaxDynamicSharedMemorySize, SMEM_K3A);
    cudaFuncSetAttribute(k3b_y,    cudaFuncAttributeMaxDynamicSharedMemorySize, SMEM_K3B);

    void *pG = nullptr, *ps = nullptr;
    cudaGetSymbolAddress(&pG, g_G);
    cudaGetSymbolAddress(&ps, g_s);
    cudaMemsetAsync(pG, 0, BB * DD * DD * sizeof(float));
    cudaMemsetAsync(ps, 0, BB * DD * sizeof(float));

    k2a_weights<<<16, 256>>>(we, wk, bk, be, wf, wv, bv, bf, wo);
    k1_mma<<<dim3(16, 8), 256>>>(x1);
    k2c_attn<<<dim3(8, 8), 256, SMEM_K2C>>>(wq, bq);
    k3a_u<<<dim3(256, 8), 256, SMEM_K3A>>>(x1);
    k3b_y<<<dim3(256, 8), 256, SMEM_K3B>>>(mask, bo, y);
}

// round 8
// speedup vs baseline: 2.3204x; 1.0869x over previous
#include <cuda_runtime.h>
#include <cuda_bf16.h>
#include <cstdint>

#define BB 8
#define DD 128
#define TT 32768
#define CC 64

typedef unsigned long long ull;

// ---------------- f32x2 packed-FMA helpers ----------------
__device__ __forceinline__ void ffma2(ull& d, ull a, ull b) {
    asm("fma.rn.f32x2 %0, %1, %2, %0;" : "+l"(d) : "l"(a), "l"(b));
}
__device__ __forceinline__ ull pk2(float lo, float hi) {
    ull r; asm("mov.b64 %0, {%1, %2};" : "=l"(r) : "f"(lo), "f"(hi)); return r;
}
__device__ __forceinline__ float2 upk(ull v) {
    float2 r; asm("mov.b64 {%0, %1}, %2;" : "=f"(r.x), "=f"(r.y) : "l"(v)); return r;
}

// ---------------- warp-level bf16 MMA + ldmatrix ----------------
__device__ __forceinline__ void mma_bf16(float* d, const uint32_t* a, const uint32_t* b) {
    asm volatile(
        "mma.sync.aligned.m16n8k16.row.col.f32.bf16.bf16.f32 "
        "{%0,%1,%2,%3}, {%4,%5,%6,%7}, {%8,%9}, {%0,%1,%2,%3};"
        : "+f"(d[0]), "+f"(d[1]), "+f"(d[2]), "+f"(d[3])
        : "r"(a[0]), "r"(a[1]), "r"(a[2]), "r"(a[3]), "r"(b[0]), "r"(b[1]));
}
__device__ __forceinline__ void ldm_x4(uint32_t* r, uint32_t addr) {
    asm volatile("ldmatrix.sync.aligned.m8n8.x4.shared.b16 {%0,%1,%2,%3}, [%4];"
        : "=r"(r[0]), "=r"(r[1]), "=r"(r[2]), "=r"(r[3]) : "r"(addr));
}
__device__ __forceinline__ uint32_t pkbf(float v0, float v1) {
    uint32_t r; asm("cvt.rn.bf16x2.f32 %0, %1, %2;" : "=r"(r) : "f"(v1), "f"(v0)); return r;
}
__device__ __forceinline__ uint32_t smem_u32(const void* p) {
    uint32_t a;
    asm("{ .reg .u64 t; cvta.to.shared.u64 t, %1; cvt.u32.u64 %0, t; }" : "=r"(a) : "l"(p));
    return a;
}

// ---------------- scratch (static device globals) ----------------
__device__ float g_G[BB * DD * DD];     // per-batch Gram (full, symmetric)
__device__ float g_s[BB * DD];          // per-batch row sums
__device__ float g_Bm[CC * DD];         // we @ wk
__device__ float g_F[CC * DD];          // wf @ wv
__device__ float g_k0[CC];
__device__ float g_v0[CC];
__device__ float g_wot[CC * DD];        // wo transposed
__device__ float g_Mt[BB * DD * CC];    // M transposed [b][d][c]
__device__ float g_cv[BB * CC];
__device__ float g_U[BB * CC * TT];     // relu(M x + c) staging

// no-op kernels: position k1_mma at ncu launch index 5 (-s 5 -c 1)
__global__ void k_nop() {}

// ================= K1 (mma.sync bf16 split, 512 thr): Gram + row sums =================
// G = P + C + C^T, P = Xh Xh^T, C = Xh Xl^T.
// 16 warps = 8 m-stripes x 2 n-halves -> 64 acc regs/thread, 4 warps/SMSP.
// grid (16, 8). Each CTA: 2048 t in 32 chunks of 64.
#define TSEG 2048
#define TCH  64
#define NCH  (TSEG / TCH)
#define KSTR 72   // smem row stride (bf16 elems); 144 B

__global__ __launch_bounds__(512, 1) void k1_mma(const float* __restrict__ x) {
    __shared__ __align__(16) unsigned short sh_hi[DD][KSTR];
    __shared__ __align__(16) unsigned short sh_lo[DD][KSTR];
    const int tid = threadIdx.x;
    const int w   = tid >> 5, l = tid & 31;
    const int g   = l >> 2, tg = l & 3;
    const int q   = l >> 3, i5 = l & 7;
    const int b   = blockIdx.y;
    const int tseg = blockIdx.x * TSEG;
    const int d   = tid >> 2;            // 0..127
    const int kh  = (tid & 3) * 16;      // 0,16,32,48
    const float* xp = x + ((size_t)b * DD + d) * TT + tseg + kh;

    float accP[8][4], accC[8][4];
#pragma unroll
    for (int j = 0; j < 8; j++)
#pragma unroll
        for (int qq = 0; qq < 4; qq++) { accP[j][qq] = 0.f; accC[j][qq] = 0.f; }
    float srow = 0.f;

    const int m0 = (w & 7) * 16;
    const int n0 = (w >> 3) * 64;
    const uint32_t sbh = smem_u32(sh_hi);
    const uint32_t sbl = smem_u32(sh_lo);
    // A(hi) lane base: q0:(m0+i,0) q1:(m0+8+i,0) q2:(m0+i,8) q3:(m0+8+i,8)
    const uint32_t pa  = sbh + (uint32_t)(((m0 + (q & 1) * 8 + i5) * KSTR + (q >> 1) * 8) * 2);
    // B lane base (n0 folded in): q0:(n+i,0) q1:(n+i,8) q2:(n+8+i,0) q3:(n+8+i,8)
    const uint32_t rb  = (uint32_t)(((n0 + (q >> 1) * 8 + i5) * KSTR + (q & 1) * 8) * 2);
    const uint32_t pbh = sbh + rb;
    const uint32_t pbl = sbl + rb;

    float4 r[4], r2[4];
#pragma unroll
    for (int ii = 0; ii < 4; ii++) r[ii] = *reinterpret_cast<const float4*>(xp + 4 * ii);

    for (int c = 0; c < NCH; c++) {
        if (c + 1 < NCH) {
            const float* xn = xp + (c + 1) * TCH;
#pragma unroll
            for (int ii = 0; ii < 4; ii++) r2[ii] = *reinterpret_cast<const float4*>(xn + 4 * ii);
        }
        // ---- convert fp32 -> bf16 hi/lo, store K-major tiles ----
#pragma unroll
        for (int it = 0; it < 4; it++) {
            float4 v = r[it];
            srow += (v.x + v.y) + (v.z + v.w);
            uint32_t hp0 = pkbf(v.x, v.y), hp1 = pkbf(v.z, v.w);
            float h0 = __uint_as_float(hp0 << 16);
            float h1 = __uint_as_float(hp0 & 0xFFFF0000u);
            float h2 = __uint_as_float(hp1 << 16);
            float h3 = __uint_as_float(hp1 & 0xFFFF0000u);
            uint32_t lp0 = pkbf(v.x - h0, v.y - h1);
            uint32_t lp1 = pkbf(v.z - h2, v.w - h3);
            *reinterpret_cast<uint2*>(&sh_hi[d][kh + it * 4]) = make_uint2(hp0, hp1);
            *reinterpret_cast<uint2*>(&sh_lo[d][kh + it * 4]) = make_uint2(lp0, lp1);
        }
        __syncthreads();
        // ---- mma: P += Ah Bh^T, C += Ah Bl^T over 4 k-steps, 8 n-tiles ----
#pragma unroll
        for (int ks = 0; ks < 4; ks++) {
            uint32_t ah[4];
            ldm_x4(ah, pa + ks * 32);
#pragma unroll
            for (int jp = 0; jp < 4; jp++) {
                const uint32_t boff = (uint32_t)(jp * 16 * KSTR * 2 + ks * 32);
                uint32_t bh[4], bl[4];
                ldm_x4(bh, pbh + boff);
                ldm_x4(bl, pbl + boff);
                mma_bf16(accP[2 * jp],     ah, bh);
                mma_bf16(accP[2 * jp + 1], ah, bh + 2);
                mma_bf16(accC[2 * jp],     ah, bl);
                mma_bf16(accC[2 * jp + 1], ah, bl + 2);
            }
        }
        __syncthreads();
#pragma unroll
        for (int ii = 0; ii < 4; ii++) r[ii] = r2[ii];
    }

    // ---- epilogue: G[r][c] += P+C ; G[c][r] += C ----
    float* Gb = g_G + b * DD * DD;
    const int row = m0 + g;
#pragma unroll
    for (int j = 0; j < 8; j++) {
        const int col = n0 + j * 8 + tg * 2;
        atomicAdd(&Gb[row * DD + col],           accP[j][0] + accC[j][0]);
        atomicAdd(&Gb[row * DD + col + 1],       accP[j][1] + accC[j][1]);
        atomicAdd(&Gb[(row + 8) * DD + col],     accP[j][2] + accC[j][2]);
        atomicAdd(&Gb[(row + 8) * DD + col + 1], accP[j][3] + accC[j][3]);
        atomicAdd(&Gb[col * DD + row],           accC[j][0]);
        atomicAdd(&Gb[(col + 1) * DD + row],     accC[j][1]);
        atomicAdd(&Gb[col * DD + row + 8],       accC[j][2]);
        atomicAdd(&Gb[(col + 1) * DD + row + 8], accC[j][3]);
    }
    atomicAdd(&g_s[b * DD + d], srow);
}

// ============ K2a: batch-independent weight products (grid 16) ============
__global__ void k2a_weights(const float* __restrict__ we, const float* __restrict__ wk,
                            const float* __restrict__ bk, const float* __restrict__ be,
                            const float* __restrict__ wf, const float* __restrict__ wv,
                            const float* __restrict__ bv, const float* __restrict__ bf,
                            const float* __restrict__ wo) {
    const int j = blockIdx.x, tid = threadIdx.x;
    if (j < 8) {
#pragma unroll
        for (int it = 0; it < 4; it++) {
            int idx = tid + 256 * it;
            int o = j * 8 + (idx >> 7);
            int d = idx & 127;
            float acc = 0.f;
            for (int c = 0; c < CC; c++) acc = fmaf(we[o * CC + c], wk[c * DD + d], acc);
            g_Bm[o * DD + d] = acc;
        }
        if (j == 0 && tid < CC) {
            float acc = be[tid];
            for (int c = 0; c < CC; c++) acc = fmaf(we[tid * CC + c], bk[c], acc);
            g_k0[tid] = acc;
        }
        if (j == 1) {
#pragma unroll
            for (int it = 0; it < 32; it++) {
                int idx = tid + 256 * it;
                int c = idx >> 7, o = idx & 127;
                g_wot[c * DD + o] = wo[o * CC + c];
            }
        }
    } else {
        int jj = j - 8;
#pragma unroll
        for (int it = 0; it < 4; it++) {
            int idx = tid + 256 * it;
            int o = jj * 8 + (idx >> 7);
            int d = idx & 127;
            float acc = 0.f;
            for (int c = 0; c < CC; c++) acc = fmaf(wf[o * CC + c], wv[c * DD + d], acc);
            g_F[o * DD + d] = acc;
        }
        if (j == 8 && tid < CC) {
            float acc = bf[tid];
            for (int c = 0; c < CC; c++) acc = fmaf(wf[tid * CC + c], bv[c], acc);
            g_v0[tid] = acc;
        }
    }
}

// ============ K2c: AG + S + softmax + M + cv, fused. grid (8 c-groups, 8 b) ============
#define KPAD 132
__global__ void k2c_attn(const float* __restrict__ wq, const float* __restrict__ bq) {
    extern __shared__ float sm2[];
    float* Gs  = sm2;                  // 128 x KPAD
    float* Bms = Gs  + DD * KPAD;      //  64 x KPAD
    float* Fs  = Bms + CC * KPAD;      //  64 x KPAD
    float* wqs = Fs  + CC * KPAD;      //   8 x KPAD
    float* AGs = wqs + 8 * KPAD;       //   8 x KPAD
    float* Ps  = AGs + 8 * KPAD;       //   8 x 64
    float* ss  = Ps  + 8 * CC;         // 128
    float* bs  = ss  + DD;             //  64
    float* k0s = bs  + CC;             //  64
    float* v0s = k0s + CC;             //  64
    float* qs  = v0s + CC;             //   8
    float* bqs = qs  + 8;              //   8
    const int cg = blockIdx.x, b = blockIdx.y, tid = threadIdx.x;

    const float* Gb = g_G + b * DD * DD;
    for (int i = tid; i < DD * 32; i += 256) {
        int r = i >> 5, c4 = (i & 31) << 2;
        *reinterpret_cast<float4*>(&Gs[r * KPAD + c4]) =
            *reinterpret_cast<const float4*>(&Gb[r * DD + c4]);
    }
    for (int i = tid; i < CC * 32; i += 256) {
        int r = i >> 5, c4 = (i & 31) << 2;
        *reinterpret_cast<float4*>(&Bms[r * KPAD + c4]) =
            *reinterpret_cast<const float4*>(&g_Bm[r * DD + c4]);
        *reinterpret_cast<float4*>(&Fs[r * KPAD + c4]) =
            *reinterpret_cast<const float4*>(&g_F[r * DD + c4]);
    }
    for (int i = tid; i < 8 * 32; i += 256) {
        int r = i >> 5, c4 = (i & 31) << 2;
        *reinterpret_cast<float4*>(&wqs[r * KPAD + c4]) =
            *reinterpret_cast<const float4*>(&wq[(cg * 8 + r) * DD + c4]);
    }
    if (tid < DD) ss[tid] = g_s[b * DD + tid];
    if (tid < CC) { k0s[tid] = g_k0[tid]; v0s[tid] = g_v0[tid]; }
    if (tid < 8)  bqs[tid] = bq[cg * 8 + tid];
    __syncthreads();

    if (tid < CC) {
        float a = 0.f;
        const float* r = &Bms[tid * KPAD];
        for (int d = 0; d < DD; d++) a = fmaf(r[d], ss[d], a);
        bs[tid] = a;
    } else if (tid < CC + 8) {
        int ci = tid - CC;
        float a = 0.f;
        const float* r = &wqs[ci * KPAD];
        for (int d = 0; d < DD; d++) a = fmaf(r[d], ss[d], a);
        qs[ci] = a;
    }
    {
        const int d = tid >> 1, cb = (tid & 1) * 4;
        float a0 = 0.f, a1 = 0.f, a2 = 0.f, a3 = 0.f;
        for (int d1 = 0; d1 < DD; d1++) {
            float g = Gs[d1 * KPAD + d];
            a0 = fmaf(g, wqs[(cb + 0) * KPAD + d1], a0);
            a1 = fmaf(g, wqs[(cb + 1) * KPAD + d1], a1);
            a2 = fmaf(g, wqs[(cb + 2) * KPAD + d1], a2);
            a3 = fmaf(g, wqs[(cb + 3) * KPAD + d1], a3);
        }
        AGs[(cb + 0) * KPAD + d] = a0;
        AGs[(cb + 1) * KPAD + d] = a1;
        AGs[(cb + 2) * KPAD + d] = a2;
        AGs[(cb + 3) * KPAD + d] = a3;
    }
    __syncthreads();

    {
        const int ci = tid >> 5, k = tid & 31;
#pragma unroll
        for (int rep = 0; rep < 2; rep++) {
            int kk = k + rep * 32;
            float acc = 0.f;
            for (int d4 = 0; d4 < 32; d4++) {
                float4 ag = *reinterpret_cast<const float4*>(&AGs[ci * KPAD + d4 * 4]);
                float4 bm = *reinterpret_cast<const float4*>(&Bms[kk * KPAD + d4 * 4]);
                acc = fmaf(ag.x, bm.x, acc); acc = fmaf(ag.y, bm.y, acc);
                acc = fmaf(ag.z, bm.z, acc); acc = fmaf(ag.w, bm.w, acc);
            }
            acc += qs[ci] * k0s[kk] + bqs[ci] * bs[kk] + (float)TT * bqs[ci] * k0s[kk];
            Ps[ci * CC + kk] = acc * 0.125f;  // /sqrt(64)
        }
    }
    __syncthreads();

    {
        const int w = tid >> 5, lane = tid & 31;
        float v0 = Ps[w * CC + lane], v1 = Ps[w * CC + lane + 32];
        float m = fmaxf(v0, v1);
#pragma unroll
        for (int off = 16; off; off >>= 1) m = fmaxf(m, __shfl_xor_sync(~0u, m, off));
        float e0 = expf(v0 - m), e1 = expf(v1 - m);
        float sum = e0 + e1;
#pragma unroll
        for (int off = 16; off; off >>= 1) sum += __shfl_xor_sync(~0u, sum, off);
        float inv = 1.f / sum;
        Ps[w * CC + lane]      = e0 * inv;
        Ps[w * CC + lane + 32] = e1 * inv;
    }
    __syncthreads();

    {
        const int d = tid >> 1, cb = (tid & 1) * 4;
        float a0 = 0.f, a1 = 0.f, a2 = 0.f, a3 = 0.f;
        for (int k = 0; k < CC; k++) {
            float f = Fs[k * KPAD + d];
            a0 = fmaf(Ps[(cb + 0) * CC + k], f, a0);
            a1 = fmaf(Ps[(cb + 1) * CC + k], f, a1);
            a2 = fmaf(Ps[(cb + 2) * CC + k], f, a2);
            a3 = fmaf(Ps[(cb + 3) * CC + k], f, a3);
        }
        float4 o = {a0, a1, a2, a3};
        *reinterpret_cast<float4*>(&g_Mt[b * DD * CC + d * CC + cg * 8 + cb]) = o;
    }
    if (tid < 8) {
        float acc = 0.f;
        for (int k = 0; k < CC; k++) acc = fmaf(Ps[tid * CC + k], v0s[k], acc);
        g_cv[b * CC + cg * 8 + tid] = acc;
    }
}

// ============ K3a: U = relu(M X + c). grid (256, 8), 256 thr, 2 CTA/SM ============
__global__ __launch_bounds__(256, 2) void k3a_u(const float* __restrict__ x) {
    extern __shared__ float sma[];
    float* Xs  = sma;               // 128 x 128 (X[d][t])
    float* Mts = Xs + DD * 128;     // 128 x 64  (M transposed)
    const int b   = blockIdx.y;
    const int t0  = blockIdx.x * 128;
    const int tid = threadIdx.x;

    {
        const float4* src = reinterpret_cast<const float4*>(g_Mt + b * DD * CC);
        float4* dst = reinterpret_cast<float4*>(Mts);
#pragma unroll
        for (int i = 0; i < 8; i++) dst[tid + 256 * i] = src[tid + 256 * i];
    }
    {
        const float* xb = x + (size_t)b * DD * TT + t0;
#pragma unroll
        for (int i = 0; i < 16; i++) {
            int f4 = tid + 256 * i;
            int d  = f4 >> 5;
            int tl = (f4 & 31) << 2;
            *reinterpret_cast<float4*>(&Xs[d * 128 + tl]) =
                *reinterpret_cast<const float4*>(xb + (size_t)d * TT + tl);
        }
    }
    __syncthreads();

    const int c0  = (tid >> 5) * 8;
    const int tl0 = (tid & 31) * 4;
    ull acc[4][4];
#pragma unroll
    for (int i = 0; i < 4; i++)
#pragma unroll
        for (int j = 0; j < 4; j++) acc[i][j] = 0ull;
#pragma unroll 8
    for (int k = 0; k < DD; k++) {
        float4 m0 = *reinterpret_cast<const float4*>(&Mts[k * CC + c0]);
        float4 m1 = *reinterpret_cast<const float4*>(&Mts[k * CC + c0 + 4]);
        float4 xv = *reinterpret_cast<const float4*>(&Xs[k * 128 + tl0]);
        ull mp0 = pk2(m0.x, m0.y), mp1 = pk2(m0.z, m0.w);
        ull mp2 = pk2(m1.x, m1.y), mp3 = pk2(m1.z, m1.w);
        float xa[4] = {xv.x, xv.y, xv.z, xv.w};
#pragma unroll
        for (int j = 0; j < 4; j++) {
            ull xd = pk2(xa[j], xa[j]);
            ffma2(acc[0][j], mp0, xd);
            ffma2(acc[1][j], mp1, xd);
            ffma2(acc[2][j], mp2, xd);
            ffma2(acc[3][j], mp3, xd);
        }
    }
    float* ub = g_U + (size_t)b * CC * TT + t0 + tl0;
#pragma unroll
    for (int cp = 0; cp < 4; cp++) {
        int c = c0 + 2 * cp;
        float cv0 = g_cv[b * CC + c], cv1 = g_cv[b * CC + c + 1];
        float4 r0, r1;
        float2 v0 = upk(acc[cp][0]), v1 = upk(acc[cp][1]);
        float2 v2 = upk(acc[cp][2]), v3 = upk(acc[cp][3]);
        r0.x = fmaxf(v0.x + cv0, 0.f); r1.x = fmaxf(v0.y + cv1, 0.f);
        r0.y = fmaxf(v1.x + cv0, 0.f); r1.y = fmaxf(v1.y + cv1, 0.f);
        r0.z = fmaxf(v2.x + cv0, 0.f); r1.z = fmaxf(v2.y + cv1, 0.f);
        r0.w = fmaxf(v3.x + cv0, 0.f); r1.w = fmaxf(v3.y + cv1, 0.f);
        *reinterpret_cast<float4*>(ub + (size_t)c * TT)       = r0;
        *reinterpret_cast<float4*>(ub + (size_t)(c + 1) * TT) = r1;
    }
}

// ============ K3b: y = mask * (wo @ U + bo). grid (256, 8), 256 thr, 2 CTA/SM ============
__global__ __launch_bounds__(256, 2) void k3b_y(const float* __restrict__ mask,
                                                const float* __restrict__ bo,
                                                float* __restrict__ y) {
    extern __shared__ float smb[];
    float* Us  = smb;               // 64 x 128
    float* Wts = Us + CC * 128;     // 64 x 128
    const int b   = blockIdx.y;
    const int t0  = blockIdx.x * 128;
    const int tid = threadIdx.x;

    {
        const float4* src = reinterpret_cast<const float4*>(g_wot);
        float4* dst = reinterpret_cast<float4*>(Wts);
#pragma unroll
        for (int i = 0; i < 8; i++) dst[tid + 256 * i] = src[tid + 256 * i];
    }
    {
        const float* ub = g_U + (size_t)b * CC * TT + t0;
#pragma unroll
        for (int i = 0; i < 8; i++) {
            int f4 = tid + 256 * i;
            int c  = f4 >> 5;
            int tl = (f4 & 31) << 2;
            *reinterpret_cast<float4*>(&Us[c * 128 + tl]) =
                *reinterpret_cast<const float4*>(ub + (size_t)c * TT + tl);
        }
    }
    __syncthreads();

    const int o0  = (tid >> 4) * 8;
    const int tl0 = (tid & 15) * 8;
    ull acc[4][8];
#pragma unroll
    for (int i = 0; i < 4; i++)
#pragma unroll
        for (int j = 0; j < 8; j++) acc[i][j] = 0ull;
#pragma unroll 4
    for (int k = 0; k < CC; k++) {
        float4 w0 = *reinterpret_cast<const float4*>(&Wts[k * DD + o0]);
        float4 w1 = *reinterpret_cast<const float4*>(&Wts[k * DD + o0 + 4]);
        float4 u0 = *reinterpret_cast<const float4*>(&Us[k * 128 + tl0]);
        float4 u1 = *reinterpret_cast<const float4*>(&Us[k * 128 + tl0 + 4]);
        ull wp0 = pk2(w0.x, w0.y), wp1 = pk2(w0.z, w0.w);
        ull wp2 = pk2(w1.x, w1.y), wp3 = pk2(w1.z, w1.w);
        float ua[8] = {u0.x, u0.y, u0.z, u0.w, u1.x, u1.y, u1.z, u1.w};
#pragma unroll
        for (int j = 0; j < 8; j++) {
            ull ud = pk2(ua[j], ua[j]);
            ffma2(acc[0][j], wp0, ud);
            ffma2(acc[1][j], wp1, ud);
            ffma2(acc[2][j], wp2, ud);
            ffma2(acc[3][j], wp3, ud);
        }
    }
    const float* mb = mask + (size_t)b * TT + t0 + tl0;
    float4 mq0 = *reinterpret_cast<const float4*>(mb);
    float4 mq1 = *reinterpret_cast<const float4*>(mb + 4);
    float mv[8] = {mq0.x, mq0.y, mq0.z, mq0.w, mq1.x, mq1.y, mq1.z, mq1.w};
    float* yb = y + (size_t)b * DD * TT + t0 + tl0;
#pragma unroll
    for (int op = 0; op < 4; op++) {
        int o = o0 + 2 * op;
        float bo0 = bo[o], bo1 = bo[o + 1];
        float r0[8], r1[8];
#pragma unroll
        for (int j = 0; j < 8; j++) {
            float2 v = upk(acc[op][j]);
            r0[j] = (v.x + bo0) * mv[j];
            r1[j] = (v.y + bo1) * mv[j];
        }
        float* row0 = yb + (size_t)o * TT;
        float* row1 = yb + (size_t)(o + 1) * TT;
        *reinterpret_cast<float4*>(row0)     = make_float4(r0[0], r0[1], r0[2], r0[3]);
        *reinterpret_cast<float4*>(row0 + 4) = make_float4(r0[4], r0[5], r0[6], r0[7]);
        *reinterpret_cast<float4*>(row1)     = make_float4(r1[0], r1[1], r1[2], r1[3]);
        *reinterpret_cast<float4*>(row1 + 4) = make_float4(r1[4], r1[5], r1[6], r1[7]);
    }
}

static const int SMEM_K2C = (DD * KPAD + CC * KPAD * 2 + 8 * KPAD * 2 + 8 * CC +
                             DD + 3 * CC + 16) * (int)sizeof(float);
static const int SMEM_K3A = (DD * 128 + DD * CC) * (int)sizeof(float);   // 96 KB
static const int SMEM_K3B = (CC * 128 + CC * DD) * (int)sizeof(float);   // 64 KB

extern "C" void kernel_launch(void* const* d_in, const int* in_sizes, int n_in,
                              void* d_out, int out_size) {
    const float* x1   = (const float*)d_in[0];
    const float* mask = (const float*)d_in[2];
    const float* wq   = (const float*)d_in[3];
    const float* bq   = (const float*)d_in[4];
    const float* wk   = (const float*)d_in[5];
    const float* bk   = (const float*)d_in[6];
    const float* wv   = (const float*)d_in[7];
    const float* bv   = (const float*)d_in[8];
    const float* we   = (const float*)d_in[9];
    const float* be   = (const float*)d_in[10];
    const float* wf   = (const float*)d_in[11];
    const float* bf   = (const float*)d_in[12];
    const float* wo   = (const float*)d_in[13];
    const float* bo   = (const float*)d_in[14];
    float* y = (float*)d_out;

    cudaFuncSetAttribute(k2c_attn, cudaFuncAttributeMaxDynamicSharedMemorySize, SMEM_K2C);
    cudaFuncSetAttribute(k3a_u,    cudaFuncAttributeMaxDynamicSharedMemorySize, SMEM_K3A);
    cudaFuncSetAttribute(k3b_y,    cudaFuncAttributeMaxDynamicSharedMemorySize, SMEM_K3B);

    void *pG = nullptr, *ps = nullptr;
    cudaGetSymbolAddress(&pG, g_G);
    cudaGetSymbolAddress(&ps, g_s);
    cudaMemsetAsync(pG, 0, BB * DD * DD * sizeof(float));   // launch 0
    cudaMemsetAsync(ps, 0, BB * DD * sizeof(float));        // launch 1

    k2a_weights<<<16, 256>>>(we, wk, bk, be, wf, wv, bv, bf, wo);  // launch 2
    k_nop<<<1, 32>>>();                                            // launch 3
    k_nop<<<1, 32>>>();                                            // launch 4
    k1_mma<<<dim3(16, 8), 512>>>(x1);                              // launch 5 (ncu -s 5)
    k2c_attn<<<dim3(8, 8), 256, SMEM_K2C>>>(wq, bq);
    k3a_u<<<dim3(256, 8), 256, SMEM_K3A>>>(x1);
    k3b_y<<<dim3(256, 8), 256, SMEM_K3B>>>(mask, bo, y);
}

// round 10
// speedup vs baseline: 3.2120x; 1.3842x over previous
#include <cuda_runtime.h>
#include <cuda_bf16.h>
#include <cstdint>

#define BB 8
#define DD 128
#define TT 32768
#define CC 64

// ---------------- warp-level bf16 MMA + ldmatrix ----------------
__device__ __forceinline__ void mma_bf16(float* d, const uint32_t* a, const uint32_t* b) {
    asm volatile(
        "mma.sync.aligned.m16n8k16.row.col.f32.bf16.bf16.f32 "
        "{%0,%1,%2,%3}, {%4,%5,%6,%7}, {%8,%9}, {%0,%1,%2,%3};"
        : "+f"(d[0]), "+f"(d[1]), "+f"(d[2]), "+f"(d[3])
        : "r"(a[0]), "r"(a[1]), "r"(a[2]), "r"(a[3]), "r"(b[0]), "r"(b[1]));
}
__device__ __forceinline__ void ldm_x4(uint32_t* r, uint32_t addr) {
    asm volatile("ldmatrix.sync.aligned.m8n8.x4.shared.b16 {%0,%1,%2,%3}, [%4];"
        : "=r"(r[0]), "=r"(r[1]), "=r"(r[2]), "=r"(r[3]) : "r"(addr));
}
__device__ __forceinline__ void ldm_x4t(uint32_t* r, uint32_t addr) {
    asm volatile("ldmatrix.sync.aligned.m8n8.x4.trans.shared.b16 {%0,%1,%2,%3}, [%4];"
        : "=r"(r[0]), "=r"(r[1]), "=r"(r[2]), "=r"(r[3]) : "r"(addr));
}
__device__ __forceinline__ uint32_t pkbf(float v0, float v1) {
    uint32_t r; asm("cvt.rn.bf16x2.f32 %0, %1, %2;" : "=r"(r) : "f"(v1), "f"(v0)); return r;
}
__device__ __forceinline__ uint32_t smem_u32(const void* p) {
    uint32_t a;
    asm("{ .reg .u64 t; cvta.to.shared.u64 t, %1; cvt.u32.u64 %0, t; }" : "=r"(a) : "l"(p));
    return a;
}
// split float4 -> bf16 hi pair + lo (residual) pair
__device__ __forceinline__ void cvt4(const float4 v, uint2& h, uint2& lo) {
    h.x = pkbf(v.x, v.y); h.y = pkbf(v.z, v.w);
    float r0 = v.x - __uint_as_float(h.x << 16);
    float r1 = v.y - __uint_as_float(h.x & 0xFFFF0000u);
    float r2 = v.z - __uint_as_float(h.y << 16);
    float r3 = v.w - __uint_as_float(h.y & 0xFFFF0000u);
    lo.x = pkbf(r0, r1); lo.y = pkbf(r2, r3);
}

// ---------------- scratch (static device globals) ----------------
__device__ float g_G[BB * DD * DD];     // per-batch Gram (full, symmetric)
__device__ float g_s[BB * DD];          // per-batch row sums
__device__ float g_Bm[CC * DD];         // we @ wk
__device__ float g_F[CC * DD];          // wf @ wv
__device__ float g_k0[CC];
__device__ float g_v0[CC];
__device__ float g_M[BB * CC * DD];     // M row-major [b][c][d]
__device__ float g_cv[BB * CC];

// ================= K1 (mma.sync bf16 split, 512 thr): Gram + row sums =================
#define TSEG 2048
#define TCH  64
#define NCH  (TSEG / TCH)
#define KSTR 72

__global__ __launch_bounds__(512, 1) void k1_mma(const float* __restrict__ x) {
    __shared__ __align__(16) unsigned short sh_hi[DD][KSTR];
    __shared__ __align__(16) unsigned short sh_lo[DD][KSTR];
    const int tid = threadIdx.x;
    const int w   = tid >> 5, l = tid & 31;
    const int g   = l >> 2, tg = l & 3;
    const int q   = l >> 3, i5 = l & 7;
    const int b   = blockIdx.y;
    const int tseg = blockIdx.x * TSEG;
    const int d   = tid >> 2;
    const int kh  = (tid & 3) * 16;
    const float* xp = x + ((size_t)b * DD + d) * TT + tseg + kh;

    float accP[8][4], accC[8][4];
#pragma unroll
    for (int j = 0; j < 8; j++)
#pragma unroll
        for (int qq = 0; qq < 4; qq++) { accP[j][qq] = 0.f; accC[j][qq] = 0.f; }
    float srow = 0.f;

    const int m0 = (w & 7) * 16;
    const int n0 = (w >> 3) * 64;
    const uint32_t sbh = smem_u32(sh_hi);
    const uint32_t sbl = smem_u32(sh_lo);
    const uint32_t pa  = sbh + (uint32_t)(((m0 + (q & 1) * 8 + i5) * KSTR + (q >> 1) * 8) * 2);
    const uint32_t rb  = (uint32_t)(((n0 + (q >> 1) * 8 + i5) * KSTR + (q & 1) * 8) * 2);
    const uint32_t pbh = sbh + rb;
    const uint32_t pbl = sbl + rb;

    float4 r[4], r2[4];
#pragma unroll
    for (int ii = 0; ii < 4; ii++) r[ii] = *reinterpret_cast<const float4*>(xp + 4 * ii);

    for (int c = 0; c < NCH; c++) {
        if (c + 1 < NCH) {
            const float* xn = xp + (c + 1) * TCH;
#pragma unroll
            for (int ii = 0; ii < 4; ii++) r2[ii] = *reinterpret_cast<const float4*>(xn + 4 * ii);
        }
#pragma unroll
        for (int it = 0; it < 4; it++) {
            float4 v = r[it];
            srow += (v.x + v.y) + (v.z + v.w);
            uint2 hv, lv;
            cvt4(v, hv, lv);
            *reinterpret_cast<uint2*>(&sh_hi[d][kh + it * 4]) = hv;
            *reinterpret_cast<uint2*>(&sh_lo[d][kh + it * 4]) = lv;
        }
        __syncthreads();
#pragma unroll
        for (int ks = 0; ks < 4; ks++) {
            uint32_t ah[4];
            ldm_x4(ah, pa + ks * 32);
#pragma unroll
            for (int jp = 0; jp < 4; jp++) {
                const uint32_t boff = (uint32_t)(jp * 16 * KSTR * 2 + ks * 32);
                uint32_t bh[4], bl[4];
                ldm_x4(bh, pbh + boff);
                ldm_x4(bl, pbl + boff);
                mma_bf16(accP[2 * jp],     ah, bh);
                mma_bf16(accP[2 * jp + 1], ah, bh + 2);
                mma_bf16(accC[2 * jp],     ah, bl);
                mma_bf16(accC[2 * jp + 1], ah, bl + 2);
            }
        }
        __syncthreads();
#pragma unroll
        for (int ii = 0; ii < 4; ii++) r[ii] = r2[ii];
    }

    float* Gb = g_G + b * DD * DD;
    const int row = m0 + g;
#pragma unroll
    for (int j = 0; j < 8; j++) {
        const int col = n0 + j * 8 + tg * 2;
        atomicAdd(&Gb[row * DD + col],           accP[j][0] + accC[j][0]);
        atomicAdd(&Gb[row * DD + col + 1],       accP[j][1] + accC[j][1]);
        atomicAdd(&Gb[(row + 8) * DD + col],     accP[j][2] + accC[j][2]);
        atomicAdd(&Gb[(row + 8) * DD + col + 1], accP[j][3] + accC[j][3]);
        atomicAdd(&Gb[col * DD + row],           accC[j][0]);
        atomicAdd(&Gb[(col + 1) * DD + row],     accC[j][1]);
        atomicAdd(&Gb[col * DD + row + 8],       accC[j][2]);
        atomicAdd(&Gb[(col + 1) * DD + row + 8], accC[j][3]);
    }
    atomicAdd(&g_s[b * DD + d], srow);
}

// ============ K2a: batch-independent weight products (grid 16) ============
__global__ void k2a_weights(const float* __restrict__ we, const float* __restrict__ wk,
                            const float* __restrict__ bk, const float* __restrict__ be,
                            const float* __restrict__ wf, const float* __restrict__ wv,
                            const float* __restrict__ bv, const float* __restrict__ bf) {
    const int j = blockIdx.x, tid = threadIdx.x;
    if (j < 8) {
#pragma unroll
        for (int it = 0; it < 4; it++) {
            int idx = tid + 256 * it;
            int o = j * 8 + (idx >> 7);
            int d = idx & 127;
            float acc = 0.f;
            for (int c = 0; c < CC; c++) acc = fmaf(we[o * CC + c], wk[c * DD + d], acc);
            g_Bm[o * DD + d] = acc;
        }
        if (j == 0 && tid < CC) {
            float acc = be[tid];
            for (int c = 0; c < CC; c++) acc = fmaf(we[tid * CC + c], bk[c], acc);
            g_k0[tid] = acc;
        }
    } else {
        int jj = j - 8;
#pragma unroll
        for (int it = 0; it < 4; it++) {
            int idx = tid + 256 * it;
            int o = jj * 8 + (idx >> 7);
            int d = idx & 127;
            float acc = 0.f;
            for (int c = 0; c < CC; c++) acc = fmaf(wf[o * CC + c], wv[c * DD + d], acc);
            g_F[o * DD + d] = acc;
        }
        if (j == 8 && tid < CC) {
            float acc = bf[tid];
            for (int c = 0; c < CC; c++) acc = fmaf(wf[tid * CC + c], bv[c], acc);
            g_v0[tid] = acc;
        }
    }
}

// ============ K2c: AG + S + softmax + M + cv, fused. grid (8 c-groups, 8 b) ============
#define KPAD 132
__global__ void k2c_attn(const float* __restrict__ wq, const float* __restrict__ bq) {
    extern __shared__ float sm2[];
    float* Gs  = sm2;
    float* Bms = Gs  + DD * KPAD;
    float* Fs  = Bms + CC * KPAD;
    float* wqs = Fs  + CC * KPAD;
    float* AGs = wqs + 8 * KPAD;
    float* Ps  = AGs + 8 * KPAD;
    float* ss  = Ps  + 8 * CC;
    float* bs  = ss  + DD;
    float* k0s = bs  + CC;
    float* v0s = k0s + CC;
    float* qs  = v0s + CC;
    float* bqs = qs  + 8;
    const int cg = blockIdx.x, b = blockIdx.y, tid = threadIdx.x;

    const float* Gb = g_G + b * DD * DD;
    for (int i = tid; i < DD * 32; i += 256) {
        int r = i >> 5, c4 = (i & 31) << 2;
        *reinterpret_cast<float4*>(&Gs[r * KPAD + c4]) =
            *reinterpret_cast<const float4*>(&Gb[r * DD + c4]);
    }
    for (int i = tid; i < CC * 32; i += 256) {
        int r = i >> 5, c4 = (i & 31) << 2;
        *reinterpret_cast<float4*>(&Bms[r * KPAD + c4]) =
            *reinterpret_cast<const float4*>(&g_Bm[r * DD + c4]);
        *reinterpret_cast<float4*>(&Fs[r * KPAD + c4]) =
            *reinterpret_cast<const float4*>(&g_F[r * DD + c4]);
    }
    for (int i = tid; i < 8 * 32; i += 256) {
        int r = i >> 5, c4 = (i & 31) << 2;
        *reinterpret_cast<float4*>(&wqs[r * KPAD + c4]) =
            *reinterpret_cast<const float4*>(&wq[(cg * 8 + r) * DD + c4]);
    }
    if (tid < DD) ss[tid] = g_s[b * DD + tid];
    if (tid < CC) { k0s[tid] = g_k0[tid]; v0s[tid] = g_v0[tid]; }
    if (tid < 8)  bqs[tid] = bq[cg * 8 + tid];
    __syncthreads();

    if (tid < CC) {
        float a = 0.f;
        const float* r = &Bms[tid * KPAD];
        for (int d = 0; d < DD; d++) a = fmaf(r[d], ss[d], a);
        bs[tid] = a;
    } else if (tid < CC + 8) {
        int ci = tid - CC;
        float a = 0.f;
        const float* r = &wqs[ci * KPAD];
        for (int d = 0; d < DD; d++) a = fmaf(r[d], ss[d], a);
        qs[ci] = a;
    }
    {
        const int d = tid >> 1, cb = (tid & 1) * 4;
        float a0 = 0.f, a1 = 0.f, a2 = 0.f, a3 = 0.f;
        for (int d1 = 0; d1 < DD; d1++) {
            float g = Gs[d1 * KPAD + d];
            a0 = fmaf(g, wqs[(cb + 0) * KPAD + d1], a0);
            a1 = fmaf(g, wqs[(cb + 1) * KPAD + d1], a1);
            a2 = fmaf(g, wqs[(cb + 2) * KPAD + d1], a2);
            a3 = fmaf(g, wqs[(cb + 3) * KPAD + d1], a3);
        }
        AGs[(cb + 0) * KPAD + d] = a0;
        AGs[(cb + 1) * KPAD + d] = a1;
        AGs[(cb + 2) * KPAD + d] = a2;
        AGs[(cb + 3) * KPAD + d] = a3;
    }
    __syncthreads();

    {
        const int ci = tid >> 5, k = tid & 31;
#pragma unroll
        for (int rep = 0; rep < 2; rep++) {
            int kk = k + rep * 32;
            float acc = 0.f;
            for (int d4 = 0; d4 < 32; d4++) {
                float4 ag = *reinterpret_cast<const float4*>(&AGs[ci * KPAD + d4 * 4]);
                float4 bm = *reinterpret_cast<const float4*>(&Bms[kk * KPAD + d4 * 4]);
                acc = fmaf(ag.x, bm.x, acc); acc = fmaf(ag.y, bm.y, acc);
                acc = fmaf(ag.z, bm.z, acc); acc = fmaf(ag.w, bm.w, acc);
            }
            acc += qs[ci] * k0s[kk] + bqs[ci] * bs[kk] + (float)TT * bqs[ci] * k0s[kk];
            Ps[ci * CC + kk] = acc * 0.125f;
        }
    }
    __syncthreads();

    {
        const int w = tid >> 5, lane = tid & 31;
        float v0 = Ps[w * CC + lane], v1 = Ps[w * CC + lane + 32];
        float m = fmaxf(v0, v1);
#pragma unroll
        for (int off = 16; off; off >>= 1) m = fmaxf(m, __shfl_xor_sync(~0u, m, off));
        float e0 = expf(v0 - m), e1 = expf(v1 - m);
        float sum = e0 + e1;
#pragma unroll
        for (int off = 16; off; off >>= 1) sum += __shfl_xor_sync(~0u, sum, off);
        float inv = 1.f / sum;
        Ps[w * CC + lane]      = e0 * inv;
        Ps[w * CC + lane + 32] = e1 * inv;
    }
    __syncthreads();

    {
        const int d = tid >> 1, cb = (tid & 1) * 4;
        float a0 = 0.f, a1 = 0.f, a2 = 0.f, a3 = 0.f;
        for (int k = 0; k < CC; k++) {
            float f = Fs[k * KPAD + d];
            a0 = fmaf(Ps[(cb + 0) * CC + k], f, a0);
            a1 = fmaf(Ps[(cb + 1) * CC + k], f, a1);
            a2 = fmaf(Ps[(cb + 2) * CC + k], f, a2);
            a3 = fmaf(Ps[(cb + 3) * CC + k], f, a3);
        }
        float* Mb = g_M + b * CC * DD + (cg * 8 + cb) * DD + d;
        Mb[0]      = a0;
        Mb[DD]     = a1;
        Mb[2 * DD] = a2;
        Mb[3 * DD] = a3;
    }
    if (tid < 8) {
        float acc = 0.f;
        for (int k = 0; k < CC; k++) acc = fmaf(Ps[tid * CC + k], v0s[k], acc);
        g_cv[b * CC + cg * 8 + tid] = acc;
    }
}

// ============ K3f (fused, tensor): y = mask*(wo@relu(M X + cv) + bo) ============
// grid (256, 8), 512 thr. t-tile 128. All GEMMs split-bf16, 3 products.
#define TP 136   // X / U col stride (elems)
#define DP 136   // M col stride
#define CP 72    // W col stride
#define OX_H 0u
#define OX_L 34816u
#define OM_H 69632u
#define OM_L 87040u
#define OW_H 104448u
#define OW_L 122880u
#define OU_H 141312u
#define OU_L 158720u
#define SMEM_K3F 176128

__global__ __launch_bounds__(512, 1) void k3f(const float* __restrict__ x,
                                              const float* __restrict__ wo,
                                              const float* __restrict__ bo,
                                              const float* __restrict__ mask,
                                              float* __restrict__ y) {
    extern __shared__ __align__(16) char smem[];
    const uint32_t sb = smem_u32(smem);
    const int tid = threadIdx.x;
    const int w = tid >> 5, l = tid & 31;
    const int g = l >> 2, tg = l & 3;
    const int q = l >> 3, i5 = l & 7;
    const int b  = blockIdx.y;
    const int t0 = blockIdx.x * 128;

    // ---- convert M, wo, X tiles to bf16 hi/lo ----
    {
        const float* Mb = g_M + b * CC * DD;
#pragma unroll
        for (int i = 0; i < 4; i++) {
            int f4 = tid + 512 * i;
            int c = f4 >> 5, d4 = (f4 & 31) << 2;
            float4 v = *reinterpret_cast<const float4*>(Mb + c * DD + d4);
            uint2 hv, lv; cvt4(v, hv, lv);
            *reinterpret_cast<uint2*>(smem + OM_H + (c * DP + d4) * 2) = hv;
            *reinterpret_cast<uint2*>(smem + OM_L + (c * DP + d4) * 2) = lv;
        }
#pragma unroll
        for (int i = 0; i < 4; i++) {
            int f4 = tid + 512 * i;
            int o = f4 >> 4, c4 = (f4 & 15) << 2;
            float4 v = *reinterpret_cast<const float4*>(wo + o * CC + c4);
            uint2 hv, lv; cvt4(v, hv, lv);
            *reinterpret_cast<uint2*>(smem + OW_H + (o * CP + c4) * 2) = hv;
            *reinterpret_cast<uint2*>(smem + OW_L + (o * CP + c4) * 2) = lv;
        }
        const float* xb = x + (size_t)b * DD * TT + t0;
#pragma unroll
        for (int i = 0; i < 8; i++) {   // 4096 float4 = full 128x128 X tile
            int f4 = tid + 512 * i;
            int d = f4 >> 5, t4 = (f4 & 31) << 2;
            float4 v = *reinterpret_cast<const float4*>(xb + (size_t)d * TT + t4);
            uint2 hv, lv; cvt4(v, hv, lv);
            *reinterpret_cast<uint2*>(smem + OX_H + (d * TP + t4) * 2) = hv;
            *reinterpret_cast<uint2*>(smem + OX_L + (d * TP + t4) * 2) = lv;
        }
    }
    __syncthreads();

    // ---- stage 1: U = relu(M X + cv). m=c(64): 4 stripes; n=t(128): 4 groups of 32 ----
    {
        const int mw = (w & 3) * 16;
        const int nw = (w >> 2) * 32;
        float accU[4][4];
#pragma unroll
        for (int j = 0; j < 4; j++)
#pragma unroll
            for (int qq = 0; qq < 4; qq++) accU[j][qq] = 0.f;

        const uint32_t aoff = (uint32_t)(((mw + (q & 1) * 8 + i5) * DP + (q >> 1) * 8) * 2);
        const uint32_t pa_h = sb + OM_H + aoff, pa_l = sb + OM_L + aoff;
        const uint32_t boff = (uint32_t)((((q & 1) * 8 + i5) * TP + nw + (q >> 1) * 8) * 2);
        const uint32_t pb_h = sb + OX_H + boff, pb_l = sb + OX_L + boff;

#pragma unroll
        for (int ks = 0; ks < 8; ks++) {
            uint32_t ah[4], al[4];
            ldm_x4(ah, pa_h + ks * 32);
            ldm_x4(al, pa_l + ks * 32);
#pragma unroll
            for (int jp = 0; jp < 2; jp++) {
                uint32_t off = (uint32_t)(ks * 16 * TP * 2 + jp * 32);
                uint32_t bh[4], bl[4];
                ldm_x4t(bh, pb_h + off);
                ldm_x4t(bl, pb_l + off);
                mma_bf16(accU[2 * jp],     ah, bh);
                mma_bf16(accU[2 * jp],     ah, bl);
                mma_bf16(accU[2 * jp],     al, bh);
                mma_bf16(accU[2 * jp + 1], ah, bh + 2);
                mma_bf16(accU[2 * jp + 1], ah, bl + 2);
                mma_bf16(accU[2 * jp + 1], al, bh + 2);
            }
        }

        const float cv0 = g_cv[b * CC + mw + g];
        const float cv1 = g_cv[b * CC + mw + g + 8];
#pragma unroll
        for (int j = 0; j < 4; j++) {
            int t = nw + 8 * j + 2 * tg;
            float u00 = fmaxf(accU[j][0] + cv0, 0.f);
            float u01 = fmaxf(accU[j][1] + cv0, 0.f);
            float u10 = fmaxf(accU[j][2] + cv1, 0.f);
            float u11 = fmaxf(accU[j][3] + cv1, 0.f);
            uint32_t h0 = pkbf(u00, u01);
            uint32_t l0 = pkbf(u00 - __uint_as_float(h0 << 16),
                               u01 - __uint_as_float(h0 & 0xFFFF0000u));
            uint32_t h1 = pkbf(u10, u11);
            uint32_t l1 = pkbf(u10 - __uint_as_float(h1 << 16),
                               u11 - __uint_as_float(h1 & 0xFFFF0000u));
            *reinterpret_cast<uint32_t*>(smem + OU_H + ((mw + g) * TP + t) * 2)     = h0;
            *reinterpret_cast<uint32_t*>(smem + OU_L + ((mw + g) * TP + t) * 2)     = l0;
            *reinterpret_cast<uint32_t*>(smem + OU_H + ((mw + g + 8) * TP + t) * 2) = h1;
            *reinterpret_cast<uint32_t*>(smem + OU_L + ((mw + g + 8) * TP + t) * 2) = l1;
        }
    }
    __syncthreads();

    // ---- stage 2: y = mask*(wo U + bo). m=o(128): 8 stripes; n=t(128): 2 halves ----
    {
        const int mw2 = (w & 7) * 16;
        const int nw2 = (w >> 3) * 64;
        float acc2[8][4];
#pragma unroll
        for (int j = 0; j < 8; j++)
#pragma unroll
            for (int qq = 0; qq < 4; qq++) acc2[j][qq] = 0.f;

        const uint32_t aoff2 = (uint32_t)(((mw2 + (q & 1) * 8 + i5) * CP + (q >> 1) * 8) * 2);
        const uint32_t pa2h = sb + OW_H + aoff2, pa2l = sb + OW_L + aoff2;
        const uint32_t boff2 = (uint32_t)((((q & 1) * 8 + i5) * TP + nw2 + (q >> 1) * 8) * 2);
        const uint32_t pb2h = sb + OU_H + boff2, pb2l = sb + OU_L + boff2;

#pragma unroll
        for (int ks = 0; ks < 4; ks++) {
            uint32_t ah[4], al[4];
            ldm_x4(ah, pa2h + ks * 32);
            ldm_x4(al, pa2l + ks * 32);
#pragma unroll
            for (int jp = 0; jp < 4; jp++) {
                uint32_t off = (uint32_t)(ks * 16 * TP * 2 + jp * 32);
                uint32_t bh[4], bl[4];
                ldm_x4t(bh, pb2h + off);
                ldm_x4t(bl, pb2l + off);
                mma_bf16(acc2[2 * jp],     ah, bh);
                mma_bf16(acc2[2 * jp],     ah, bl);
                mma_bf16(acc2[2 * jp],     al, bh);
                mma_bf16(acc2[2 * jp + 1], ah, bh + 2);
                mma_bf16(acc2[2 * jp + 1], ah, bl + 2);
                mma_bf16(acc2[2 * jp + 1], al, bh + 2);
            }
        }

        const int o = mw2 + g;
        const float bo0 = bo[o], bo1 = bo[o + 8];
        const float* mrow = mask + (size_t)b * TT + t0;
        float* yb = y + (size_t)b * DD * TT + t0;
#pragma unroll
        for (int j = 0; j < 8; j++) {
            int t = nw2 + 8 * j + 2 * tg;
            float2 mk = *reinterpret_cast<const float2*>(mrow + t);
            float2 y0, y1;
            y0.x = (acc2[j][0] + bo0) * mk.x;
            y0.y = (acc2[j][1] + bo0) * mk.y;
            y1.x = (acc2[j][2] + bo1) * mk.x;
            y1.y = (acc2[j][3] + bo1) * mk.y;
            *reinterpret_cast<float2*>(yb + (size_t)o * TT + t)       = y0;
            *reinterpret_cast<float2*>(yb + (size_t)(o + 8) * TT + t) = y1;
        }
    }
}

static const int SMEM_K2C = (DD * KPAD + CC * KPAD * 2 + 8 * KPAD * 2 + 8 * CC +
                             DD + 3 * CC + 16) * (int)sizeof(float);

extern "C" void kernel_launch(void* const* d_in, const int* in_sizes, int n_in,
                              void* d_out, int out_size) {
    const float* x1   = (const float*)d_in[0];
    const float* mask = (const float*)d_in[2];
    const float* wq   = (const float*)d_in[3];
    const float* bq   = (const float*)d_in[4];
    const float* wk   = (const float*)d_in[5];
    const float* bk   = (const float*)d_in[6];
    const float* wv   = (const float*)d_in[7];
    const float* bv   = (const float*)d_in[8];
    const float* we   = (const float*)d_in[9];
    const float* be   = (const float*)d_in[10];
    const float* wf   = (const float*)d_in[11];
    const float* bf   = (const float*)d_in[12];
    const float* wo   = (const float*)d_in[13];
    const float* bo   = (const float*)d_in[14];
    float* y = (float*)d_out;

    cudaFuncSetAttribute(k2c_attn, cudaFuncAttributeMaxDynamicSharedMemorySize, SMEM_K2C);
    cudaFuncSetAttribute(k3f,      cudaFuncAttributeMaxDynamicSharedMemorySize, SMEM_K3F);

    void *pG = nullptr, *ps = nullptr;
    cudaGetSymbolAddress(&pG, g_G);
    cudaGetSymbolAddress(&ps, g_s);
    cudaMemsetAsync(pG, 0, BB * DD * DD * sizeof(float));   // launch 0
    cudaMemsetAsync(ps, 0, BB * DD * sizeof(float));        // launch 1

    k2a_weights<<<16, 256>>>(we, wk, bk, be, wf, wv, bv, bf);   // launch 2
    k1_mma<<<dim3(16, 8), 512>>>(x1);                            // launch 3
    k2c_attn<<<dim3(8, 8), 256, SMEM_K2C>>>(wq, bq);             // launch 4
    k3f<<<dim3(256, 8), 512, SMEM_K3F>>>(x1, wo, bo, mask, y);   // launch 5 (ncu -s 5)
}

// round 11
// speedup vs baseline: 3.2726x; 1.0189x over previous
#include <cuda_runtime.h>
#include <cuda_bf16.h>
#include <cstdint>

#define BB 8
#define DD 128
#define TT 32768
#define CC 64

// ---------------- warp-level bf16 MMA + ldmatrix ----------------
__device__ __forceinline__ void mma_bf16(float* d, const uint32_t* a, const uint32_t* b) {
    asm volatile(
        "mma.sync.aligned.m16n8k16.row.col.f32.bf16.bf16.f32 "
        "{%0,%1,%2,%3}, {%4,%5,%6,%7}, {%8,%9}, {%0,%1,%2,%3};"
        : "+f"(d[0]), "+f"(d[1]), "+f"(d[2]), "+f"(d[3])
        : "r"(a[0]), "r"(a[1]), "r"(a[2]), "r"(a[3]), "r"(b[0]), "r"(b[1]));
}
__device__ __forceinline__ void ldm_x4(uint32_t* r, uint32_t addr) {
    asm volatile("ldmatrix.sync.aligned.m8n8.x4.shared.b16 {%0,%1,%2,%3}, [%4];"
        : "=r"(r[0]), "=r"(r[1]), "=r"(r[2]), "=r"(r[3]) : "r"(addr));
}
__device__ __forceinline__ void ldm_x4t(uint32_t* r, uint32_t addr) {
    asm volatile("ldmatrix.sync.aligned.m8n8.x4.trans.shared.b16 {%0,%1,%2,%3}, [%4];"
        : "=r"(r[0]), "=r"(r[1]), "=r"(r[2]), "=r"(r[3]) : "r"(addr));
}
__device__ __forceinline__ uint32_t pkbf(float v0, float v1) {
    uint32_t r; asm("cvt.rn.bf16x2.f32 %0, %1, %2;" : "=r"(r) : "f"(v1), "f"(v0)); return r;
}
__device__ __forceinline__ uint32_t smem_u32(const void* p) {
    uint32_t a;
    asm("{ .reg .u64 t; cvta.to.shared.u64 t, %1; cvt.u32.u64 %0, t; }" : "=r"(a) : "l"(p));
    return a;
}
// split float4 -> bf16 hi pair + lo (residual) pair
__device__ __forceinline__ void cvt4(const float4 v, uint2& h, uint2& lo) {
    h.x = pkbf(v.x, v.y); h.y = pkbf(v.z, v.w);
    float r0 = v.x - __uint_as_float(h.x << 16);
    float r1 = v.y - __uint_as_float(h.x & 0xFFFF0000u);
    float r2 = v.z - __uint_as_float(h.y << 16);
    float r3 = v.w - __uint_as_float(h.y & 0xFFFF0000u);
    lo.x = pkbf(r0, r1); lo.y = pkbf(r2, r3);
}

// ---------------- scratch (static device globals) ----------------
__device__ float g_G[BB * DD * DD];     // per-batch Gram (full, symmetric)
__device__ float g_s[BB * DD];          // per-batch row sums
__device__ float g_Bm[CC * DD];         // we @ wk
__device__ float g_F[CC * DD];          // wf @ wv
__device__ float g_k0[CC];
__device__ float g_v0[CC];
__device__ float g_M[BB * CC * DD];     // M row-major [b][c][d]
__device__ float g_cv[BB * CC];

// ================= K1 (mma.sync bf16 split, 512 thr): Gram + row sums =================
#define TSEG 2048
#define TCH  64
#define NCH  (TSEG / TCH)
#define KSTR 72

__global__ __launch_bounds__(512, 1) void k1_mma(const float* __restrict__ x) {
    __shared__ __align__(16) unsigned short sh_hi[DD][KSTR];
    __shared__ __align__(16) unsigned short sh_lo[DD][KSTR];
    const int tid = threadIdx.x;
    const int w   = tid >> 5, l = tid & 31;
    const int g   = l >> 2, tg = l & 3;
    const int q   = l >> 3, i5 = l & 7;
    const int b   = blockIdx.y;
    const int tseg = blockIdx.x * TSEG;
    const int d   = tid >> 2;
    const int kh  = (tid & 3) * 16;
    const float* xp = x + ((size_t)b * DD + d) * TT + tseg + kh;

    float accP[8][4], accC[8][4];
#pragma unroll
    for (int j = 0; j < 8; j++)
#pragma unroll
        for (int qq = 0; qq < 4; qq++) { accP[j][qq] = 0.f; accC[j][qq] = 0.f; }
    float srow = 0.f;

    const int m0 = (w & 7) * 16;
    const int n0 = (w >> 3) * 64;
    const uint32_t sbh = smem_u32(sh_hi);
    const uint32_t sbl = smem_u32(sh_lo);
    const uint32_t pa  = sbh + (uint32_t)(((m0 + (q & 1) * 8 + i5) * KSTR + (q >> 1) * 8) * 2);
    const uint32_t rb  = (uint32_t)(((n0 + (q >> 1) * 8 + i5) * KSTR + (q & 1) * 8) * 2);
    const uint32_t pbh = sbh + rb;
    const uint32_t pbl = sbl + rb;

    float4 r[4], r2[4];
#pragma unroll
    for (int ii = 0; ii < 4; ii++) r[ii] = *reinterpret_cast<const float4*>(xp + 4 * ii);

    for (int c = 0; c < NCH; c++) {
        if (c + 1 < NCH) {
            const float* xn = xp + (c + 1) * TCH;
#pragma unroll
            for (int ii = 0; ii < 4; ii++) r2[ii] = *reinterpret_cast<const float4*>(xn + 4 * ii);
        }
#pragma unroll
        for (int it = 0; it < 4; it++) {
            float4 v = r[it];
            srow += (v.x + v.y) + (v.z + v.w);
            uint2 hv, lv;
            cvt4(v, hv, lv);
            *reinterpret_cast<uint2*>(&sh_hi[d][kh + it * 4]) = hv;
            *reinterpret_cast<uint2*>(&sh_lo[d][kh + it * 4]) = lv;
        }
        __syncthreads();
#pragma unroll
        for (int ks = 0; ks < 4; ks++) {
            uint32_t ah[4];
            ldm_x4(ah, pa + ks * 32);
#pragma unroll
            for (int jp = 0; jp < 4; jp++) {
                const uint32_t boff = (uint32_t)(jp * 16 * KSTR * 2 + ks * 32);
                uint32_t bh[4], bl[4];
                ldm_x4(bh, pbh + boff);
                ldm_x4(bl, pbl + boff);
                mma_bf16(accP[2 * jp],     ah, bh);
                mma_bf16(accP[2 * jp + 1], ah, bh + 2);
                mma_bf16(accC[2 * jp],     ah, bl);
                mma_bf16(accC[2 * jp + 1], ah, bl + 2);
            }
        }
        __syncthreads();
#pragma unroll
        for (int ii = 0; ii < 4; ii++) r[ii] = r2[ii];
    }

    float* Gb = g_G + b * DD * DD;
    const int row = m0 + g;
#pragma unroll
    for (int j = 0; j < 8; j++) {
        const int col = n0 + j * 8 + tg * 2;
        atomicAdd(&Gb[row * DD + col],           accP[j][0] + accC[j][0]);
        atomicAdd(&Gb[row * DD + col + 1],       accP[j][1] + accC[j][1]);
        atomicAdd(&Gb[(row + 8) * DD + col],     accP[j][2] + accC[j][2]);
        atomicAdd(&Gb[(row + 8) * DD + col + 1], accP[j][3] + accC[j][3]);
        atomicAdd(&Gb[col * DD + row],           accC[j][0]);
        atomicAdd(&Gb[(col + 1) * DD + row],     accC[j][1]);
        atomicAdd(&Gb[col * DD + row + 8],       accC[j][2]);
        atomicAdd(&Gb[(col + 1) * DD + row + 8], accC[j][3]);
    }
    atomicAdd(&g_s[b * DD + d], srow);
}

// ============ K2a: batch-independent weight products (grid 16) ============
__global__ void k2a_weights(const float* __restrict__ we, const float* __restrict__ wk,
                            const float* __restrict__ bk, const float* __restrict__ be,
                            const float* __restrict__ wf, const float* __restrict__ wv,
                            const float* __restrict__ bv, const float* __restrict__ bf) {
    const int j = blockIdx.x, tid = threadIdx.x;
    if (j < 8) {
#pragma unroll
        for (int it = 0; it < 4; it++) {
            int idx = tid + 256 * it;
            int o = j * 8 + (idx >> 7);
            int d = idx & 127;
            float acc = 0.f;
            for (int c = 0; c < CC; c++) acc = fmaf(we[o * CC + c], wk[c * DD + d], acc);
            g_Bm[o * DD + d] = acc;
        }
        if (j == 0 && tid < CC) {
            float acc = be[tid];
            for (int c = 0; c < CC; c++) acc = fmaf(we[tid * CC + c], bk[c], acc);
            g_k0[tid] = acc;
        }
    } else {
        int jj = j - 8;
#pragma unroll
        for (int it = 0; it < 4; it++) {
            int idx = tid + 256 * it;
            int o = jj * 8 + (idx >> 7);
            int d = idx & 127;
            float acc = 0.f;
            for (int c = 0; c < CC; c++) acc = fmaf(wf[o * CC + c], wv[c * DD + d], acc);
            g_F[o * DD + d] = acc;
        }
        if (j == 8 && tid < CC) {
            float acc = bf[tid];
            for (int c = 0; c < CC; c++) acc = fmaf(wf[tid * CC + c], bv[c], acc);
            g_v0[tid] = acc;
        }
    }
}

// ============ K2c: AG + S + softmax + M + cv, fused. grid (8 c-groups, 8 b) ============
#define KPAD 132
__global__ void k2c_attn(const float* __restrict__ wq, const float* __restrict__ bq) {
    extern __shared__ float sm2[];
    float* Gs  = sm2;
    float* Bms = Gs  + DD * KPAD;
    float* Fs  = Bms + CC * KPAD;
    float* wqs = Fs  + CC * KPAD;
    float* AGs = wqs + 8 * KPAD;
    float* Ps  = AGs + 8 * KPAD;
    float* ss  = Ps  + 8 * CC;
    float* bs  = ss  + DD;
    float* k0s = bs  + CC;
    float* v0s = k0s + CC;
    float* qs  = v0s + CC;
    float* bqs = qs  + 8;
    const int cg = blockIdx.x, b = blockIdx.y, tid = threadIdx.x;

    const float* Gb = g_G + b * DD * DD;
    for (int i = tid; i < DD * 32; i += 256) {
        int r = i >> 5, c4 = (i & 31) << 2;
        *reinterpret_cast<float4*>(&Gs[r * KPAD + c4]) =
            *reinterpret_cast<const float4*>(&Gb[r * DD + c4]);
    }
    for (int i = tid; i < CC * 32; i += 256) {
        int r = i >> 5, c4 = (i & 31) << 2;
        *reinterpret_cast<float4*>(&Bms[r * KPAD + c4]) =
            *reinterpret_cast<const float4*>(&g_Bm[r * DD + c4]);
        *reinterpret_cast<float4*>(&Fs[r * KPAD + c4]) =
            *reinterpret_cast<const float4*>(&g_F[r * DD + c4]);
    }
    for (int i = tid; i < 8 * 32; i += 256) {
        int r = i >> 5, c4 = (i & 31) << 2;
        *reinterpret_cast<float4*>(&wqs[r * KPAD + c4]) =
            *reinterpret_cast<const float4*>(&wq[(cg * 8 + r) * DD + c4]);
    }
    if (tid < DD) ss[tid] = g_s[b * DD + tid];
    if (tid < CC) { k0s[tid] = g_k0[tid]; v0s[tid] = g_v0[tid]; }
    if (tid < 8)  bqs[tid] = bq[cg * 8 + tid];
    __syncthreads();

    if (tid < CC) {
        float a = 0.f;
        const float* r = &Bms[tid * KPAD];
        for (int d = 0; d < DD; d++) a = fmaf(r[d], ss[d], a);
        bs[tid] = a;
    } else if (tid < CC + 8) {
        int ci = tid - CC;
        float a = 0.f;
        const float* r = &wqs[ci * KPAD];
        for (int d = 0; d < DD; d++) a = fmaf(r[d], ss[d], a);
        qs[ci] = a;
    }
    {
        const int d = tid >> 1, cb = (tid & 1) * 4;
        float a0 = 0.f, a1 = 0.f, a2 = 0.f, a3 = 0.f;
        for (int d1 = 0; d1 < DD; d1++) {
            float g = Gs[d1 * KPAD + d];
            a0 = fmaf(g, wqs[(cb + 0) * KPAD + d1], a0);
            a1 = fmaf(g, wqs[(cb + 1) * KPAD + d1], a1);
            a2 = fmaf(g, wqs[(cb + 2) * KPAD + d1], a2);
            a3 = fmaf(g, wqs[(cb + 3) * KPAD + d1], a3);
        }
        AGs[(cb + 0) * KPAD + d] = a0;
        AGs[(cb + 1) * KPAD + d] = a1;
        AGs[(cb + 2) * KPAD + d] = a2;
        AGs[(cb + 3) * KPAD + d] = a3;
    }
    __syncthreads();

    {
        const int ci = tid >> 5, k = tid & 31;
#pragma unroll
        for (int rep = 0; rep < 2; rep++) {
            int kk = k + rep * 32;
            float acc = 0.f;
            for (int d4 = 0; d4 < 32; d4++) {
                float4 ag = *reinterpret_cast<const float4*>(&AGs[ci * KPAD + d4 * 4]);
                float4 bm = *reinterpret_cast<const float4*>(&Bms[kk * KPAD + d4 * 4]);
                acc = fmaf(ag.x, bm.x, acc); acc = fmaf(ag.y, bm.y, acc);
                acc = fmaf(ag.z, bm.z, acc); acc = fmaf(ag.w, bm.w, acc);
            }
            acc += qs[ci] * k0s[kk] + bqs[ci] * bs[kk] + (float)TT * bqs[ci] * k0s[kk];
            Ps[ci * CC + kk] = acc * 0.125f;
        }
    }
    __syncthreads();

    {
        const int w = tid >> 5, lane = tid & 31;
        float v0 = Ps[w * CC + lane], v1 = Ps[w * CC + lane + 32];
        float m = fmaxf(v0, v1);
#pragma unroll
        for (int off = 16; off; off >>= 1) m = fmaxf(m, __shfl_xor_sync(~0u, m, off));
        float e0 = expf(v0 - m), e1 = expf(v1 - m);
        float sum = e0 + e1;
#pragma unroll
        for (int off = 16; off; off >>= 1) sum += __shfl_xor_sync(~0u, sum, off);
        float inv = 1.f / sum;
        Ps[w * CC + lane]      = e0 * inv;
        Ps[w * CC + lane + 32] = e1 * inv;
    }
    __syncthreads();

    {
        const int d = tid >> 1, cb = (tid & 1) * 4;
        float a0 = 0.f, a1 = 0.f, a2 = 0.f, a3 = 0.f;
        for (int k = 0; k < CC; k++) {
            float f = Fs[k * KPAD + d];
            a0 = fmaf(Ps[(cb + 0) * CC + k], f, a0);
            a1 = fmaf(Ps[(cb + 1) * CC + k], f, a1);
            a2 = fmaf(Ps[(cb + 2) * CC + k], f, a2);
            a3 = fmaf(Ps[(cb + 3) * CC + k], f, a3);
        }
        float* Mb = g_M + b * CC * DD + (cg * 8 + cb) * DD + d;
        Mb[0]      = a0;
        Mb[DD]     = a1;
        Mb[2 * DD] = a2;
        Mb[3 * DD] = a3;
    }
    if (tid < 8) {
        float acc = 0.f;
        for (int k = 0; k < CC; k++) acc = fmaf(Ps[tid * CC + k], v0s[k], acc);
        g_cv[b * CC + cg * 8 + tid] = acc;
    }
}

// ============ K3f (fused, tensor, 3 CTA/SM): y = mask*(wo@relu(M X + cv) + bo) ============
// grid (512, 8), 256 thr. t-tile 64. Smem overlay: region A = X then U; region B = M then W.
#define TPX 72    // X / U / W col stride (elems)
#define DPM 136   // M col stride
#define OX_H 0u
#define OX_L 18432u
#define OU_H 0u
#define OU_L 9216u
#define OM_H 36864u
#define OM_L 54272u
#define OW_H 36864u
#define OW_L 55296u
#define SMEM_K3F 73728

__global__ __launch_bounds__(256, 3) void k3f(const float* __restrict__ x,
                                              const float* __restrict__ wo,
                                              const float* __restrict__ bo,
                                              const float* __restrict__ mask,
                                              float* __restrict__ y) {
    extern __shared__ __align__(16) char smem[];
    const uint32_t sb = smem_u32(smem);
    const int tid = threadIdx.x;
    const int w = tid >> 5, l = tid & 31;
    const int g = l >> 2, tg = l & 3;
    const int q = l >> 3, i5 = l & 7;
    const int b  = blockIdx.y;
    const int t0 = blockIdx.x * 64;

    // ---- phase 1: convert X (128x64) and M (64x128) to bf16 hi/lo ----
    {
        const float* xb = x + (size_t)b * DD * TT + t0;
#pragma unroll
        for (int i = 0; i < 8; i++) {
            int f4 = tid + 256 * i;
            int d = f4 >> 4, t4 = (f4 & 15) << 2;
            float4 v = *reinterpret_cast<const float4*>(xb + (size_t)d * TT + t4);
            uint2 hv, lv; cvt4(v, hv, lv);
            *reinterpret_cast<uint2*>(smem + OX_H + (d * TPX + t4) * 2) = hv;
            *reinterpret_cast<uint2*>(smem + OX_L + (d * TPX + t4) * 2) = lv;
        }
        const float* Mb = g_M + b * CC * DD;
#pragma unroll
        for (int i = 0; i < 8; i++) {
            int f4 = tid + 256 * i;
            int c = f4 >> 5, d4 = (f4 & 31) << 2;
            float4 v = *reinterpret_cast<const float4*>(Mb + c * DD + d4);
            uint2 hv, lv; cvt4(v, hv, lv);
            *reinterpret_cast<uint2*>(smem + OM_H + (c * DPM + d4) * 2) = hv;
            *reinterpret_cast<uint2*>(smem + OM_L + (c * DPM + d4) * 2) = lv;
        }
    }
    __syncthreads();

    // ---- stage 1: accU = M X. m=c(64): 4 stripes; n=t(64): 2 groups of 32 ----
    float accU[4][4];
    const int mw = (w & 3) * 16;
    const int nw = (w >> 2) * 32;
    {
#pragma unroll
        for (int j = 0; j < 4; j++)
#pragma unroll
            for (int qq = 0; qq < 4; qq++) accU[j][qq] = 0.f;

        const uint32_t aoff = (uint32_t)(((mw + (q & 1) * 8 + i5) * DPM + (q >> 1) * 8) * 2);
        const uint32_t pa_h = sb + OM_H + aoff, pa_l = sb + OM_L + aoff;
        const uint32_t boff = (uint32_t)((((q & 1) * 8 + i5) * TPX + nw + (q >> 1) * 8) * 2);
        const uint32_t pb_h = sb + OX_H + boff, pb_l = sb + OX_L + boff;

#pragma unroll
        for (int ks = 0; ks < 8; ks++) {
            uint32_t ah[4], al[4];
            ldm_x4(ah, pa_h + ks * 32);
            ldm_x4(al, pa_l + ks * 32);
#pragma unroll
            for (int jp = 0; jp < 2; jp++) {
                uint32_t off = (uint32_t)(ks * 16 * TPX * 2 + jp * 32);
                uint32_t bh[4], bl[4];
                ldm_x4t(bh, pb_h + off);
                ldm_x4t(bl, pb_l + off);
                mma_bf16(accU[2 * jp],     ah, bh);
                mma_bf16(accU[2 * jp],     ah, bl);
                mma_bf16(accU[2 * jp],     al, bh);
                mma_bf16(accU[2 * jp + 1], ah, bh + 2);
                mma_bf16(accU[2 * jp + 1], ah, bl + 2);
                mma_bf16(accU[2 * jp + 1], al, bh + 2);
            }
        }
    }
    __syncthreads();   // all X/M reads done; A and B regions free

    // ---- phase 3: write U (relu + split) into region A; convert W into region B ----
    {
        const float cv0 = g_cv[b * CC + mw + g];
        const float cv1 = g_cv[b * CC + mw + g + 8];
#pragma unroll
        for (int j = 0; j < 4; j++) {
            int t = nw + 8 * j + 2 * tg;
            float u00 = fmaxf(accU[j][0] + cv0, 0.f);
            float u01 = fmaxf(accU[j][1] + cv0, 0.f);
            float u10 = fmaxf(accU[j][2] + cv1, 0.f);
            float u11 = fmaxf(accU[j][3] + cv1, 0.f);
            uint32_t h0 = pkbf(u00, u01);
            uint32_t l0 = pkbf(u00 - __uint_as_float(h0 << 16),
                               u01 - __uint_as_float(h0 & 0xFFFF0000u));
            uint32_t h1 = pkbf(u10, u11);
            uint32_t l1 = pkbf(u10 - __uint_as_float(h1 << 16),
                               u11 - __uint_as_float(h1 & 0xFFFF0000u));
            *reinterpret_cast<uint32_t*>(smem + OU_H + ((mw + g) * TPX + t) * 2)     = h0;
            *reinterpret_cast<uint32_t*>(smem + OU_L + ((mw + g) * TPX + t) * 2)     = l0;
            *reinterpret_cast<uint32_t*>(smem + OU_H + ((mw + g + 8) * TPX + t) * 2) = h1;
            *reinterpret_cast<uint32_t*>(smem + OU_L + ((mw + g + 8) * TPX + t) * 2) = l1;
        }
#pragma unroll
        for (int i = 0; i < 8; i++) {
            int f4 = tid + 256 * i;
            int o = f4 >> 4, c4 = (f4 & 15) << 2;
            float4 v = *reinterpret_cast<const float4*>(wo + o * CC + c4);
            uint2 hv, lv; cvt4(v, hv, lv);
            *reinterpret_cast<uint2*>(smem + OW_H + (o * TPX + c4) * 2) = hv;
            *reinterpret_cast<uint2*>(smem + OW_L + (o * TPX + c4) * 2) = lv;
        }
    }
    __syncthreads();

    // ---- stage 2: y = mask*(wo U + bo). m=o(128): 8 stripes of 16; n=t(64) full ----
    {
        const int mw2 = w * 16;
        float acc2[8][4];
#pragma unroll
        for (int j = 0; j < 8; j++)
#pragma unroll
            for (int qq = 0; qq < 4; qq++) acc2[j][qq] = 0.f;

        const uint32_t aoff2 = (uint32_t)(((mw2 + (q & 1) * 8 + i5) * TPX + (q >> 1) * 8) * 2);
        const uint32_t pa2h = sb + OW_H + aoff2, pa2l = sb + OW_L + aoff2;
        const uint32_t boff2 = (uint32_t)((((q & 1) * 8 + i5) * TPX + (q >> 1) * 8) * 2);
        const uint32_t pb2h = sb + OU_H + boff2, pb2l = sb + OU_L + boff2;

#pragma unroll
        for (int ks = 0; ks < 4; ks++) {
            uint32_t ah[4], al[4];
            ldm_x4(ah, pa2h + ks * 32);
            ldm_x4(al, pa2l + ks * 32);
#pragma unroll
            for (int jp = 0; jp < 4; jp++) {
                uint32_t off = (uint32_t)(ks * 16 * TPX * 2 + jp * 32);
                uint32_t bh[4], bl[4];
                ldm_x4t(bh, pb2h + off);
                ldm_x4t(bl, pb2l + off);
                mma_bf16(acc2[2 * jp],     ah, bh);
                mma_bf16(acc2[2 * jp],     ah, bl);
                mma_bf16(acc2[2 * jp],     al, bh);
                mma_bf16(acc2[2 * jp + 1], ah, bh + 2);
                mma_bf16(acc2[2 * jp + 1], ah, bl + 2);
                mma_bf16(acc2[2 * jp + 1], al, bh + 2);
            }
        }

        const int o = mw2 + g;
        const float bo0 = bo[o], bo1 = bo[o + 8];
        const float* mrow = mask + (size_t)b * TT + t0;
        float* yb = y + (size_t)b * DD * TT + t0;
#pragma unroll
        for (int j = 0; j < 8; j++) {
            int t = 8 * j + 2 * tg;
            float2 mk = *reinterpret_cast<const float2*>(mrow + t);
            float2 y0, y1;
            y0.x = (acc2[j][0] + bo0) * mk.x;
            y0.y = (acc2[j][1] + bo0) * mk.y;
            y1.x = (acc2[j][2] + bo1) * mk.x;
            y1.y = (acc2[j][3] + bo1) * mk.y;
            *reinterpret_cast<float2*>(yb + (size_t)o * TT + t)       = y0;
            *reinterpret_cast<float2*>(yb + (size_t)(o + 8) * TT + t) = y1;
        }
    }
}

static const int SMEM_K2C = (DD * KPAD + CC * KPAD * 2 + 8 * KPAD * 2 + 8 * CC +
                             DD + 3 * CC + 16) * (int)sizeof(float);

extern "C" void kernel_launch(void* const* d_in, const int* in_sizes, int n_in,
                              void* d_out, int out_size) {
    const float* x1   = (const float*)d_in[0];
    const float* mask = (const float*)d_in[2];
    const float* wq   = (const float*)d_in[3];
    const float* bq   = (const float*)d_in[4];
    const float* wk   = (const float*)d_in[5];
    const float* bk   = (const float*)d_in[6];
    const float* wv   = (const float*)d_in[7];
    const float* bv   = (const float*)d_in[8];
    const float* we   = (const float*)d_in[9];
    const float* be   = (const float*)d_in[10];
    const float* wf   = (const float*)d_in[11];
    const float* bf   = (const float*)d_in[12];
    const float* wo   = (const float*)d_in[13];
    const float* bo   = (const float*)d_in[14];
    float* y = (float*)d_out;

    cudaFuncSetAttribute(k2c_attn, cudaFuncAttributeMaxDynamicSharedMemorySize, SMEM_K2C);
    cudaFuncSetAttribute(k3f,      cudaFuncAttributeMaxDynamicSharedMemorySize, SMEM_K3F);

    void *pG = nullptr, *ps = nullptr;
    cudaGetSymbolAddress(&pG, g_G);
    cudaGetSymbolAddress(&ps, g_s);
    cudaMemsetAsync(pG, 0, BB * DD * DD * sizeof(float));   // launch 0
    cudaMemsetAsync(ps, 0, BB * DD * sizeof(float));        // launch 1

    k2a_weights<<<16, 256>>>(we, wk, bk, be, wf, wv, bv, bf);   // launch 2
    k1_mma<<<dim3(16, 8), 512>>>(x1);                            // launch 3
    k2c_attn<<<dim3(8, 8), 256, SMEM_K2C>>>(wq, bq);             // launch 4
    k3f<<<dim3(512, 8), 256, SMEM_K3F>>>(x1, wo, bo, mask, y);   // launch 5 (ncu -s 5)
}

// round 12
// speedup vs baseline: 3.2731x; 1.0001x over previous
#include <cuda_runtime.h>
#include <cuda_bf16.h>
#include <cstdint>

#define BB 8
#define DD 128
#define TT 32768
#define CC 64

typedef unsigned short ushort_t;

// ---------------- warp-level bf16 MMA + ldmatrix ----------------
__device__ __forceinline__ void mma_bf16(float* d, const uint32_t* a, const uint32_t* b) {
    asm volatile(
        "mma.sync.aligned.m16n8k16.row.col.f32.bf16.bf16.f32 "
        "{%0,%1,%2,%3}, {%4,%5,%6,%7}, {%8,%9}, {%0,%1,%2,%3};"
        : "+f"(d[0]), "+f"(d[1]), "+f"(d[2]), "+f"(d[3])
        : "r"(a[0]), "r"(a[1]), "r"(a[2]), "r"(a[3]), "r"(b[0]), "r"(b[1]));
}
__device__ __forceinline__ void ldm_x4(uint32_t* r, uint32_t addr) {
    asm volatile("ldmatrix.sync.aligned.m8n8.x4.shared.b16 {%0,%1,%2,%3}, [%4];"
        : "=r"(r[0]), "=r"(r[1]), "=r"(r[2]), "=r"(r[3]) : "r"(addr));
}
__device__ __forceinline__ void ldm_x4t(uint32_t* r, uint32_t addr) {
    asm volatile("ldmatrix.sync.aligned.m8n8.x4.trans.shared.b16 {%0,%1,%2,%3}, [%4];"
        : "=r"(r[0]), "=r"(r[1]), "=r"(r[2]), "=r"(r[3]) : "r"(addr));
}
__device__ __forceinline__ uint32_t pkbf(float v0, float v1) {
    uint32_t r; asm("cvt.rn.bf16x2.f32 %0, %1, %2;" : "=r"(r) : "f"(v1), "f"(v0)); return r;
}
__device__ __forceinline__ uint32_t smem_u32(const void* p) {
    uint32_t a;
    asm("{ .reg .u64 t; cvta.to.shared.u64 t, %1; cvt.u32.u64 %0, t; }" : "=r"(a) : "l"(p));
    return a;
}
// split float4 -> bf16 hi pair + lo (residual) pair
__device__ __forceinline__ void cvt4(const float4 v, uint2& h, uint2& lo) {
    h.x = pkbf(v.x, v.y); h.y = pkbf(v.z, v.w);
    float r0 = v.x - __uint_as_float(h.x << 16);
    float r1 = v.y - __uint_as_float(h.x & 0xFFFF0000u);
    float r2 = v.z - __uint_as_float(h.y << 16);
    float r3 = v.w - __uint_as_float(h.y & 0xFFFF0000u);
    lo.x = pkbf(r0, r1); lo.y = pkbf(r2, r3);
}
// split scalar
__device__ __forceinline__ void cvt1(float v, ushort_t& h, ushort_t& lo) {
    __nv_bfloat16 hb = __float2bfloat16_rn(v);
    h = __bfloat16_as_ushort(hb);
    lo = __bfloat16_as_ushort(__float2bfloat16_rn(v - __bfloat162float(hb)));
}

// ---------------- scratch (static device globals) ----------------
__device__ float g_G[BB * DD * DD];     // per-batch Gram (full, symmetric)
__device__ float g_s[BB * DD];          // per-batch row sums
__device__ float g_Bm[CC * DD];         // we @ wk
__device__ float g_F[CC * DD];          // wf @ wv
__device__ float g_k0[CC];
__device__ float g_v0[CC];
__device__ float g_cv[BB * CC];
__device__ ushort_t g_Mh[BB * CC * DD]; // M bf16 hi [b][c][d]
__device__ ushort_t g_Ml[BB * CC * DD]; // M bf16 lo
__device__ ushort_t g_Wh[DD * CC];      // wo bf16 hi [o][c]
__device__ ushort_t g_Wl[DD * CC];      // wo bf16 lo

// ================= K1 (mma.sync bf16 split, 512 thr): Gram + row sums =================
#define TSEG 2048
#define TCH  64
#define NCH  (TSEG / TCH)
#define KSTR 72

__global__ __launch_bounds__(512, 1) void k1_mma(const float* __restrict__ x) {
    __shared__ __align__(16) unsigned short sh_hi[DD][KSTR];
    __shared__ __align__(16) unsigned short sh_lo[DD][KSTR];
    const int tid = threadIdx.x;
    const int w   = tid >> 5, l = tid & 31;
    const int g   = l >> 2, tg = l & 3;
    const int q   = l >> 3, i5 = l & 7;
    const int b   = blockIdx.y;
    const int tseg = blockIdx.x * TSEG;
    const int d   = tid >> 2;
    const int kh  = (tid & 3) * 16;
    const float* xp = x + ((size_t)b * DD + d) * TT + tseg + kh;

    float accP[8][4], accC[8][4];
#pragma unroll
    for (int j = 0; j < 8; j++)
#pragma unroll
        for (int qq = 0; qq < 4; qq++) { accP[j][qq] = 0.f; accC[j][qq] = 0.f; }
    float srow = 0.f;

    const int m0 = (w & 7) * 16;
    const int n0 = (w >> 3) * 64;
    const uint32_t sbh = smem_u32(sh_hi);
    const uint32_t sbl = smem_u32(sh_lo);
    const uint32_t pa  = sbh + (uint32_t)(((m0 + (q & 1) * 8 + i5) * KSTR + (q >> 1) * 8) * 2);
    const uint32_t rb  = (uint32_t)(((n0 + (q >> 1) * 8 + i5) * KSTR + (q & 1) * 8) * 2);
    const uint32_t pbh = sbh + rb;
    const uint32_t pbl = sbl + rb;

    float4 r[4], r2[4];
#pragma unroll
    for (int ii = 0; ii < 4; ii++) r[ii] = *reinterpret_cast<const float4*>(xp + 4 * ii);

    for (int c = 0; c < NCH; c++) {
        if (c + 1 < NCH) {
            const float* xn = xp + (c + 1) * TCH;
#pragma unroll
            for (int ii = 0; ii < 4; ii++) r2[ii] = *reinterpret_cast<const float4*>(xn + 4 * ii);
        }
#pragma unroll
        for (int it = 0; it < 4; it++) {
            float4 v = r[it];
            srow += (v.x + v.y) + (v.z + v.w);
            uint2 hv, lv;
            cvt4(v, hv, lv);
            *reinterpret_cast<uint2*>(&sh_hi[d][kh + it * 4]) = hv;
            *reinterpret_cast<uint2*>(&sh_lo[d][kh + it * 4]) = lv;
        }
        __syncthreads();
#pragma unroll
        for (int ks = 0; ks < 4; ks++) {
            uint32_t ah[4];
            ldm_x4(ah, pa + ks * 32);
#pragma unroll
            for (int jp = 0; jp < 4; jp++) {
                const uint32_t boff = (uint32_t)(jp * 16 * KSTR * 2 + ks * 32);
                uint32_t bh[4], bl[4];
                ldm_x4(bh, pbh + boff);
                ldm_x4(bl, pbl + boff);
                mma_bf16(accP[2 * jp],     ah, bh);
                mma_bf16(accP[2 * jp + 1], ah, bh + 2);
                mma_bf16(accC[2 * jp],     ah, bl);
                mma_bf16(accC[2 * jp + 1], ah, bl + 2);
            }
        }
        __syncthreads();
#pragma unroll
        for (int ii = 0; ii < 4; ii++) r[ii] = r2[ii];
    }

    float* Gb = g_G + b * DD * DD;
    const int row = m0 + g;
#pragma unroll
    for (int j = 0; j < 8; j++) {
        const int col = n0 + j * 8 + tg * 2;
        atomicAdd(&Gb[row * DD + col],           accP[j][0] + accC[j][0]);
        atomicAdd(&Gb[row * DD + col + 1],       accP[j][1] + accC[j][1]);
        atomicAdd(&Gb[(row + 8) * DD + col],     accP[j][2] + accC[j][2]);
        atomicAdd(&Gb[(row + 8) * DD + col + 1], accP[j][3] + accC[j][3]);
        atomicAdd(&Gb[col * DD + row],           accC[j][0]);
        atomicAdd(&Gb[(col + 1) * DD + row],     accC[j][1]);
        atomicAdd(&Gb[col * DD + row + 8],       accC[j][2]);
        atomicAdd(&Gb[(col + 1) * DD + row + 8], accC[j][3]);
    }
    atomicAdd(&g_s[b * DD + d], srow);
}

// ============ K2a: weight products + wo bf16 split (grid 16) ============
__global__ void k2a_weights(const float* __restrict__ we, const float* __restrict__ wk,
                            const float* __restrict__ bk, const float* __restrict__ be,
                            const float* __restrict__ wf, const float* __restrict__ wv,
                            const float* __restrict__ bv, const float* __restrict__ bf,
                            const float* __restrict__ wo) {
    const int j = blockIdx.x, tid = threadIdx.x;
    if (j < 8) {
#pragma unroll
        for (int it = 0; it < 4; it++) {
            int idx = tid + 256 * it;
            int o = j * 8 + (idx >> 7);
            int d = idx & 127;
            float acc = 0.f;
            for (int c = 0; c < CC; c++) acc = fmaf(we[o * CC + c], wk[c * DD + d], acc);
            g_Bm[o * DD + d] = acc;
        }
        if (j == 0 && tid < CC) {
            float acc = be[tid];
            for (int c = 0; c < CC; c++) acc = fmaf(we[tid * CC + c], bk[c], acc);
            g_k0[tid] = acc;
        }
        if (j == 1) {
            // wo split: 128x64 elems
#pragma unroll
            for (int it = 0; it < 32; it++) {
                int idx = tid + 256 * it;
                float v = wo[idx];
                ushort_t h, lo; cvt1(v, h, lo);
                g_Wh[idx] = h; g_Wl[idx] = lo;
            }
        }
    } else {
        int jj = j - 8;
#pragma unroll
        for (int it = 0; it < 4; it++) {
            int idx = tid + 256 * it;
            int o = jj * 8 + (idx >> 7);
            int d = idx & 127;
            float acc = 0.f;
            for (int c = 0; c < CC; c++) acc = fmaf(wf[o * CC + c], wv[c * DD + d], acc);
            g_F[o * DD + d] = acc;
        }
        if (j == 8 && tid < CC) {
            float acc = bf[tid];
            for (int c = 0; c < CC; c++) acc = fmaf(wf[tid * CC + c], bv[c], acc);
            g_v0[tid] = acc;
        }
    }
}

// ============ K2c: AG + S + softmax + M(split) + cv. grid (8 c-groups, 8 b) ============
#define KPAD 132
__global__ void k2c_attn(const float* __restrict__ wq, const float* __restrict__ bq) {
    extern __shared__ float sm2[];
    float* Gs  = sm2;
    float* Bms = Gs  + DD * KPAD;
    float* Fs  = Bms + CC * KPAD;
    float* wqs = Fs  + CC * KPAD;
    float* AGs = wqs + 8 * KPAD;
    float* Ps  = AGs + 8 * KPAD;
    float* ss  = Ps  + 8 * CC;
    float* bs  = ss  + DD;
    float* k0s = bs  + CC;
    float* v0s = k0s + CC;
    float* qs  = v0s + CC;
    float* bqs = qs  + 8;
    const int cg = blockIdx.x, b = blockIdx.y, tid = threadIdx.x;

    const float* Gb = g_G + b * DD * DD;
    for (int i = tid; i < DD * 32; i += 256) {
        int r = i >> 5, c4 = (i & 31) << 2;
        *reinterpret_cast<float4*>(&Gs[r * KPAD + c4]) =
            *reinterpret_cast<const float4*>(&Gb[r * DD + c4]);
    }
    for (int i = tid; i < CC * 32; i += 256) {
        int r = i >> 5, c4 = (i & 31) << 2;
        *reinterpret_cast<float4*>(&Bms[r * KPAD + c4]) =
            *reinterpret_cast<const float4*>(&g_Bm[r * DD + c4]);
        *reinterpret_cast<float4*>(&Fs[r * KPAD + c4]) =
            *reinterpret_cast<const float4*>(&g_F[r * DD + c4]);
    }
    for (int i = tid; i < 8 * 32; i += 256) {
        int r = i >> 5, c4 = (i & 31) << 2;
        *reinterpret_cast<float4*>(&wqs[r * KPAD + c4]) =
            *reinterpret_cast<const float4*>(&wq[(cg * 8 + r) * DD + c4]);
    }
    if (tid < DD) ss[tid] = g_s[b * DD + tid];
    if (tid < CC) { k0s[tid] = g_k0[tid]; v0s[tid] = g_v0[tid]; }
    if (tid < 8)  bqs[tid] = bq[cg * 8 + tid];
    __syncthreads();

    if (tid < CC) {
        float a = 0.f;
        const float* r = &Bms[tid * KPAD];
        for (int d = 0; d < DD; d++) a = fmaf(r[d], ss[d], a);
        bs[tid] = a;
    } else if (tid < CC + 8) {
        int ci = tid - CC;
        float a = 0.f;
        const float* r = &wqs[ci * KPAD];
        for (int d = 0; d < DD; d++) a = fmaf(r[d], ss[d], a);
        qs[ci] = a;
    }
    {
        const int d = tid >> 1, cb = (tid & 1) * 4;
        float a0 = 0.f, a1 = 0.f, a2 = 0.f, a3 = 0.f;
        for (int d1 = 0; d1 < DD; d1++) {
            float g = Gs[d1 * KPAD + d];
            a0 = fmaf(g, wqs[(cb + 0) * KPAD + d1], a0);
            a1 = fmaf(g, wqs[(cb + 1) * KPAD + d1], a1);
            a2 = fmaf(g, wqs[(cb + 2) * KPAD + d1], a2);
            a3 = fmaf(g, wqs[(cb + 3) * KPAD + d1], a3);
        }
        AGs[(cb + 0) * KPAD + d] = a0;
        AGs[(cb + 1) * KPAD + d] = a1;
        AGs[(cb + 2) * KPAD + d] = a2;
        AGs[(cb + 3) * KPAD + d] = a3;
    }
    __syncthreads();

    {
        const int ci = tid >> 5, k = tid & 31;
#pragma unroll
        for (int rep = 0; rep < 2; rep++) {
            int kk = k + rep * 32;
            float acc = 0.f;
            for (int d4 = 0; d4 < 32; d4++) {
                float4 ag = *reinterpret_cast<const float4*>(&AGs[ci * KPAD + d4 * 4]);
                float4 bm = *reinterpret_cast<const float4*>(&Bms[kk * KPAD + d4 * 4]);
                acc = fmaf(ag.x, bm.x, acc); acc = fmaf(ag.y, bm.y, acc);
                acc = fmaf(ag.z, bm.z, acc); acc = fmaf(ag.w, bm.w, acc);
            }
            acc += qs[ci] * k0s[kk] + bqs[ci] * bs[kk] + (float)TT * bqs[ci] * k0s[kk];
            Ps[ci * CC + kk] = acc * 0.125f;
        }
    }
    __syncthreads();

    {
        const int w = tid >> 5, lane = tid & 31;
        float v0 = Ps[w * CC + lane], v1 = Ps[w * CC + lane + 32];
        float m = fmaxf(v0, v1);
#pragma unroll
        for (int off = 16; off; off >>= 1) m = fmaxf(m, __shfl_xor_sync(~0u, m, off));
        float e0 = expf(v0 - m), e1 = expf(v1 - m);
        float sum = e0 + e1;
#pragma unroll
        for (int off = 16; off; off >>= 1) sum += __shfl_xor_sync(~0u, sum, off);
        float inv = 1.f / sum;
        Ps[w * CC + lane]      = e0 * inv;
        Ps[w * CC + lane + 32] = e1 * inv;
    }
    __syncthreads();

    {
        const int d = tid >> 1, cb = (tid & 1) * 4;
        float a[4] = {0.f, 0.f, 0.f, 0.f};
        for (int k = 0; k < CC; k++) {
            float f = Fs[k * KPAD + d];
            a[0] = fmaf(Ps[(cb + 0) * CC + k], f, a[0]);
            a[1] = fmaf(Ps[(cb + 1) * CC + k], f, a[1]);
            a[2] = fmaf(Ps[(cb + 2) * CC + k], f, a[2]);
            a[3] = fmaf(Ps[(cb + 3) * CC + k], f, a[3]);
        }
#pragma unroll
        for (int i = 0; i < 4; i++) {
            ushort_t h, lo; cvt1(a[i], h, lo);
            int idx = b * CC * DD + (cg * 8 + cb + i) * DD + d;
            g_Mh[idx] = h; g_Ml[idx] = lo;
        }
    }
    if (tid < 8) {
        float acc = 0.f;
        for (int k = 0; k < CC; k++) acc = fmaf(Ps[tid * CC + k], v0s[k], acc);
        g_cv[b * CC + cg * 8 + tid] = acc;
    }
}

// ============ K3f (fused, tensor, 3 CTA/SM): y = mask*(wo@relu(M X + cv) + bo) ============
// grid (512, 8), 256 thr. t-tile 64. Smem overlay: region A = X then U; region B = M then W.
// M and W arrive pre-split in bf16 (plain uint4 copies — no cvt, half the bytes).
#define TPX 72    // X / U / W col stride (elems)
#define DPM 136   // M col stride
#define OX_H 0u
#define OX_L 18432u
#define OU_H 0u
#define OU_L 9216u
#define OM_H 36864u
#define OM_L 54272u
#define OW_H 36864u
#define OW_L 55296u
#define SMEM_K3F 73728

__global__ __launch_bounds__(256, 3) void k3f(const float* __restrict__ x,
                                              const float* __restrict__ bo,
                                              const float* __restrict__ mask,
                                              float* __restrict__ y) {
    extern __shared__ __align__(16) char smem[];
    const uint32_t sb = smem_u32(smem);
    const int tid = threadIdx.x;
    const int w = tid >> 5, l = tid & 31;
    const int g = l >> 2, tg = l & 3;
    const int q = l >> 3, i5 = l & 7;
    const int b  = blockIdx.y;
    const int t0 = blockIdx.x * 64;

    // ---- phase 1: convert X (128x64); copy M hi/lo (pre-split) ----
    {
        const float* xb = x + (size_t)b * DD * TT + t0;
#pragma unroll
        for (int i = 0; i < 8; i++) {
            int f4 = tid + 256 * i;
            int d = f4 >> 4, t4 = (f4 & 15) << 2;
            float4 v = *reinterpret_cast<const float4*>(xb + (size_t)d * TT + t4);
            uint2 hv, lv; cvt4(v, hv, lv);
            *reinterpret_cast<uint2*>(smem + OX_H + (d * TPX + t4) * 2) = hv;
            *reinterpret_cast<uint2*>(smem + OX_L + (d * TPX + t4) * 2) = lv;
        }
        const uint4* Mh = reinterpret_cast<const uint4*>(g_Mh + b * CC * DD);
        const uint4* Ml = reinterpret_cast<const uint4*>(g_Ml + b * CC * DD);
#pragma unroll
        for (int i = 0; i < 4; i++) {
            int f8 = tid + 256 * i;                 // 1024 uint4 = 64x128 ushorts
            int c = f8 >> 4, d8 = (f8 & 15) << 3;
            *reinterpret_cast<uint4*>(smem + OM_H + (c * DPM + d8) * 2) = Mh[f8];
            *reinterpret_cast<uint4*>(smem + OM_L + (c * DPM + d8) * 2) = Ml[f8];
        }
    }
    __syncthreads();

    // ---- stage 1: accU = M X. m=c(64): 4 stripes; n=t(64): 2 groups of 32 ----
    float accU[4][4];
    const int mw = (w & 3) * 16;
    const int nw = (w >> 2) * 32;
    {
#pragma unroll
        for (int j = 0; j < 4; j++)
#pragma unroll
            for (int qq = 0; qq < 4; qq++) accU[j][qq] = 0.f;

        const uint32_t aoff = (uint32_t)(((mw + (q & 1) * 8 + i5) * DPM + (q >> 1) * 8) * 2);
        const uint32_t pa_h = sb + OM_H + aoff, pa_l = sb + OM_L + aoff;
        const uint32_t boff = (uint32_t)((((q & 1) * 8 + i5) * TPX + nw + (q >> 1) * 8) * 2);
        const uint32_t pb_h = sb + OX_H + boff, pb_l = sb + OX_L + boff;

#pragma unroll
        for (int ks = 0; ks < 8; ks++) {
            uint32_t ah[4], al[4];
            ldm_x4(ah, pa_h + ks * 32);
            ldm_x4(al, pa_l + ks * 32);
#pragma unroll
            for (int jp = 0; jp < 2; jp++) {
                uint32_t off = (uint32_t)(ks * 16 * TPX * 2 + jp * 32);
                uint32_t bh[4], bl[4];
                ldm_x4t(bh, pb_h + off);
                ldm_x4t(bl, pb_l + off);
                mma_bf16(accU[2 * jp],     ah, bh);
                mma_bf16(accU[2 * jp],     ah, bl);
                mma_bf16(accU[2 * jp],     al, bh);
                mma_bf16(accU[2 * jp + 1], ah, bh + 2);
                mma_bf16(accU[2 * jp + 1], ah, bl + 2);
                mma_bf16(accU[2 * jp + 1], al, bh + 2);
            }
        }
    }
    __syncthreads();   // all X/M reads done; A and B regions free

    // ---- phase 3: write U (relu + split) into region A; copy W hi/lo into region B ----
    {
        const float cv0 = g_cv[b * CC + mw + g];
        const float cv1 = g_cv[b * CC + mw + g + 8];
#pragma unroll
        for (int j = 0; j < 4; j++) {
            int t = nw + 8 * j + 2 * tg;
            float u00 = fmaxf(accU[j][0] + cv0, 0.f);
            float u01 = fmaxf(accU[j][1] + cv0, 0.f);
            float u10 = fmaxf(accU[j][2] + cv1, 0.f);
            float u11 = fmaxf(accU[j][3] + cv1, 0.f);
            uint32_t h0 = pkbf(u00, u01);
            uint32_t l0 = pkbf(u00 - __uint_as_float(h0 << 16),
                               u01 - __uint_as_float(h0 & 0xFFFF0000u));
            uint32_t h1 = pkbf(u10, u11);
            uint32_t l1 = pkbf(u10 - __uint_as_float(h1 << 16),
                               u11 - __uint_as_float(h1 & 0xFFFF0000u));
            *reinterpret_cast<uint32_t*>(smem + OU_H + ((mw + g) * TPX + t) * 2)     = h0;
            *reinterpret_cast<uint32_t*>(smem + OU_L + ((mw + g) * TPX + t) * 2)     = l0;
            *reinterpret_cast<uint32_t*>(smem + OU_H + ((mw + g + 8) * TPX + t) * 2) = h1;
            *reinterpret_cast<uint32_t*>(smem + OU_L + ((mw + g + 8) * TPX + t) * 2) = l1;
        }
        const uint4* Wh = reinterpret_cast<const uint4*>(g_Wh);
        const uint4* Wl = reinterpret_cast<const uint4*>(g_Wl);
#pragma unroll
        for (int i = 0; i < 4; i++) {
            int f8 = tid + 256 * i;                 // 1024 uint4 = 128x64 ushorts
            int o = f8 >> 3, c8 = (f8 & 7) << 3;
            *reinterpret_cast<uint4*>(smem + OW_H + (o * TPX + c8) * 2) = Wh[f8];
            *reinterpret_cast<uint4*>(smem + OW_L + (o * TPX + c8) * 2) = Wl[f8];
        }
    }
    __syncthreads();

    // ---- stage 2: y = mask*(wo U + bo). m=o(128): 8 stripes of 16; n=t(64) full ----
    {
        const int mw2 = w * 16;
        float acc2[8][4];
#pragma unroll
        for (int j = 0; j < 8; j++)
#pragma unroll
            for (int qq = 0; qq < 4; qq++) acc2[j][qq] = 0.f;

        const uint32_t aoff2 = (uint32_t)(((mw2 + (q & 1) * 8 + i5) * TPX + (q >> 1) * 8) * 2);
        const uint32_t pa2h = sb + OW_H + aoff2, pa2l = sb + OW_L + aoff2;
        const uint32_t boff2 = (uint32_t)((((q & 1) * 8 + i5) * TPX + (q >> 1) * 8) * 2);
        const uint32_t pb2h = sb + OU_H + boff2, pb2l = sb + OU_L + boff2;

#pragma unroll
        for (int ks = 0; ks < 4; ks++) {
            uint32_t ah[4], al[4];
            ldm_x4(ah, pa2h + ks * 32);
            ldm_x4(al, pa2l + ks * 32);
#pragma unroll
            for (int jp = 0; jp < 4; jp++) {
                uint32_t off = (uint32_t)(ks * 16 * TPX * 2 + jp * 32);
                uint32_t bh[4], bl[4];
                ldm_x4t(bh, pb2h + off);
                ldm_x4t(bl, pb2l + off);
                mma_bf16(acc2[2 * jp],     ah, bh);
                mma_bf16(acc2[2 * jp],     ah, bl);
                mma_bf16(acc2[2 * jp],     al, bh);
                mma_bf16(acc2[2 * jp + 1], ah, bh + 2);
                mma_bf16(acc2[2 * jp + 1], ah, bl + 2);
                mma_bf16(acc2[2 * jp + 1], al, bh + 2);
            }
        }

        const int o = mw2 + g;
        const float bo0 = bo[o], bo1 = bo[o + 8];
        const float* mrow = mask + (size_t)b * TT + t0;
        float* yb = y + (size_t)b * DD * TT + t0;
#pragma unroll
        for (int j = 0; j < 8; j++) {
            int t = 8 * j + 2 * tg;
            float2 mk = *reinterpret_cast<const float2*>(mrow + t);
            float2 y0, y1;
            y0.x = (acc2[j][0] + bo0) * mk.x;
            y0.y = (acc2[j][1] + bo0) * mk.y;
            y1.x = (acc2[j][2] + bo1) * mk.x;
            y1.y = (acc2[j][3] + bo1) * mk.y;
            *reinterpret_cast<float2*>(yb + (size_t)o * TT + t)       = y0;
            *reinterpret_cast<float2*>(yb + (size_t)(o + 8) * TT + t) = y1;
        }
    }
}

static const int SMEM_K2C = (DD * KPAD + CC * KPAD * 2 + 8 * KPAD * 2 + 8 * CC +
                             DD + 3 * CC + 16) * (int)sizeof(float);

extern "C" void kernel_launch(void* const* d_in, const int* in_sizes, int n_in,
                              void* d_out, int out_size) {
    const float* x1   = (const float*)d_in[0];
    const float* mask = (const float*)d_in[2];
    const float* wq   = (const float*)d_in[3];
    const float* bq   = (const float*)d_in[4];
    const float* wk   = (const float*)d_in[5];
    const float* bk   = (const float*)d_in[6];
    const float* wv   = (const float*)d_in[7];
    const float* bv   = (const float*)d_in[8];
    const float* we   = (const float*)d_in[9];
    const float* be   = (const float*)d_in[10];
    const float* wf   = (const float*)d_in[11];
    const float* bf   = (const float*)d_in[12];
    const float* wo   = (const float*)d_in[13];
    const float* bo   = (const float*)d_in[14];
    float* y = (float*)d_out;

    cudaFuncSetAttribute(k2c_attn, cudaFuncAttributeMaxDynamicSharedMemorySize, SMEM_K2C);
    cudaFuncSetAttribute(k3f,      cudaFuncAttributeMaxDynamicSharedMemorySize, SMEM_K3F);

    void *pG = nullptr, *ps = nullptr;
    cudaGetSymbolAddress(&pG, g_G);
    cudaGetSymbolAddress(&ps, g_s);
    cudaMemsetAsync(pG, 0, BB * DD * DD * sizeof(float));   // launch 0
    cudaMemsetAsync(ps, 0, BB * DD * sizeof(float));        // launch 1

    k2a_weights<<<16, 256>>>(we, wk, bk, be, wf, wv, bv, bf, wo);  // launch 2
    k1_mma<<<dim3(16, 8), 512>>>(x1);                               // launch 3
    k2c_attn<<<dim3(8, 8), 256, SMEM_K2C>>>(wq, bq);                // launch 4
    k3f<<<dim3(512, 8), 256, SMEM_K3F>>>(x1, bo, mask, y);          // launch 5 (ncu -s 5)
}

// round 13
// speedup vs baseline: 3.3704x; 1.0297x over previous
#include <cuda_runtime.h>
#include <cuda_bf16.h>
#include <cstdint>

#define BB 8
#define DD 128
#define TT 32768
#define CC 64

typedef unsigned short ushort_t;

// ---------------- warp-level bf16 MMA + ldmatrix ----------------
__device__ __forceinline__ void mma_bf16(float* d, const uint32_t* a, const uint32_t* b) {
    asm volatile(
        "mma.sync.aligned.m16n8k16.row.col.f32.bf16.bf16.f32 "
        "{%0,%1,%2,%3}, {%4,%5,%6,%7}, {%8,%9}, {%0,%1,%2,%3};"
        : "+f"(d[0]), "+f"(d[1]), "+f"(d[2]), "+f"(d[3])
        : "r"(a[0]), "r"(a[1]), "r"(a[2]), "r"(a[3]), "r"(b[0]), "r"(b[1]));
}
__device__ __forceinline__ void ldm_x4(uint32_t* r, uint32_t addr) {
    asm volatile("ldmatrix.sync.aligned.m8n8.x4.shared.b16 {%0,%1,%2,%3}, [%4];"
        : "=r"(r[0]), "=r"(r[1]), "=r"(r[2]), "=r"(r[3]) : "r"(addr));
}
__device__ __forceinline__ void ldm_x4t(uint32_t* r, uint32_t addr) {
    asm volatile("ldmatrix.sync.aligned.m8n8.x4.trans.shared.b16 {%0,%1,%2,%3}, [%4];"
        : "=r"(r[0]), "=r"(r[1]), "=r"(r[2]), "=r"(r[3]) : "r"(addr));
}
__device__ __forceinline__ uint32_t pkbf(float v0, float v1) {
    uint32_t r; asm("cvt.rn.bf16x2.f32 %0, %1, %2;" : "=r"(r) : "f"(v1), "f"(v0)); return r;
}
__device__ __forceinline__ uint32_t smem_u32(const void* p) {
    uint32_t a;
    asm("{ .reg .u64 t; cvta.to.shared.u64 t, %1; cvt.u32.u64 %0, t; }" : "=r"(a) : "l"(p));
    return a;
}
// split float4 -> bf16 hi pair + lo (residual) pair
__device__ __forceinline__ void cvt4(const float4 v, uint2& h, uint2& lo) {
    h.x = pkbf(v.x, v.y); h.y = pkbf(v.z, v.w);
    float r0 = v.x - __uint_as_float(h.x << 16);
    float r1 = v.y - __uint_as_float(h.x & 0xFFFF0000u);
    float r2 = v.z - __uint_as_float(h.y << 16);
    float r3 = v.w - __uint_as_float(h.y & 0xFFFF0000u);
    lo.x = pkbf(r0, r1); lo.y = pkbf(r2, r3);
}
// split scalar
__device__ __forceinline__ void cvt1(float v, ushort_t& h, ushort_t& lo) {
    __nv_bfloat16 hb = __float2bfloat16_rn(v);
    h = __bfloat16_as_ushort(hb);
    lo = __bfloat16_as_ushort(__float2bfloat16_rn(v - __bfloat162float(hb)));
}

// ---------------- scratch (static device globals) ----------------
__device__ float g_G[BB * DD * DD];
__device__ float g_s[BB * DD];
__device__ float g_Bm[CC * DD];
__device__ float g_F[CC * DD];
__device__ float g_k0[CC];
__device__ float g_v0[CC];
__device__ float g_cv[BB * CC];
__device__ ushort_t g_Mh[BB * CC * DD];
__device__ ushort_t g_Ml[BB * CC * DD];
__device__ ushort_t g_Wh[DD * CC];
__device__ ushort_t g_Wl[DD * CC];

// ================= K1 (mma.sync bf16 split, 4m x 4n warp grid) =================
#define TSEG 2048
#define TCH  64
#define NCH  (TSEG / TCH)
#define KSTR 72
#define A2OFF (16 * KSTR * 2)   // byte offset of second m16 tile

__global__ __launch_bounds__(512, 1) void k1_mma(const float* __restrict__ x) {
    __shared__ __align__(16) unsigned short sh_hi[DD][KSTR];
    __shared__ __align__(16) unsigned short sh_lo[DD][KSTR];
    const int tid = threadIdx.x;
    const int w   = tid >> 5, l = tid & 31;
    const int g   = l >> 2, tg = l & 3;
    const int q   = l >> 3, i5 = l & 7;
    const int b   = blockIdx.y;
    const int tseg = blockIdx.x * TSEG;
    const int d   = tid >> 2;
    const int kh  = (tid & 3) * 16;
    const float* xp = x + ((size_t)b * DD + d) * TT + tseg + kh;

    float accP[2][4][4], accC[2][4][4];
#pragma unroll
    for (int mt = 0; mt < 2; mt++)
#pragma unroll
        for (int j = 0; j < 4; j++)
#pragma unroll
            for (int qq = 0; qq < 4; qq++) { accP[mt][j][qq] = 0.f; accC[mt][j][qq] = 0.f; }
    float srow = 0.f;

    const int m0 = (w & 3) * 32;
    const int n0 = (w >> 2) * 32;
    const uint32_t sbh = smem_u32(sh_hi);
    const uint32_t sbl = smem_u32(sh_lo);
    const uint32_t pa  = sbh + (uint32_t)(((m0 + (q & 1) * 8 + i5) * KSTR + (q >> 1) * 8) * 2);
    const uint32_t rb  = (uint32_t)(((n0 + (q >> 1) * 8 + i5) * KSTR + (q & 1) * 8) * 2);
    const uint32_t pbh = sbh + rb;
    const uint32_t pbl = sbl + rb;

    float4 r[4], r2[4];
#pragma unroll
    for (int ii = 0; ii < 4; ii++) r[ii] = *reinterpret_cast<const float4*>(xp + 4 * ii);

    for (int c = 0; c < NCH; c++) {
        if (c + 1 < NCH) {
            const float* xn = xp + (c + 1) * TCH;
#pragma unroll
            for (int ii = 0; ii < 4; ii++) r2[ii] = *reinterpret_cast<const float4*>(xn + 4 * ii);
        }
#pragma unroll
        for (int it = 0; it < 4; it++) {
            float4 v = r[it];
            srow += (v.x + v.y) + (v.z + v.w);
            uint2 hv, lv;
            cvt4(v, hv, lv);
            *reinterpret_cast<uint2*>(&sh_hi[d][kh + it * 4]) = hv;
            *reinterpret_cast<uint2*>(&sh_lo[d][kh + it * 4]) = lv;
        }
        __syncthreads();
#pragma unroll
        for (int ks = 0; ks < 4; ks++) {
            uint32_t ah0[4], ah1[4];
            ldm_x4(ah0, pa + ks * 32);
            ldm_x4(ah1, pa + A2OFF + ks * 32);
#pragma unroll
            for (int jp = 0; jp < 2; jp++) {
                const uint32_t boff = (uint32_t)(jp * 16 * KSTR * 2 + ks * 32);
                uint32_t bh[4], bl[4];
                ldm_x4(bh, pbh + boff);
                ldm_x4(bl, pbl + boff);
                mma_bf16(accP[0][2 * jp],     ah0, bh);
                mma_bf16(accP[0][2 * jp + 1], ah0, bh + 2);
                mma_bf16(accP[1][2 * jp],     ah1, bh);
                mma_bf16(accP[1][2 * jp + 1], ah1, bh + 2);
                mma_bf16(accC[0][2 * jp],     ah0, bl);
                mma_bf16(accC[0][2 * jp + 1], ah0, bl + 2);
                mma_bf16(accC[1][2 * jp],     ah1, bl);
                mma_bf16(accC[1][2 * jp + 1], ah1, bl + 2);
            }
        }
        __syncthreads();
#pragma unroll
        for (int ii = 0; ii < 4; ii++) r[ii] = r2[ii];
    }

    float* Gb = g_G + b * DD * DD;
#pragma unroll
    for (int mt = 0; mt < 2; mt++) {
        const int row = m0 + mt * 16 + g;
#pragma unroll
        for (int j = 0; j < 4; j++) {
            const int col = n0 + j * 8 + tg * 2;
            atomicAdd(&Gb[row * DD + col],           accP[mt][j][0] + accC[mt][j][0]);
            atomicAdd(&Gb[row * DD + col + 1],       accP[mt][j][1] + accC[mt][j][1]);
            atomicAdd(&Gb[(row + 8) * DD + col],     accP[mt][j][2] + accC[mt][j][2]);
            atomicAdd(&Gb[(row + 8) * DD + col + 1], accP[mt][j][3] + accC[mt][j][3]);
            atomicAdd(&Gb[col * DD + row],           accC[mt][j][0]);
            atomicAdd(&Gb[(col + 1) * DD + row],     accC[mt][j][1]);
            atomicAdd(&Gb[col * DD + row + 8],       accC[mt][j][2]);
            atomicAdd(&Gb[(col + 1) * DD + row + 8], accC[mt][j][3]);
        }
    }
    atomicAdd(&g_s[b * DD + d], srow);
}

// ============ K2a: weight products + wo bf16 split (grid 16) ============
__global__ void k2a_weights(const float* __restrict__ we, const float* __restrict__ wk,
                            const float* __restrict__ bk, const float* __restrict__ be,
                            const float* __restrict__ wf, const float* __restrict__ wv,
                            const float* __restrict__ bv, const float* __restrict__ bf,
                            const float* __restrict__ wo) {
    const int j = blockIdx.x, tid = threadIdx.x;
    if (j < 8) {
#pragma unroll
        for (int it = 0; it < 4; it++) {
            int idx = tid + 256 * it;
            int o = j * 8 + (idx >> 7);
            int d = idx & 127;
            float acc = 0.f;
            for (int c = 0; c < CC; c++) acc = fmaf(we[o * CC + c], wk[c * DD + d], acc);
            g_Bm[o * DD + d] = acc;
        }
        if (j == 0 && tid < CC) {
            float acc = be[tid];
            for (int c = 0; c < CC; c++) acc = fmaf(we[tid * CC + c], bk[c], acc);
            g_k0[tid] = acc;
        }
        if (j == 1) {
#pragma unroll
            for (int it = 0; it < 32; it++) {
                int idx = tid + 256 * it;
                float v = wo[idx];
                ushort_t h, lo; cvt1(v, h, lo);
                g_Wh[idx] = h; g_Wl[idx] = lo;
            }
        }
    } else {
        int jj = j - 8;
#pragma unroll
        for (int it = 0; it < 4; it++) {
            int idx = tid + 256 * it;
            int o = jj * 8 + (idx >> 7);
            int d = idx & 127;
            float acc = 0.f;
            for (int c = 0; c < CC; c++) acc = fmaf(wf[o * CC + c], wv[c * DD + d], acc);
            g_F[o * DD + d] = acc;
        }
        if (j == 8 && tid < CC) {
            float acc = bf[tid];
            for (int c = 0; c < CC; c++) acc = fmaf(wf[tid * CC + c], bv[c], acc);
            g_v0[tid] = acc;
        }
    }
}

// ============ K2c: AG + S + softmax + M(split) + cv. grid (8 c-groups, 8 b) ============
#define KPAD 132
__global__ void k2c_attn(const float* __restrict__ wq, const float* __restrict__ bq) {
    extern __shared__ float sm2[];
    float* Gs  = sm2;
    float* Bms = Gs  + DD * KPAD;
    float* Fs  = Bms + CC * KPAD;
    float* wqs = Fs  + CC * KPAD;
    float* AGs = wqs + 8 * KPAD;
    float* Ps  = AGs + 8 * KPAD;
    float* ss  = Ps  + 8 * CC;
    float* bs  = ss  + DD;
    float* k0s = bs  + CC;
    float* v0s = k0s + CC;
    float* qs  = v0s + CC;
    float* bqs = qs  + 8;
    const int cg = blockIdx.x, b = blockIdx.y, tid = threadIdx.x;

    const float* Gb = g_G + b * DD * DD;
    for (int i = tid; i < DD * 32; i += 256) {
        int r = i >> 5, c4 = (i & 31) << 2;
        *reinterpret_cast<float4*>(&Gs[r * KPAD + c4]) =
            *reinterpret_cast<const float4*>(&Gb[r * DD + c4]);
    }
    for (int i = tid; i < CC * 32; i += 256) {
        int r = i >> 5, c4 = (i & 31) << 2;
        *reinterpret_cast<float4*>(&Bms[r * KPAD + c4]) =
            *reinterpret_cast<const float4*>(&g_Bm[r * DD + c4]);
        *reinterpret_cast<float4*>(&Fs[r * KPAD + c4]) =
            *reinterpret_cast<const float4*>(&g_F[r * DD + c4]);
    }
    for (int i = tid; i < 8 * 32; i += 256) {
        int r = i >> 5, c4 = (i & 31) << 2;
        *reinterpret_cast<float4*>(&wqs[r * KPAD + c4]) =
            *reinterpret_cast<const float4*>(&wq[(cg * 8 + r) * DD + c4]);
    }
    if (tid < DD) ss[tid] = g_s[b * DD + tid];
    if (tid < CC) { k0s[tid] = g_k0[tid]; v0s[tid] = g_v0[tid]; }
    if (tid < 8)  bqs[tid] = bq[cg * 8 + tid];
    __syncthreads();

    if (tid < CC) {
        float a = 0.f;
        const float* r = &Bms[tid * KPAD];
        for (int d = 0; d < DD; d++) a = fmaf(r[d], ss[d], a);
        bs[tid] = a;
    } else if (tid < CC + 8) {
        int ci = tid - CC;
        float a = 0.f;
        const float* r = &wqs[ci * KPAD];
        for (int d = 0; d < DD; d++) a = fmaf(r[d], ss[d], a);
        qs[ci] = a;
    }
    {
        const int d = tid >> 1, cb = (tid & 1) * 4;
        float a0 = 0.f, a1 = 0.f, a2 = 0.f, a3 = 0.f;
        for (int d1 = 0; d1 < DD; d1++) {
            float g = Gs[d1 * KPAD + d];
            a0 = fmaf(g, wqs[(cb + 0) * KPAD + d1], a0);
            a1 = fmaf(g, wqs[(cb + 1) * KPAD + d1], a1);
            a2 = fmaf(g, wqs[(cb + 2) * KPAD + d1], a2);
            a3 = fmaf(g, wqs[(cb + 3) * KPAD + d1], a3);
        }
        AGs[(cb + 0) * KPAD + d] = a0;
        AGs[(cb + 1) * KPAD + d] = a1;
        AGs[(cb + 2) * KPAD + d] = a2;
        AGs[(cb + 3) * KPAD + d] = a3;
    }
    __syncthreads();

    {
        const int ci = tid >> 5, k = tid & 31;
#pragma unroll
        for (int rep = 0; rep < 2; rep++) {
            int kk = k + rep * 32;
            float acc = 0.f;
            for (int d4 = 0; d4 < 32; d4++) {
                float4 ag = *reinterpret_cast<const float4*>(&AGs[ci * KPAD + d4 * 4]);
                float4 bm = *reinterpret_cast<const float4*>(&Bms[kk * KPAD + d4 * 4]);
                acc = fmaf(ag.x, bm.x, acc); acc = fmaf(ag.y, bm.y, acc);
                acc = fmaf(ag.z, bm.z, acc); acc = fmaf(ag.w, bm.w, acc);
            }
            acc += qs[ci] * k0s[kk] + bqs[ci] * bs[kk] + (float)TT * bqs[ci] * k0s[kk];
            Ps[ci * CC + kk] = acc * 0.125f;
        }
    }
    __syncthreads();

    {
        const int w = tid >> 5, lane = tid & 31;
        float v0 = Ps[w * CC + lane], v1 = Ps[w * CC + lane + 32];
        float m = fmaxf(v0, v1);
#pragma unroll
        for (int off = 16; off; off >>= 1) m = fmaxf(m, __shfl_xor_sync(~0u, m, off));
        float e0 = expf(v0 - m), e1 = expf(v1 - m);
        float sum = e0 + e1;
#pragma unroll
        for (int off = 16; off; off >>= 1) sum += __shfl_xor_sync(~0u, sum, off);
        float inv = 1.f / sum;
        Ps[w * CC + lane]      = e0 * inv;
        Ps[w * CC + lane + 32] = e1 * inv;
    }
    __syncthreads();

    {
        const int d = tid >> 1, cb = (tid & 1) * 4;
        float a[4] = {0.f, 0.f, 0.f, 0.f};
        for (int k = 0; k < CC; k++) {
            float f = Fs[k * KPAD + d];
            a[0] = fmaf(Ps[(cb + 0) * CC + k], f, a[0]);
            a[1] = fmaf(Ps[(cb + 1) * CC + k], f, a[1]);
            a[2] = fmaf(Ps[(cb + 2) * CC + k], f, a[2]);
            a[3] = fmaf(Ps[(cb + 3) * CC + k], f, a[3]);
        }
#pragma unroll
        for (int i = 0; i < 4; i++) {
            ushort_t h, lo; cvt1(a[i], h, lo);
            int idx = b * CC * DD + (cg * 8 + cb + i) * DD + d;
            g_Mh[idx] = h; g_Ml[idx] = lo;
        }
    }
    if (tid < 8) {
        float acc = 0.f;
        for (int k = 0; k < CC; k++) acc = fmaf(Ps[tid * CC + k], v0s[k], acc);
        g_cv[b * CC + cg * 8 + tid] = acc;
    }
}

// ============ K3f (fused, tensor, 3 CTA/SM): y = mask*(wo@relu(M X + cv) + bo) ============
#define TPX 72
#define DPM 136
#define OX_H 0u
#define OX_L 18432u
#define OU_H 0u
#define OU_L 9216u
#define OM_H 36864u
#define OM_L 54272u
#define OW_H 36864u
#define OW_L 55296u
#define SMEM_K3F 73728

__global__ __launch_bounds__(256, 3) void k3f(const float* __restrict__ x,
                                              const float* __restrict__ bo,
                                              const float* __restrict__ mask,
                                              float* __restrict__ y) {
    extern __shared__ __align__(16) char smem[];
    const uint32_t sb = smem_u32(smem);
    const int tid = threadIdx.x;
    const int w = tid >> 5, l = tid & 31;
    const int g = l >> 2, tg = l & 3;
    const int q = l >> 3, i5 = l & 7;
    const int b  = blockIdx.y;
    const int t0 = blockIdx.x * 64;

    // ---- phase 1: convert X (128x64); copy M hi/lo (pre-split) ----
    {
        const float* xb = x + (size_t)b * DD * TT + t0;
#pragma unroll
        for (int i = 0; i < 8; i++) {
            int f4 = tid + 256 * i;
            int d = f4 >> 4, t4 = (f4 & 15) << 2;
            float4 v = *reinterpret_cast<const float4*>(xb + (size_t)d * TT + t4);
            uint2 hv, lv; cvt4(v, hv, lv);
            *reinterpret_cast<uint2*>(smem + OX_H + (d * TPX + t4) * 2) = hv;
            *reinterpret_cast<uint2*>(smem + OX_L + (d * TPX + t4) * 2) = lv;
        }
        const uint4* Mh = reinterpret_cast<const uint4*>(g_Mh + b * CC * DD);
        const uint4* Ml = reinterpret_cast<const uint4*>(g_Ml + b * CC * DD);
#pragma unroll
        for (int i = 0; i < 4; i++) {
            int f8 = tid + 256 * i;
            int c = f8 >> 4, d8 = (f8 & 15) << 3;
            *reinterpret_cast<uint4*>(smem + OM_H + (c * DPM + d8) * 2) = Mh[f8];
            *reinterpret_cast<uint4*>(smem + OM_L + (c * DPM + d8) * 2) = Ml[f8];
        }
    }
    __syncthreads();

    // ---- stage 1: accU = M X. m=c(64): 4 stripes; n=t(64): 2 groups of 32 ----
    float accU[4][4];
    const int mw = (w & 3) * 16;
    const int nw = (w >> 2) * 32;
    {
#pragma unroll
        for (int j = 0; j < 4; j++)
#pragma unroll
            for (int qq = 0; qq < 4; qq++) accU[j][qq] = 0.f;

        const uint32_t aoff = (uint32_t)(((mw + (q & 1) * 8 + i5) * DPM + (q >> 1) * 8) * 2);
        const uint32_t pa_h = sb + OM_H + aoff, pa_l = sb + OM_L + aoff;
        const uint32_t boff = (uint32_t)((((q & 1) * 8 + i5) * TPX + nw + (q >> 1) * 8) * 2);
        const uint32_t pb_h = sb + OX_H + boff, pb_l = sb + OX_L + boff;

#pragma unroll
        for (int ks = 0; ks < 8; ks++) {
            uint32_t ah[4], al[4];
            ldm_x4(ah, pa_h + ks * 32);
            ldm_x4(al, pa_l + ks * 32);
#pragma unroll
            for (int jp = 0; jp < 2; jp++) {
                uint32_t off = (uint32_t)(ks * 16 * TPX * 2 + jp * 32);
                uint32_t bh[4], bl[4];
                ldm_x4t(bh, pb_h + off);
                ldm_x4t(bl, pb_l + off);
                mma_bf16(accU[2 * jp],     ah, bh);
                mma_bf16(accU[2 * jp],     ah, bl);
                mma_bf16(accU[2 * jp],     al, bh);
                mma_bf16(accU[2 * jp + 1], ah, bh + 2);
                mma_bf16(accU[2 * jp + 1], ah, bl + 2);
                mma_bf16(accU[2 * jp + 1], al, bh + 2);
            }
        }
    }
    __syncthreads();

    // ---- phase 3: write U (relu + split) into region A; copy W hi/lo into region B ----
    {
        const float cv0 = g_cv[b * CC + mw + g];
        const float cv1 = g_cv[b * CC + mw + g + 8];
#pragma unroll
        for (int j = 0; j < 4; j++) {
            int t = nw + 8 * j + 2 * tg;
            float u00 = fmaxf(accU[j][0] + cv0, 0.f);
            float u01 = fmaxf(accU[j][1] + cv0, 0.f);
            float u10 = fmaxf(accU[j][2] + cv1, 0.f);
            float u11 = fmaxf(accU[j][3] + cv1, 0.f);
            uint32_t h0 = pkbf(u00, u01);
            uint32_t l0 = pkbf(u00 - __uint_as_float(h0 << 16),
                               u01 - __uint_as_float(h0 & 0xFFFF0000u));
            uint32_t h1 = pkbf(u10, u11);
            uint32_t l1 = pkbf(u10 - __uint_as_float(h1 << 16),
                               u11 - __uint_as_float(h1 & 0xFFFF0000u));
            *reinterpret_cast<uint32_t*>(smem + OU_H + ((mw + g) * TPX + t) * 2)     = h0;
            *reinterpret_cast<uint32_t*>(smem + OU_L + ((mw + g) * TPX + t) * 2)     = l0;
            *reinterpret_cast<uint32_t*>(smem + OU_H + ((mw + g + 8) * TPX + t) * 2) = h1;
            *reinterpret_cast<uint32_t*>(smem + OU_L + ((mw + g + 8) * TPX + t) * 2) = l1;
        }
        const uint4* Wh = reinterpret_cast<const uint4*>(g_Wh);
        const uint4* Wl = reinterpret_cast<const uint4*>(g_Wl);
#pragma unroll
        for (int i = 0; i < 4; i++) {
            int f8 = tid + 256 * i;
            int o = f8 >> 3, c8 = (f8 & 7) << 3;
            *reinterpret_cast<uint4*>(smem + OW_H + (o * TPX + c8) * 2) = Wh[f8];
            *reinterpret_cast<uint4*>(smem + OW_L + (o * TPX + c8) * 2) = Wl[f8];
        }
    }
    __syncthreads();

    // ---- stage 2: y = mask*(wo U + bo). 4m x 2n warp grid (32o x 32t per warp) ----
    {
        const int mw2 = (w & 3) * 32;
        const int nw2 = (w >> 2) * 32;
        float acc2[2][4][4];
#pragma unroll
        for (int mt = 0; mt < 2; mt++)
#pragma unroll
            for (int j = 0; j < 4; j++)
#pragma unroll
                for (int qq = 0; qq < 4; qq++) acc2[mt][j][qq] = 0.f;

        const uint32_t aoff2 = (uint32_t)(((mw2 + (q & 1) * 8 + i5) * TPX + (q >> 1) * 8) * 2);
        const uint32_t pa2h = sb + OW_H + aoff2, pa2l = sb + OW_L + aoff2;
        const uint32_t A2 = (uint32_t)(16 * TPX * 2);
        const uint32_t boff2 = (uint32_t)((((q & 1) * 8 + i5) * TPX + nw2 + (q >> 1) * 8) * 2);
        const uint32_t pb2h = sb + OU_H + boff2, pb2l = sb + OU_L + boff2;

#pragma unroll
        for (int ks = 0; ks < 4; ks++) {
            uint32_t ah0[4], al0[4], ah1[4], al1[4];
            ldm_x4(ah0, pa2h + ks * 32);
            ldm_x4(al0, pa2l + ks * 32);
            ldm_x4(ah1, pa2h + A2 + ks * 32);
            ldm_x4(al1, pa2l + A2 + ks * 32);
#pragma unroll
            for (int jp = 0; jp < 2; jp++) {
                uint32_t off = (uint32_t)(ks * 16 * TPX * 2 + jp * 32);
                uint32_t bh[4], bl[4];
                ldm_x4t(bh, pb2h + off);
                ldm_x4t(bl, pb2l + off);
                mma_bf16(acc2[0][2 * jp],     ah0, bh);
                mma_bf16(acc2[0][2 * jp],     ah0, bl);
                mma_bf16(acc2[0][2 * jp],     al0, bh);
                mma_bf16(acc2[0][2 * jp + 1], ah0, bh + 2);
                mma_bf16(acc2[0][2 * jp + 1], ah0, bl + 2);
                mma_bf16(acc2[0][2 * jp + 1], al0, bh + 2);
                mma_bf16(acc2[1][2 * jp],     ah1, bh);
                mma_bf16(acc2[1][2 * jp],     ah1, bl);
                mma_bf16(acc2[1][2 * jp],     al1, bh);
                mma_bf16(acc2[1][2 * jp + 1], ah1, bh + 2);
                mma_bf16(acc2[1][2 * jp + 1], ah1, bl + 2);
                mma_bf16(acc2[1][2 * jp + 1], al1, bh + 2);
            }
        }

        const float* mrow = mask + (size_t)b * TT + t0;
        float* yb = y + (size_t)b * DD * TT + t0;
#pragma unroll
        for (int mt = 0; mt < 2; mt++) {
            const int o = mw2 + mt * 16 + g;
            const float bo0 = bo[o], bo1 = bo[o + 8];
#pragma unroll
            for (int j = 0; j < 4; j++) {
                int t = nw2 + 8 * j + 2 * tg;
                float2 mk = *reinterpret_cast<const float2*>(mrow + t);
                float2 y0, y1;
                y0.x = (acc2[mt][j][0] + bo0) * mk.x;
                y0.y = (acc2[mt][j][1] + bo0) * mk.y;
                y1.x = (acc2[mt][j][2] + bo1) * mk.x;
                y1.y = (acc2[mt][j][3] + bo1) * mk.y;
                *reinterpret_cast<float2*>(yb + (size_t)o * TT + t)       = y0;
                *reinterpret_cast<float2*>(yb + (size_t)(o + 8) * TT + t) = y1;
            }
        }
    }
}

static const int SMEM_K2C = (DD * KPAD + CC * KPAD * 2 + 8 * KPAD * 2 + 8 * CC +
                             DD + 3 * CC + 16) * (int)sizeof(float);

extern "C" void kernel_launch(void* const* d_in, const int* in_sizes, int n_in,
                              void* d_out, int out_size) {
    const float* x1   = (const float*)d_in[0];
    const float* mask = (const float*)d_in[2];
    const float* wq   = (const float*)d_in[3];
    const float* bq   = (const float*)d_in[4];
    const float* wk   = (const float*)d_in[5];
    const float* bk   = (const float*)d_in[6];
    const float* wv   = (const float*)d_in[7];
    const float* bv   = (const float*)d_in[8];
    const float* we   = (const float*)d_in[9];
    const float* be   = (const float*)d_in[10];
    const float* wf   = (const float*)d_in[11];
    const float* bf   = (const float*)d_in[12];
    const float* wo   = (const float*)d_in[13];
    const float* bo   = (const float*)d_in[14];
    float* y = (float*)d_out;

    cudaFuncSetAttribute(k2c_attn, cudaFuncAttributeMaxDynamicSharedMemorySize, SMEM_K2C);
    cudaFuncSetAttribute(k3f,      cudaFuncAttributeMaxDynamicSharedMemorySize, SMEM_K3F);

    void *pG = nullptr, *ps = nullptr;
    cudaGetSymbolAddress(&pG, g_G);
    cudaGetSymbolAddress(&ps, g_s);
    cudaMemsetAsync(pG, 0, BB * DD * DD * sizeof(float));   // launch 0
    cudaMemsetAsync(ps, 0, BB * DD * sizeof(float));        // launch 1

    k2a_weights<<<16, 256>>>(we, wk, bk, be, wf, wv, bv, bf, wo);  // launch 2
    k1_mma<<<dim3(16, 8), 512>>>(x1);                               // launch 3
    k2c_attn<<<dim3(8, 8), 256, SMEM_K2C>>>(wq, bq);                // launch 4
    k3f<<<dim3(512, 8), 256, SMEM_K3F>>>(x1, bo, mask, y);          // launch 5 (ncu -s 5)
}

// round 14
// speedup vs baseline: 3.4996x; 1.0383x over previous
#include <cuda_runtime.h>
#include <cuda_bf16.h>
#include <cstdint>

#define BB 8
#define DD 128
#define TT 32768
#define CC 64

typedef unsigned short ushort_t;

// ---------------- warp-level bf16 MMA + ldmatrix ----------------
__device__ __forceinline__ void mma_bf16(float* d, const uint32_t* a, const uint32_t* b) {
    asm volatile(
        "mma.sync.aligned.m16n8k16.row.col.f32.bf16.bf16.f32 "
        "{%0,%1,%2,%3}, {%4,%5,%6,%7}, {%8,%9}, {%0,%1,%2,%3};"
        : "+f"(d[0]), "+f"(d[1]), "+f"(d[2]), "+f"(d[3])
        : "r"(a[0]), "r"(a[1]), "r"(a[2]), "r"(a[3]), "r"(b[0]), "r"(b[1]));
}
__device__ __forceinline__ void ldm_x4(uint32_t* r, uint32_t addr) {
    asm volatile("ldmatrix.sync.aligned.m8n8.x4.shared.b16 {%0,%1,%2,%3}, [%4];"
        : "=r"(r[0]), "=r"(r[1]), "=r"(r[2]), "=r"(r[3]) : "r"(addr));
}
__device__ __forceinline__ void ldm_x4t(uint32_t* r, uint32_t addr) {
    asm volatile("ldmatrix.sync.aligned.m8n8.x4.trans.shared.b16 {%0,%1,%2,%3}, [%4];"
        : "=r"(r[0]), "=r"(r[1]), "=r"(r[2]), "=r"(r[3]) : "r"(addr));
}
__device__ __forceinline__ uint32_t pkbf(float v0, float v1) {
    uint32_t r; asm("cvt.rn.bf16x2.f32 %0, %1, %2;" : "=r"(r) : "f"(v1), "f"(v0)); return r;
}
__device__ __forceinline__ uint32_t smem_u32(const void* p) {
    uint32_t a;
    asm("{ .reg .u64 t; cvta.to.shared.u64 t, %1; cvt.u32.u64 %0, t; }" : "=r"(a) : "l"(p));
    return a;
}
// split float4 -> bf16 hi pair + lo (residual) pair
__device__ __forceinline__ void cvt4(const float4 v, uint2& h, uint2& lo) {
    h.x = pkbf(v.x, v.y); h.y = pkbf(v.z, v.w);
    float r0 = v.x - __uint_as_float(h.x << 16);
    float r1 = v.y - __uint_as_float(h.x & 0xFFFF0000u);
    float r2 = v.z - __uint_as_float(h.y << 16);
    float r3 = v.w - __uint_as_float(h.y & 0xFFFF0000u);
    lo.x = pkbf(r0, r1); lo.y = pkbf(r2, r3);
}
// split scalar
__device__ __forceinline__ void cvt1(float v, ushort_t& h, ushort_t& lo) {
    __nv_bfloat16 hb = __float2bfloat16_rn(v);
    h = __bfloat16_as_ushort(hb);
    lo = __bfloat16_as_ushort(__float2bfloat16_rn(v - __bfloat162float(hb)));
}

// ---------------- scratch (static device globals) ----------------
__device__ float g_G[BB * DD * DD];
__device__ float g_s[BB * DD];
__device__ float g_Bm[CC * DD];
__device__ float g_F[CC * DD];
__device__ float g_k0[CC];
__device__ float g_v0[CC];
__device__ float g_cv[BB * CC];
__device__ ushort_t g_Mh[BB * CC * DD];
__device__ ushort_t g_Ml[BB * CC * DD];
__device__ ushort_t g_Wh[DD * CC];
__device__ ushort_t g_Wl[DD * CC];

// ================= K1 (mma.sync bf16 split, 4m x 4n, double-buffered) =================
#define TSEG 2048
#define TCH  64
#define NCH  (TSEG / TCH)
#define KSTR 72
#define A2OFF (16 * KSTR * 2)       // byte offset of second m16 tile
#define K1BUF (2 * DD * KSTR * 2)   // one buffer = hi + lo = 36864 B
#define K1LO  (DD * KSTR * 2)       // lo offset inside a buffer = 18432 B
#define SMEM_K1 (2 * K1BUF)         // 73728 B

__global__ __launch_bounds__(512, 1) void k1_mma(const float* __restrict__ x) {
    extern __shared__ __align__(16) char sm1[];
    const int tid = threadIdx.x;
    const int w   = tid >> 5, l = tid & 31;
    const int g   = l >> 2, tg = l & 3;
    const int q   = l >> 3, i5 = l & 7;
    const int b   = blockIdx.y;
    const int tseg = blockIdx.x * TSEG;
    const int d   = tid >> 2;
    const int kh  = (tid & 3) * 16;
    const float* xp = x + ((size_t)b * DD + d) * TT + tseg + kh;

    float accP[2][4][4], accC[2][4][4];
#pragma unroll
    for (int mt = 0; mt < 2; mt++)
#pragma unroll
        for (int j = 0; j < 4; j++)
#pragma unroll
            for (int qq = 0; qq < 4; qq++) { accP[mt][j][qq] = 0.f; accC[mt][j][qq] = 0.f; }
    float srow = 0.f;

    const int m0 = (w & 3) * 32;
    const int n0 = (w >> 2) * 32;
    const uint32_t sb0 = smem_u32(sm1);
    // ldmatrix bases per buffer
    const uint32_t aoff = (uint32_t)(((m0 + (q & 1) * 8 + i5) * KSTR + (q >> 1) * 8) * 2);
    const uint32_t boff = (uint32_t)(((n0 + (q >> 1) * 8 + i5) * KSTR + (q & 1) * 8) * 2);
    uint32_t pa[2], pbh[2], pbl[2];
#pragma unroll
    for (int bu = 0; bu < 2; bu++) {
        pa[bu]  = sb0 + bu * K1BUF + aoff;
        pbh[bu] = sb0 + bu * K1BUF + boff;
        pbl[bu] = sb0 + bu * K1BUF + K1LO + boff;
    }
    // store base (this thread's row/khalf), per buffer
    char* stH[2]; char* stL[2];
#pragma unroll
    for (int bu = 0; bu < 2; bu++) {
        stH[bu] = sm1 + bu * K1BUF + (d * KSTR + kh) * 2;
        stL[bu] = stH[bu] + K1LO;
    }

    // prologue: load + convert chunk 0 into buffer 0
    {
        float4 v[4];
#pragma unroll
        for (int ii = 0; ii < 4; ii++) v[ii] = *reinterpret_cast<const float4*>(xp + 4 * ii);
#pragma unroll
        for (int it = 0; it < 4; it++) {
            srow += (v[it].x + v[it].y) + (v[it].z + v[it].w);
            uint2 hv, lv; cvt4(v[it], hv, lv);
            *reinterpret_cast<uint2*>(stH[0] + it * 8) = hv;
            *reinterpret_cast<uint2*>(stL[0] + it * 8) = lv;
        }
    }
    __syncthreads();

    for (int c = 0; c < NCH; c++) {
        const int cur = c & 1, nxt = cur ^ 1;
        float4 r2[4];
        if (c + 1 < NCH) {
            const float* xn = xp + (c + 1) * TCH;
#pragma unroll
            for (int ii = 0; ii < 4; ii++) r2[ii] = *reinterpret_cast<const float4*>(xn + 4 * ii);
        }
        // mma on current buffer
#pragma unroll
        for (int ks = 0; ks < 4; ks++) {
            uint32_t ah0[4], ah1[4];
            ldm_x4(ah0, pa[cur] + ks * 32);
            ldm_x4(ah1, pa[cur] + A2OFF + ks * 32);
#pragma unroll
            for (int jp = 0; jp < 2; jp++) {
                const uint32_t bo2 = (uint32_t)(jp * 16 * KSTR * 2 + ks * 32);
                uint32_t bh[4], bl[4];
                ldm_x4(bh, pbh[cur] + bo2);
                ldm_x4(bl, pbl[cur] + bo2);
                mma_bf16(accP[0][2 * jp],     ah0, bh);
                mma_bf16(accP[0][2 * jp + 1], ah0, bh + 2);
                mma_bf16(accP[1][2 * jp],     ah1, bh);
                mma_bf16(accP[1][2 * jp + 1], ah1, bh + 2);
                mma_bf16(accC[0][2 * jp],     ah0, bl);
                mma_bf16(accC[0][2 * jp + 1], ah0, bl + 2);
                mma_bf16(accC[1][2 * jp],     ah1, bl);
                mma_bf16(accC[1][2 * jp + 1], ah1, bl + 2);
            }
        }
        // convert + store next chunk into the other buffer
        if (c + 1 < NCH) {
#pragma unroll
            for (int it = 0; it < 4; it++) {
                srow += (r2[it].x + r2[it].y) + (r2[it].z + r2[it].w);
                uint2 hv, lv; cvt4(r2[it], hv, lv);
                *reinterpret_cast<uint2*>(stH[nxt] + it * 8) = hv;
                *reinterpret_cast<uint2*>(stL[nxt] + it * 8) = lv;
            }
        }
        __syncthreads();
    }

    float* Gb = g_G + b * DD * DD;
#pragma unroll
    for (int mt = 0; mt < 2; mt++) {
        const int row = m0 + mt * 16 + g;
#pragma unroll
        for (int j = 0; j < 4; j++) {
            const int col = n0 + j * 8 + tg * 2;
            atomicAdd(&Gb[row * DD + col],           accP[mt][j][0] + accC[mt][j][0]);
            atomicAdd(&Gb[row * DD + col + 1],       accP[mt][j][1] + accC[mt][j][1]);
            atomicAdd(&Gb[(row + 8) * DD + col],     accP[mt][j][2] + accC[mt][j][2]);
            atomicAdd(&Gb[(row + 8) * DD + col + 1], accP[mt][j][3] + accC[mt][j][3]);
            atomicAdd(&Gb[col * DD + row],           accC[mt][j][0]);
            atomicAdd(&Gb[(col + 1) * DD + row],     accC[mt][j][1]);
            atomicAdd(&Gb[col * DD + row + 8],       accC[mt][j][2]);
            atomicAdd(&Gb[(col + 1) * DD + row + 8], accC[mt][j][3]);
        }
    }
    atomicAdd(&g_s[b * DD + d], srow);
}

// ============ K2a: zero G/s + weight products + wo bf16 split (grid 16) ============
__global__ void k2a_weights(const float* __restrict__ we, const float* __restrict__ wk,
                            const float* __restrict__ bk, const float* __restrict__ be,
                            const float* __restrict__ wf, const float* __restrict__ wv,
                            const float* __restrict__ bv, const float* __restrict__ bf,
                            const float* __restrict__ wo) {
    const int j = blockIdx.x, tid = threadIdx.x;
    // zero accumulators (replaces host memsets): 16x256 threads cover all
    {
        const int gi = j * 256 + tid;
        float4 z = {0.f, 0.f, 0.f, 0.f};
        float4* G4 = reinterpret_cast<float4*>(g_G);
#pragma unroll
        for (int it = 0; it < 8; it++) G4[gi + 4096 * it] = z;   // 32768 float4 total
        if (gi < BB * DD) g_s[gi] = 0.f;
    }
    if (j < 8) {
#pragma unroll
        for (int it = 0; it < 4; it++) {
            int idx = tid + 256 * it;
            int o = j * 8 + (idx >> 7);
            int d = idx & 127;
            float acc = 0.f;
            for (int c = 0; c < CC; c++) acc = fmaf(we[o * CC + c], wk[c * DD + d], acc);
            g_Bm[o * DD + d] = acc;
        }
        if (j == 0 && tid < CC) {
            float acc = be[tid];
            for (int c = 0; c < CC; c++) acc = fmaf(we[tid * CC + c], bk[c], acc);
            g_k0[tid] = acc;
        }
        if (j == 1) {
#pragma unroll
            for (int it = 0; it < 32; it++) {
                int idx = tid + 256 * it;
                float v = wo[idx];
                ushort_t h, lo; cvt1(v, h, lo);
                g_Wh[idx] = h; g_Wl[idx] = lo;
            }
        }
    } else {
        int jj = j - 8;
#pragma unroll
        for (int it = 0; it < 4; it++) {
            int idx = tid + 256 * it;
            int o = jj * 8 + (idx >> 7);
            int d = idx & 127;
            float acc = 0.f;
            for (int c = 0; c < CC; c++) acc = fmaf(wf[o * CC + c], wv[c * DD + d], acc);
            g_F[o * DD + d] = acc;
        }
        if (j == 8 && tid < CC) {
            float acc = bf[tid];
            for (int c = 0; c < CC; c++) acc = fmaf(wf[tid * CC + c], bv[c], acc);
            g_v0[tid] = acc;
        }
    }
}

// ============ K2c: AG + S + softmax + M(split) + cv. grid (8 c-groups, 8 b) ============
#define KPAD 132
__global__ void k2c_attn(const float* __restrict__ wq, const float* __restrict__ bq) {
    extern __shared__ float sm2[];
    float* Gs  = sm2;
    float* Bms = Gs  + DD * KPAD;
    float* Fs  = Bms + CC * KPAD;
    float* wqs = Fs  + CC * KPAD;
    float* AGs = wqs + 8 * KPAD;
    float* Ps  = AGs + 8 * KPAD;
    float* ss  = Ps  + 8 * CC;
    float* bs  = ss  + DD;
    float* k0s = bs  + CC;
    float* v0s = k0s + CC;
    float* qs  = v0s + CC;
    float* bqs = qs  + 8;
    const int cg = blockIdx.x, b = blockIdx.y, tid = threadIdx.x;

    const float* Gb = g_G + b * DD * DD;
    for (int i = tid; i < DD * 32; i += 256) {
        int r = i >> 5, c4 = (i & 31) << 2;
        *reinterpret_cast<float4*>(&Gs[r * KPAD + c4]) =
            *reinterpret_cast<const float4*>(&Gb[r * DD + c4]);
    }
    for (int i = tid; i < CC * 32; i += 256) {
        int r = i >> 5, c4 = (i & 31) << 2;
        *reinterpret_cast<float4*>(&Bms[r * KPAD + c4]) =
            *reinterpret_cast<const float4*>(&g_Bm[r * DD + c4]);
        *reinterpret_cast<float4*>(&Fs[r * KPAD + c4]) =
            *reinterpret_cast<const float4*>(&g_F[r * DD + c4]);
    }
    for (int i = tid; i < 8 * 32; i += 256) {
        int r = i >> 5, c4 = (i & 31) << 2;
        *reinterpret_cast<float4*>(&wqs[r * KPAD + c4]) =
            *reinterpret_cast<const float4*>(&wq[(cg * 8 + r) * DD + c4]);
    }
    if (tid < DD) ss[tid] = g_s[b * DD + tid];
    if (tid < CC) { k0s[tid] = g_k0[tid]; v0s[tid] = g_v0[tid]; }
    if (tid < 8)  bqs[tid] = bq[cg * 8 + tid];
    __syncthreads();

    if (tid < CC) {
        float a = 0.f;
        const float* r = &Bms[tid * KPAD];
        for (int d = 0; d < DD; d++) a = fmaf(r[d], ss[d], a);
        bs[tid] = a;
    } else if (tid < CC + 8) {
        int ci = tid - CC;
        float a = 0.f;
        const float* r = &wqs[ci * KPAD];
        for (int d = 0; d < DD; d++) a = fmaf(r[d], ss[d], a);
        qs[ci] = a;
    }
    {
        const int d = tid >> 1, cb = (tid & 1) * 4;
        float a0 = 0.f, a1 = 0.f, a2 = 0.f, a3 = 0.f;
        for (int d1 = 0; d1 < DD; d1++) {
            float g = Gs[d1 * KPAD + d];
            a0 = fmaf(g, wqs[(cb + 0) * KPAD + d1], a0);
            a1 = fmaf(g, wqs[(cb + 1) * KPAD + d1], a1);
            a2 = fmaf(g, wqs[(cb + 2) * KPAD + d1], a2);
            a3 = fmaf(g, wqs[(cb + 3) * KPAD + d1], a3);
        }
        AGs[(cb + 0) * KPAD + d] = a0;
        AGs[(cb + 1) * KPAD + d] = a1;
        AGs[(cb + 2) * KPAD + d] = a2;
        AGs[(cb + 3) * KPAD + d] = a3;
    }
    __syncthreads();

    {
        const int ci = tid >> 5, k = tid & 31;
#pragma unroll
        for (int rep = 0; rep < 2; rep++) {
            int kk = k + rep * 32;
            float acc = 0.f;
            for (int d4 = 0; d4 < 32; d4++) {
                float4 ag = *reinterpret_cast<const float4*>(&AGs[ci * KPAD + d4 * 4]);
                float4 bm = *reinterpret_cast<const float4*>(&Bms[kk * KPAD + d4 * 4]);
                acc = fmaf(ag.x, bm.x, acc); acc = fmaf(ag.y, bm.y, acc);
                acc = fmaf(ag.z, bm.z, acc); acc = fmaf(ag.w, bm.w, acc);
            }
            acc += qs[ci] * k0s[kk] + bqs[ci] * bs[kk] + (float)TT * bqs[ci] * k0s[kk];
            Ps[ci * CC + kk] = acc * 0.125f;
        }
    }
    __syncthreads();

    {
        const int w = tid >> 5, lane = tid & 31;
        float v0 = Ps[w * CC + lane], v1 = Ps[w * CC + lane + 32];
        float m = fmaxf(v0, v1);
#pragma unroll
        for (int off = 16; off; off >>= 1) m = fmaxf(m, __shfl_xor_sync(~0u, m, off));
        float e0 = expf(v0 - m), e1 = expf(v1 - m);
        float sum = e0 + e1;
#pragma unroll
        for (int off = 16; off; off >>= 1) sum += __shfl_xor_sync(~0u, sum, off);
        float inv = 1.f / sum;
        Ps[w * CC + lane]      = e0 * inv;
        Ps[w * CC + lane + 32] = e1 * inv;
    }
    __syncthreads();

    {
        const int d = tid >> 1, cb = (tid & 1) * 4;
        float a[4] = {0.f, 0.f, 0.f, 0.f};
        for (int k = 0; k < CC; k++) {
            float f = Fs[k * KPAD + d];
            a[0] = fmaf(Ps[(cb + 0) * CC + k], f, a[0]);
            a[1] = fmaf(Ps[(cb + 1) * CC + k], f, a[1]);
            a[2] = fmaf(Ps[(cb + 2) * CC + k], f, a[2]);
            a[3] = fmaf(Ps[(cb + 3) * CC + k], f, a[3]);
        }
#pragma unroll
        for (int i = 0; i < 4; i++) {
            ushort_t h, lo; cvt1(a[i], h, lo);
            int idx = b * CC * DD + (cg * 8 + cb + i) * DD + d;
            g_Mh[idx] = h; g_Ml[idx] = lo;
        }
    }
    if (tid < 8) {
        float acc = 0.f;
        for (int k = 0; k < CC; k++) acc = fmaf(Ps[tid * CC + k], v0s[k], acc);
        g_cv[b * CC + cg * 8 + tid] = acc;
    }
}

// ============ K3f (fused, tensor, 3 CTA/SM): y = mask*(wo@relu(M X + cv) + bo) ============
#define TPX 72
#define DPM 136
#define OX_H 0u
#define OX_L 18432u
#define OU_H 0u
#define OU_L 9216u
#define OM_H 36864u
#define OM_L 54272u
#define OW_H 36864u
#define OW_L 55296u
#define SMEM_K3F 73728

__global__ __launch_bounds__(256, 3) void k3f(const float* __restrict__ x,
                                              const float* __restrict__ bo,
                                              const float* __restrict__ mask,
                                              float* __restrict__ y) {
    extern __shared__ __align__(16) char smem[];
    const uint32_t sb = smem_u32(smem);
    const int tid = threadIdx.x;
    const int w = tid >> 5, l = tid & 31;
    const int g = l >> 2, tg = l & 3;
    const int q = l >> 3, i5 = l & 7;
    const int b  = blockIdx.y;
    const int t0 = blockIdx.x * 64;

    {
        const float* xb = x + (size_t)b * DD * TT + t0;
#pragma unroll
        for (int i = 0; i < 8; i++) {
            int f4 = tid + 256 * i;
            int d = f4 >> 4, t4 = (f4 & 15) << 2;
            float4 v = *reinterpret_cast<const float4*>(xb + (size_t)d * TT + t4);
            uint2 hv, lv; cvt4(v, hv, lv);
            *reinterpret_cast<uint2*>(smem + OX_H + (d * TPX + t4) * 2) = hv;
            *reinterpret_cast<uint2*>(smem + OX_L + (d * TPX + t4) * 2) = lv;
        }
        const uint4* Mh = reinterpret_cast<const uint4*>(g_Mh + b * CC * DD);
        const uint4* Ml = reinterpret_cast<const uint4*>(g_Ml + b * CC * DD);
#pragma unroll
        for (int i = 0; i < 4; i++) {
            int f8 = tid + 256 * i;
            int c = f8 >> 4, d8 = (f8 & 15) << 3;
            *reinterpret_cast<uint4*>(smem + OM_H + (c * DPM + d8) * 2) = Mh[f8];
            *reinterpret_cast<uint4*>(smem + OM_L + (c * DPM + d8) * 2) = Ml[f8];
        }
    }
    __syncthreads();

    float accU[4][4];
    const int mw = (w & 3) * 16;
    const int nw = (w >> 2) * 32;
    {
#pragma unroll
        for (int j = 0; j < 4; j++)
#pragma unroll
            for (int qq = 0; qq < 4; qq++) accU[j][qq] = 0.f;

        const uint32_t aoff = (uint32_t)(((mw + (q & 1) * 8 + i5) * DPM + (q >> 1) * 8) * 2);
        const uint32_t pa_h = sb + OM_H + aoff, pa_l = sb + OM_L + aoff;
        const uint32_t boff = (uint32_t)((((q & 1) * 8 + i5) * TPX + nw + (q >> 1) * 8) * 2);
        const uint32_t pb_h = sb + OX_H + boff, pb_l = sb + OX_L + boff;

#pragma unroll
        for (int ks = 0; ks < 8; ks++) {
            uint32_t ah[4], al[4];
            ldm_x4(ah, pa_h + ks * 32);
            ldm_x4(al, pa_l + ks * 32);
#pragma unroll
            for (int jp = 0; jp < 2; jp++) {
                uint32_t off = (uint32_t)(ks * 16 * TPX * 2 + jp * 32);
                uint32_t bh[4], bl[4];
                ldm_x4t(bh, pb_h + off);
                ldm_x4t(bl, pb_l + off);
                mma_bf16(accU[2 * jp],     ah, bh);
                mma_bf16(accU[2 * jp],     ah, bl);
                mma_bf16(accU[2 * jp],     al, bh);
                mma_bf16(accU[2 * jp + 1], ah, bh + 2);
                mma_bf16(accU[2 * jp + 1], ah, bl + 2);
                mma_bf16(accU[2 * jp + 1], al, bh + 2);
            }
        }
    }
    __syncthreads();

    {
        const float cv0 = g_cv[b * CC + mw + g];
        const float cv1 = g_cv[b * CC + mw + g + 8];
#pragma unroll
        for (int j = 0; j < 4; j++) {
            int t = nw + 8 * j + 2 * tg;
            float u00 = fmaxf(accU[j][0] + cv0, 0.f);
            float u01 = fmaxf(accU[j][1] + cv0, 0.f);
            float u10 = fmaxf(accU[j][2] + cv1, 0.f);
            float u11 = fmaxf(accU[j][3] + cv1, 0.f);
            uint32_t h0 = pkbf(u00, u01);
            uint32_t l0 = pkbf(u00 - __uint_as_float(h0 << 16),
                               u01 - __uint_as_float(h0 & 0xFFFF0000u));
            uint32_t h1 = pkbf(u10, u11);
            uint32_t l1 = pkbf(u10 - __uint_as_float(h1 << 16),
                               u11 - __uint_as_float(h1 & 0xFFFF0000u));
            *reinterpret_cast<uint32_t*>(smem + OU_H + ((mw + g) * TPX + t) * 2)     = h0;
            *reinterpret_cast<uint32_t*>(smem + OU_L + ((mw + g) * TPX + t) * 2)     = l0;
            *reinterpret_cast<uint32_t*>(smem + OU_H + ((mw + g + 8) * TPX + t) * 2) = h1;
            *reinterpret_cast<uint32_t*>(smem + OU_L + ((mw + g + 8) * TPX + t) * 2) = l1;
        }
        const uint4* Wh = reinterpret_cast<const uint4*>(g_Wh);
        const uint4* Wl = reinterpret_cast<const uint4*>(g_Wl);
#pragma unroll
        for (int i = 0; i < 4; i++) {
            int f8 = tid + 256 * i;
            int o = f8 >> 3, c8 = (f8 & 7) << 3;
            *reinterpret_cast<uint4*>(smem + OW_H + (o * TPX + c8) * 2) = Wh[f8];
            *reinterpret_cast<uint4*>(smem + OW_L + (o * TPX + c8) * 2) = Wl[f8];
        }
    }
    __syncthreads();

    {
        const int mw2 = (w & 3) * 32;
        const int nw2 = (w >> 2) * 32;
        float acc2[2][4][4];
#pragma unroll
        for (int mt = 0; mt < 2; mt++)
#pragma unroll
            for (int j = 0; j < 4; j++)
#pragma unroll
                for (int qq = 0; qq < 4; qq++) acc2[mt][j][qq] = 0.f;

        const uint32_t aoff2 = (uint32_t)(((mw2 + (q & 1) * 8 + i5) * TPX + (q >> 1) * 8) * 2);
        const uint32_t pa2h = sb + OW_H + aoff2, pa2l = sb + OW_L + aoff2;
        const uint32_t A2 = (uint32_t)(16 * TPX * 2);
        const uint32_t boff2 = (uint32_t)((((q & 1) * 8 + i5) * TPX + nw2 + (q >> 1) * 8) * 2);
        const uint32_t pb2h = sb + OU_H + boff2, pb2l = sb + OU_L + boff2;

#pragma unroll
        for (int ks = 0; ks < 4; ks++) {
            uint32_t ah0[4], al0[4], ah1[4], al1[4];
            ldm_x4(ah0, pa2h + ks * 32);
            ldm_x4(al0, pa2l + ks * 32);
            ldm_x4(ah1, pa2h + A2 + ks * 32);
            ldm_x4(al1, pa2l + A2 + ks * 32);
#pragma unroll
            for (int jp = 0; jp < 2; jp++) {
                uint32_t off = (uint32_t)(ks * 16 * TPX * 2 + jp * 32);
                uint32_t bh[4], bl[4];
                ldm_x4t(bh, pb2h + off);
                ldm_x4t(bl, pb2l + off);
                mma_bf16(acc2[0][2 * jp],     ah0, bh);
                mma_bf16(acc2[0][2 * jp],     ah0, bl);
                mma_bf16(acc2[0][2 * jp],     al0, bh);
                mma_bf16(acc2[0][2 * jp + 1], ah0, bh + 2);
                mma_bf16(acc2[0][2 * jp + 1], ah0, bl + 2);
                mma_bf16(acc2[0][2 * jp + 1], al0, bh + 2);
                mma_bf16(acc2[1][2 * jp],     ah1, bh);
                mma_bf16(acc2[1][2 * jp],     ah1, bl);
                mma_bf16(acc2[1][2 * jp],     al1, bh);
                mma_bf16(acc2[1][2 * jp + 1], ah1, bh + 2);
                mma_bf16(acc2[1][2 * jp + 1], ah1, bl + 2);
                mma_bf16(acc2[1][2 * jp + 1], al1, bh + 2);
            }
        }

        const float* mrow = mask + (size_t)b * TT + t0;
        float* yb = y + (size_t)b * DD * TT + t0;
#pragma unroll
        for (int mt = 0; mt < 2; mt++) {
            const int o = mw2 + mt * 16 + g;
            const float bo0 = bo[o], bo1 = bo[o + 8];
#pragma unroll
            for (int j = 0; j < 4; j++) {
                int t = nw2 + 8 * j + 2 * tg;
                float2 mk = *reinterpret_cast<const float2*>(mrow + t);
                float2 y0, y1;
                y0.x = (acc2[mt][j][0] + bo0) * mk.x;
                y0.y = (acc2[mt][j][1] + bo0) * mk.y;
                y1.x = (acc2[mt][j][2] + bo1) * mk.x;
                y1.y = (acc2[mt][j][3] + bo1) * mk.y;
                *reinterpret_cast<float2*>(yb + (size_t)o * TT + t)       = y0;
                *reinterpret_cast<float2*>(yb + (size_t)(o + 8) * TT + t) = y1;
            }
        }
    }
}

static const int SMEM_K2C = (DD * KPAD + CC * KPAD * 2 + 8 * KPAD * 2 + 8 * CC +
                             DD + 3 * CC + 16) * (int)sizeof(float);

extern "C" void kernel_launch(void* const* d_in, const int* in_sizes, int n_in,
                              void* d_out, int out_size) {
    const float* x1   = (const float*)d_in[0];
    const float* mask = (const float*)d_in[2];
    const float* wq   = (const float*)d_in[3];
    const float* bq   = (const float*)d_in[4];
    const float* wk   = (const float*)d_in[5];
    const float* bk   = (const float*)d_in[6];
    const float* wv   = (const float*)d_in[7];
    const float* bv   = (const float*)d_in[8];
    const float* we   = (const float*)d_in[9];
    const float* be   = (const float*)d_in[10];
    const float* wf   = (const float*)d_in[11];
    const float* bf   = (const float*)d_in[12];
    const float* wo   = (const float*)d_in[13];
    const float* bo   = (const float*)d_in[14];
    float* y = (float*)d_out;

    cudaFuncSetAttribute(k1_mma,   cudaFuncAttributeMaxDynamicSharedMemorySize, SMEM_K1);
    cudaFuncSetAttribute(k2c_attn, cudaFuncAttributeMaxDynamicSharedMemorySize, SMEM_K2C);
    cudaFuncSetAttribute(k3f,      cudaFuncAttributeMaxDynamicSharedMemorySize, SMEM_K3F);

    k2a_weights<<<16, 256>>>(we, wk, bk, be, wf, wv, bv, bf, wo);   // launch 0 (zeros G/s)
    k1_mma<<<dim3(16, 8), 512, SMEM_K1>>>(x1);                       // launch 1
    k2c_attn<<<dim3(8, 8), 256, SMEM_K2C>>>(wq, bq);                 // launch 2
    k3f<<<dim3(512, 8), 256, SMEM_K3F>>>(x1, bo, mask, y);           // launch 3
    // 4 launches/invocation -> ncu -s 5 profiles k1_mma of the 2nd invocation
}

// round 15
// speedup vs baseline: 3.6811x; 1.0519x over previous
#include <cuda_runtime.h>
#include <cuda_bf16.h>
#include <cstdint>

#define BB 8
#define DD 128
#define TT 32768
#define CC 64

typedef unsigned short ushort_t;

// ---------------- warp-level bf16 MMA + ldmatrix ----------------
__device__ __forceinline__ void mma_bf16(float* d, const uint32_t* a, const uint32_t* b) {
    asm volatile(
        "mma.sync.aligned.m16n8k16.row.col.f32.bf16.bf16.f32 "
        "{%0,%1,%2,%3}, {%4,%5,%6,%7}, {%8,%9}, {%0,%1,%2,%3};"
        : "+f"(d[0]), "+f"(d[1]), "+f"(d[2]), "+f"(d[3])
        : "r"(a[0]), "r"(a[1]), "r"(a[2]), "r"(a[3]), "r"(b[0]), "r"(b[1]));
}
__device__ __forceinline__ void ldm_x4(uint32_t* r, uint32_t addr) {
    asm volatile("ldmatrix.sync.aligned.m8n8.x4.shared.b16 {%0,%1,%2,%3}, [%4];"
        : "=r"(r[0]), "=r"(r[1]), "=r"(r[2]), "=r"(r[3]) : "r"(addr));
}
__device__ __forceinline__ void ldm_x4t(uint32_t* r, uint32_t addr) {
    asm volatile("ldmatrix.sync.aligned.m8n8.x4.trans.shared.b16 {%0,%1,%2,%3}, [%4];"
        : "=r"(r[0]), "=r"(r[1]), "=r"(r[2]), "=r"(r[3]) : "r"(addr));
}
__device__ __forceinline__ uint32_t pkbf(float v0, float v1) {
    uint32_t r; asm("cvt.rn.bf16x2.f32 %0, %1, %2;" : "=r"(r) : "f"(v1), "f"(v0)); return r;
}
__device__ __forceinline__ uint32_t smem_u32(const void* p) {
    uint32_t a;
    asm("{ .reg .u64 t; cvta.to.shared.u64 t, %1; cvt.u32.u64 %0, t; }" : "=r"(a) : "l"(p));
    return a;
}
// split float4 -> bf16 hi pair + lo (residual) pair
__device__ __forceinline__ void cvt4(const float4 v, uint2& h, uint2& lo) {
    h.x = pkbf(v.x, v.y); h.y = pkbf(v.z, v.w);
    float r0 = v.x - __uint_as_float(h.x << 16);
    float r1 = v.y - __uint_as_float(h.x & 0xFFFF0000u);
    float r2 = v.z - __uint_as_float(h.y << 16);
    float r3 = v.w - __uint_as_float(h.y & 0xFFFF0000u);
    lo.x = pkbf(r0, r1); lo.y = pkbf(r2, r3);
}
// split scalar
__device__ __forceinline__ void cvt1(float v, ushort_t& h, ushort_t& lo) {
    __nv_bfloat16 hb = __float2bfloat16_rn(v);
    h = __bfloat16_as_ushort(hb);
    lo = __bfloat16_as_ushort(__float2bfloat16_rn(v - __bfloat162float(hb)));
}

// ---------------- scratch (static device globals) ----------------
__device__ float g_G[BB * DD * DD];
__device__ float g_s[BB * DD];
__device__ float g_Bm[CC * DD];
__device__ float g_F[CC * DD];
__device__ float g_k0[CC];
__device__ float g_v0[CC];
__device__ float g_cv[BB * CC];
__device__ ushort_t g_Mh[BB * CC * DD];
__device__ ushort_t g_Ml[BB * CC * DD];
__device__ ushort_t g_Wh[DD * CC];
__device__ ushort_t g_Wl[DD * CC];

// ================= K1 (mma.sync bf16 split, 4m x 4n, double-buffered, 144 CTAs) =================
#define TCH  64
#define NCHB 512                    // 64-t chunks per batch
#define K1GX 18                     // CTAs per batch (18*8 = 144 = 1 wave on 148 SMs)
#define KSTR 72
#define A2OFF (16 * KSTR * 2)       // byte offset of second m16 tile
#define K1BUF (2 * DD * KSTR * 2)   // one buffer = hi + lo = 36864 B
#define K1LO  (DD * KSTR * 2)       // lo offset inside a buffer = 18432 B
#define SMEM_K1 (2 * K1BUF)         // 73728 B

__global__ __launch_bounds__(512, 1) void k1_mma(const float* __restrict__ x) {
    extern __shared__ __align__(16) char sm1[];
    const int tid = threadIdx.x;
    const int w   = tid >> 5, l = tid & 31;
    const int g   = l >> 2, tg = l & 3;
    const int q   = l >> 3, i5 = l & 7;
    const int b   = blockIdx.y;
    const int bx  = blockIdx.x;
    const int cs  = (bx * NCHB) / K1GX;        // first chunk (inclusive)
    const int ce  = ((bx + 1) * NCHB) / K1GX;  // last chunk (exclusive)
    const int d   = tid >> 2;
    const int kh  = (tid & 3) * 16;
    const float* xp = x + ((size_t)b * DD + d) * TT + cs * TCH + kh;

    float accP[2][4][4], accC[2][4][4];
#pragma unroll
    for (int mt = 0; mt < 2; mt++)
#pragma unroll
        for (int j = 0; j < 4; j++)
#pragma unroll
            for (int qq = 0; qq < 4; qq++) { accP[mt][j][qq] = 0.f; accC[mt][j][qq] = 0.f; }
    float srow = 0.f;

    const int m0 = (w & 3) * 32;
    const int n0 = (w >> 2) * 32;
    const uint32_t sb0 = smem_u32(sm1);
    const uint32_t aoff = (uint32_t)(((m0 + (q & 1) * 8 + i5) * KSTR + (q >> 1) * 8) * 2);
    const uint32_t boff = (uint32_t)(((n0 + (q >> 1) * 8 + i5) * KSTR + (q & 1) * 8) * 2);
    uint32_t pa[2], pbh[2], pbl[2];
#pragma unroll
    for (int bu = 0; bu < 2; bu++) {
        pa[bu]  = sb0 + bu * K1BUF + aoff;
        pbh[bu] = sb0 + bu * K1BUF + boff;
        pbl[bu] = sb0 + bu * K1BUF + K1LO + boff;
    }
    char* stH[2]; char* stL[2];
#pragma unroll
    for (int bu = 0; bu < 2; bu++) {
        stH[bu] = sm1 + bu * K1BUF + (d * KSTR + kh) * 2;
        stL[bu] = stH[bu] + K1LO;
    }

    const int ncount = ce - cs;
    // prologue: load + convert chunk 0 into buffer 0
    {
        float4 v[4];
#pragma unroll
        for (int ii = 0; ii < 4; ii++) v[ii] = *reinterpret_cast<const float4*>(xp + 4 * ii);
#pragma unroll
        for (int it = 0; it < 4; it++) {
            srow += (v[it].x + v[it].y) + (v[it].z + v[it].w);
            uint2 hv, lv; cvt4(v[it], hv, lv);
            *reinterpret_cast<uint2*>(stH[0] + it * 8) = hv;
            *reinterpret_cast<uint2*>(stL[0] + it * 8) = lv;
        }
    }
    __syncthreads();

    for (int c = 0; c < ncount; c++) {
        const int cur = c & 1, nxt = cur ^ 1;
        float4 r2[4];
        if (c + 1 < ncount) {
            const float* xn = xp + (c + 1) * TCH;
#pragma unroll
            for (int ii = 0; ii < 4; ii++) r2[ii] = *reinterpret_cast<const float4*>(xn + 4 * ii);
        }
#pragma unroll
        for (int ks = 0; ks < 4; ks++) {
            uint32_t ah0[4], ah1[4];
            ldm_x4(ah0, pa[cur] + ks * 32);
            ldm_x4(ah1, pa[cur] + A2OFF + ks * 32);
#pragma unroll
            for (int jp = 0; jp < 2; jp++) {
                const uint32_t bo2 = (uint32_t)(jp * 16 * KSTR * 2 + ks * 32);
                uint32_t bh[4], bl[4];
                ldm_x4(bh, pbh[cur] + bo2);
                ldm_x4(bl, pbl[cur] + bo2);
                mma_bf16(accP[0][2 * jp],     ah0, bh);
                mma_bf16(accP[0][2 * jp + 1], ah0, bh + 2);
                mma_bf16(accP[1][2 * jp],     ah1, bh);
                mma_bf16(accP[1][2 * jp + 1], ah1, bh + 2);
                mma_bf16(accC[0][2 * jp],     ah0, bl);
                mma_bf16(accC[0][2 * jp + 1], ah0, bl + 2);
                mma_bf16(accC[1][2 * jp],     ah1, bl);
                mma_bf16(accC[1][2 * jp + 1], ah1, bl + 2);
            }
        }
        if (c + 1 < ncount) {
#pragma unroll
            for (int it = 0; it < 4; it++) {
                srow += (r2[it].x + r2[it].y) + (r2[it].z + r2[it].w);
                uint2 hv, lv; cvt4(r2[it], hv, lv);
                *reinterpret_cast<uint2*>(stH[nxt] + it * 8) = hv;
                *reinterpret_cast<uint2*>(stL[nxt] + it * 8) = lv;
            }
        }
        __syncthreads();
    }

    float* Gb = g_G + b * DD * DD;
#pragma unroll
    for (int mt = 0; mt < 2; mt++) {
        const int row = m0 + mt * 16 + g;
#pragma unroll
        for (int j = 0; j < 4; j++) {
            const int col = n0 + j * 8 + tg * 2;
            atomicAdd(&Gb[row * DD + col],           accP[mt][j][0] + accC[mt][j][0]);
            atomicAdd(&Gb[row * DD + col + 1],       accP[mt][j][1] + accC[mt][j][1]);
            atomicAdd(&Gb[(row + 8) * DD + col],     accP[mt][j][2] + accC[mt][j][2]);
            atomicAdd(&Gb[(row + 8) * DD + col + 1], accP[mt][j][3] + accC[mt][j][3]);
            atomicAdd(&Gb[col * DD + row],           accC[mt][j][0]);
            atomicAdd(&Gb[(col + 1) * DD + row],     accC[mt][j][1]);
            atomicAdd(&Gb[col * DD + row + 8],       accC[mt][j][2]);
            atomicAdd(&Gb[(col + 1) * DD + row + 8], accC[mt][j][3]);
        }
    }
    atomicAdd(&g_s[b * DD + d], srow);
}

// ============ K2a: zero G/s + weight products + wo bf16 split (grid 16) ============
__global__ void k2a_weights(const float* __restrict__ we, const float* __restrict__ wk,
                            const float* __restrict__ bk, const float* __restrict__ be,
                            const float* __restrict__ wf, const float* __restrict__ wv,
                            const float* __restrict__ bv, const float* __restrict__ bf,
                            const float* __restrict__ wo) {
    const int j = blockIdx.x, tid = threadIdx.x;
    {
        const int gi = j * 256 + tid;
        float4 z = {0.f, 0.f, 0.f, 0.f};
        float4* G4 = reinterpret_cast<float4*>(g_G);
#pragma unroll
        for (int it = 0; it < 8; it++) G4[gi + 4096 * it] = z;
        if (gi < BB * DD) g_s[gi] = 0.f;
    }
    if (j < 8) {
#pragma unroll
        for (int it = 0; it < 4; it++) {
            int idx = tid + 256 * it;
            int o = j * 8 + (idx >> 7);
            int d = idx & 127;
            float acc = 0.f;
            for (int c = 0; c < CC; c++) acc = fmaf(we[o * CC + c], wk[c * DD + d], acc);
            g_Bm[o * DD + d] = acc;
        }
        if (j == 0 && tid < CC) {
            float acc = be[tid];
            for (int c = 0; c < CC; c++) acc = fmaf(we[tid * CC + c], bk[c], acc);
            g_k0[tid] = acc;
        }
        if (j == 1) {
#pragma unroll
            for (int it = 0; it < 32; it++) {
                int idx = tid + 256 * it;
                float v = wo[idx];
                ushort_t h, lo; cvt1(v, h, lo);
                g_Wh[idx] = h; g_Wl[idx] = lo;
            }
        }
    } else {
        int jj = j - 8;
#pragma unroll
        for (int it = 0; it < 4; it++) {
            int idx = tid + 256 * it;
            int o = jj * 8 + (idx >> 7);
            int d = idx & 127;
            float acc = 0.f;
            for (int c = 0; c < CC; c++) acc = fmaf(wf[o * CC + c], wv[c * DD + d], acc);
            g_F[o * DD + d] = acc;
        }
        if (j == 8 && tid < CC) {
            float acc = bf[tid];
            for (int c = 0; c < CC; c++) acc = fmaf(wf[tid * CC + c], bv[c], acc);
            g_v0[tid] = acc;
        }
    }
}

// ============ K2c: AG + S + softmax + M(split) + cv. grid (8 c-groups, 8 b) ============
#define KPAD 132
__global__ void k2c_attn(const float* __restrict__ wq, const float* __restrict__ bq) {
    extern __shared__ float sm2[];
    float* Gs  = sm2;
    float* Bms = Gs  + DD * KPAD;
    float* Fs  = Bms + CC * KPAD;
    float* wqs = Fs  + CC * KPAD;
    float* AGs = wqs + 8 * KPAD;
    float* Ps  = AGs + 8 * KPAD;
    float* ss  = Ps  + 8 * CC;
    float* bs  = ss  + DD;
    float* k0s = bs  + CC;
    float* v0s = k0s + CC;
    float* qs  = v0s + CC;
    float* bqs = qs  + 8;
    const int cg = blockIdx.x, b = blockIdx.y, tid = threadIdx.x;

    const float* Gb = g_G + b * DD * DD;
    for (int i = tid; i < DD * 32; i += 256) {
        int r = i >> 5, c4 = (i & 31) << 2;
        *reinterpret_cast<float4*>(&Gs[r * KPAD + c4]) =
            *reinterpret_cast<const float4*>(&Gb[r * DD + c4]);
    }
    for (int i = tid; i < CC * 32; i += 256) {
        int r = i >> 5, c4 = (i & 31) << 2;
        *reinterpret_cast<float4*>(&Bms[r * KPAD + c4]) =
            *reinterpret_cast<const float4*>(&g_Bm[r * DD + c4]);
        *reinterpret_cast<float4*>(&Fs[r * KPAD + c4]) =
            *reinterpret_cast<const float4*>(&g_F[r * DD + c4]);
    }
    for (int i = tid; i < 8 * 32; i += 256) {
        int r = i >> 5, c4 = (i & 31) << 2;
        *reinterpret_cast<float4*>(&wqs[r * KPAD + c4]) =
            *reinterpret_cast<const float4*>(&wq[(cg * 8 + r) * DD + c4]);
    }
    if (tid < DD) ss[tid] = g_s[b * DD + tid];
    if (tid < CC) { k0s[tid] = g_k0[tid]; v0s[tid] = g_v0[tid]; }
    if (tid < 8)  bqs[tid] = bq[cg * 8 + tid];
    __syncthreads();

    if (tid < CC) {
        float a = 0.f;
        const float* r = &Bms[tid * KPAD];
        for (int d = 0; d < DD; d++) a = fmaf(r[d], ss[d], a);
        bs[tid] = a;
    } else if (tid < CC + 8) {
        int ci = tid - CC;
        float a = 0.f;
        const float* r = &wqs[ci * KPAD];
        for (int d = 0; d < DD; d++) a = fmaf(r[d], ss[d], a);
        qs[ci] = a;
    }
    {
        const int d = tid >> 1, cb = (tid & 1) * 4;
        float a0 = 0.f, a1 = 0.f, a2 = 0.f, a3 = 0.f;
        for (int d1 = 0; d1 < DD; d1++) {
            float g = Gs[d1 * KPAD + d];
            a0 = fmaf(g, wqs[(cb + 0) * KPAD + d1], a0);
            a1 = fmaf(g, wqs[(cb + 1) * KPAD + d1], a1);
            a2 = fmaf(g, wqs[(cb + 2) * KPAD + d1], a2);
            a3 = fmaf(g, wqs[(cb + 3) * KPAD + d1], a3);
        }
        AGs[(cb + 0) * KPAD + d] = a0;
        AGs[(cb + 1) * KPAD + d] = a1;
        AGs[(cb + 2) * KPAD + d] = a2;
        AGs[(cb + 3) * KPAD + d] = a3;
    }
    __syncthreads();

    {
        const int ci = tid >> 5, k = tid & 31;
#pragma unroll
        for (int rep = 0; rep < 2; rep++) {
            int kk = k + rep * 32;
            float acc = 0.f;
            for (int d4 = 0; d4 < 32; d4++) {
                float4 ag = *reinterpret_cast<const float4*>(&AGs[ci * KPAD + d4 * 4]);
                float4 bm = *reinterpret_cast<const float4*>(&Bms[kk * KPAD + d4 * 4]);
                acc = fmaf(ag.x, bm.x, acc); acc = fmaf(ag.y, bm.y, acc);
                acc = fmaf(ag.z, bm.z, acc); acc = fmaf(ag.w, bm.w, acc);
            }
            acc += qs[ci] * k0s[kk] + bqs[ci] * bs[kk] + (float)TT * bqs[ci] * k0s[kk];
            Ps[ci * CC + kk] = acc * 0.125f;
        }
    }
    __syncthreads();

    {
        const int w = tid >> 5, lane = tid & 31;
        float v0 = Ps[w * CC + lane], v1 = Ps[w * CC + lane + 32];
        float m = fmaxf(v0, v1);
#pragma unroll
        for (int off = 16; off; off >>= 1) m = fmaxf(m, __shfl_xor_sync(~0u, m, off));
        float e0 = expf(v0 - m), e1 = expf(v1 - m);
        float sum = e0 + e1;
#pragma unroll
        for (int off = 16; off; off >>= 1) sum += __shfl_xor_sync(~0u, sum, off);
        float inv = 1.f / sum;
        Ps[w * CC + lane]      = e0 * inv;
        Ps[w * CC + lane + 32] = e1 * inv;
    }
    __syncthreads();

    {
        const int d = tid >> 1, cb = (tid & 1) * 4;
        float a[4] = {0.f, 0.f, 0.f, 0.f};
        for (int k = 0; k < CC; k++) {
            float f = Fs[k * KPAD + d];
            a[0] = fmaf(Ps[(cb + 0) * CC + k], f, a[0]);
            a[1] = fmaf(Ps[(cb + 1) * CC + k], f, a[1]);
            a[2] = fmaf(Ps[(cb + 2) * CC + k], f, a[2]);
            a[3] = fmaf(Ps[(cb + 3) * CC + k], f, a[3]);
        }
#pragma unroll
        for (int i = 0; i < 4; i++) {
            ushort_t h, lo; cvt1(a[i], h, lo);
            int idx = b * CC * DD + (cg * 8 + cb + i) * DD + d;
            g_Mh[idx] = h; g_Ml[idx] = lo;
        }
    }
    if (tid < 8) {
        float acc = 0.f;
        for (int k = 0; k < CC; k++) acc = fmaf(Ps[tid * CC + k], v0s[k], acc);
        g_cv[b * CC + cg * 8 + tid] = acc;
    }
}

// ============ K3f (fused, tensor, 3 CTA/SM): y = mask*(wo@relu(M X + cv) + bo) ============
#define TPX 72
#define DPM 136
#define OX_H 0u
#define OX_L 18432u
#define OU_H 0u
#define OU_L 9216u
#define OM_H 36864u
#define OM_L 54272u
#define OW_H 36864u
#define OW_L 55296u
#define SMEM_K3F 73728

__global__ __launch_bounds__(256, 3) void k3f(const float* __restrict__ x,
                                              const float* __restrict__ bo,
                                              const float* __restrict__ mask,
                                              float* __restrict__ y) {
    extern __shared__ __align__(16) char smem[];
    const uint32_t sb = smem_u32(smem);
    const int tid = threadIdx.x;
    const int w = tid >> 5, l = tid & 31;
    const int g = l >> 2, tg = l & 3;
    const int q = l >> 3, i5 = l & 7;
    const int b  = blockIdx.y;
    const int t0 = blockIdx.x * 64;

    {
        const float* xb = x + (size_t)b * DD * TT + t0;
#pragma unroll
        for (int i = 0; i < 8; i++) {
            int f4 = tid + 256 * i;
            int d = f4 >> 4, t4 = (f4 & 15) << 2;
            float4 v = *reinterpret_cast<const float4*>(xb + (size_t)d * TT + t4);
            uint2 hv, lv; cvt4(v, hv, lv);
            *reinterpret_cast<uint2*>(smem + OX_H + (d * TPX + t4) * 2) = hv;
            *reinterpret_cast<uint2*>(smem + OX_L + (d * TPX + t4) * 2) = lv;
        }
        const uint4* Mh = reinterpret_cast<const uint4*>(g_Mh + b * CC * DD);
        const uint4* Ml = reinterpret_cast<const uint4*>(g_Ml + b * CC * DD);
#pragma unroll
        for (int i = 0; i < 4; i++) {
            int f8 = tid + 256 * i;
            int c = f8 >> 4, d8 = (f8 & 15) << 3;
            *reinterpret_cast<uint4*>(smem + OM_H + (c * DPM + d8) * 2) = Mh[f8];
            *reinterpret_cast<uint4*>(smem + OM_L + (c * DPM + d8) * 2) = Ml[f8];
        }
    }
    __syncthreads();

    float accU[4][4];
    const int mw = (w & 3) * 16;
    const int nw = (w >> 2) * 32;
    {
#pragma unroll
        for (int j = 0; j < 4; j++)
#pragma unroll
            for (int qq = 0; qq < 4; qq++) accU[j][qq] = 0.f;

        const uint32_t aoff = (uint32_t)(((mw + (q & 1) * 8 + i5) * DPM + (q >> 1) * 8) * 2);
        const uint32_t pa_h = sb + OM_H + aoff, pa_l = sb + OM_L + aoff;
        const uint32_t boff = (uint32_t)((((q & 1) * 8 + i5) * TPX + nw + (q >> 1) * 8) * 2);
        const uint32_t pb_h = sb + OX_H + boff, pb_l = sb + OX_L + boff;

#pragma unroll
        for (int ks = 0; ks < 8; ks++) {
            uint32_t ah[4], al[4];
            ldm_x4(ah, pa_h + ks * 32);
            ldm_x4(al, pa_l + ks * 32);
#pragma unroll
            for (int jp = 0; jp < 2; jp++) {
                uint32_t off = (uint32_t)(ks * 16 * TPX * 2 + jp * 32);
                uint32_t bh[4], bl[4];
                ldm_x4t(bh, pb_h + off);
                ldm_x4t(bl, pb_l + off);
                mma_bf16(accU[2 * jp],     ah, bh);
                mma_bf16(accU[2 * jp],     ah, bl);
                mma_bf16(accU[2 * jp],     al, bh);
                mma_bf16(accU[2 * jp + 1], ah, bh + 2);
                mma_bf16(accU[2 * jp + 1], ah, bl + 2);
                mma_bf16(accU[2 * jp + 1], al, bh + 2);
            }
        }
    }
    __syncthreads();

    {
        const float cv0 = g_cv[b * CC + mw + g];
        const float cv1 = g_cv[b * CC + mw + g + 8];
#pragma unroll
        for (int j = 0; j < 4; j++) {
            int t = nw + 8 * j + 2 * tg;
            float u00 = fmaxf(accU[j][0] + cv0, 0.f);
            float u01 = fmaxf(accU[j][1] + cv0, 0.f);
            float u10 = fmaxf(accU[j][2] + cv1, 0.f);
            float u11 = fmaxf(accU[j][3] + cv1, 0.f);
            uint32_t h0 = pkbf(u00, u01);
            uint32_t l0 = pkbf(u00 - __uint_as_float(h0 << 16),
                               u01 - __uint_as_float(h0 & 0xFFFF0000u));
            uint32_t h1 = pkbf(u10, u11);
            uint32_t l1 = pkbf(u10 - __uint_as_float(h1 << 16),
                               u11 - __uint_as_float(h1 & 0xFFFF0000u));
            *reinterpret_cast<uint32_t*>(smem + OU_H + ((mw + g) * TPX + t) * 2)     = h0;
            *reinterpret_cast<uint32_t*>(smem + OU_L + ((mw + g) * TPX + t) * 2)     = l0;
            *reinterpret_cast<uint32_t*>(smem + OU_H + ((mw + g + 8) * TPX + t) * 2) = h1;
            *reinterpret_cast<uint32_t*>(smem + OU_L + ((mw + g + 8) * TPX + t) * 2) = l1;
        }
        const uint4* Wh = reinterpret_cast<const uint4*>(g_Wh);
        const uint4* Wl = reinterpret_cast<const uint4*>(g_Wl);
#pragma unroll
        for (int i = 0; i < 4; i++) {
            int f8 = tid + 256 * i;
            int o = f8 >> 3, c8 = (f8 & 7) << 3;
            *reinterpret_cast<uint4*>(smem + OW_H + (o * TPX + c8) * 2) = Wh[f8];
            *reinterpret_cast<uint4*>(smem + OW_L + (o * TPX + c8) * 2) = Wl[f8];
        }
    }
    __syncthreads();

    {
        const int mw2 = (w & 3) * 32;
        const int nw2 = (w >> 2) * 32;
        float acc2[2][4][4];
#pragma unroll
        for (int mt = 0; mt < 2; mt++)
#pragma unroll
            for (int j = 0; j < 4; j++)
#pragma unroll
                for (int qq = 0; qq < 4; qq++) acc2[mt][j][qq] = 0.f;

        const uint32_t aoff2 = (uint32_t)(((mw2 + (q & 1) * 8 + i5) * TPX + (q >> 1) * 8) * 2);
        const uint32_t pa2h = sb + OW_H + aoff2, pa2l = sb + OW_L + aoff2;
        const uint32_t A2 = (uint32_t)(16 * TPX * 2);
        const uint32_t boff2 = (uint32_t)((((q & 1) * 8 + i5) * TPX + nw2 + (q >> 1) * 8) * 2);
        const uint32_t pb2h = sb + OU_H + boff2, pb2l = sb + OU_L + boff2;

#pragma unroll
        for (int ks = 0; ks < 4; ks++) {
            uint32_t ah0[4], al0[4], ah1[4], al1[4];
            ldm_x4(ah0, pa2h + ks * 32);
            ldm_x4(al0, pa2l + ks * 32);
            ldm_x4(ah1, pa2h + A2 + ks * 32);
            ldm_x4(al1, pa2l + A2 + ks * 32);
#pragma unroll
            for (int jp = 0; jp < 2; jp++) {
                uint32_t off = (uint32_t)(ks * 16 * TPX * 2 + jp * 32);
                uint32_t bh[4], bl[4];
                ldm_x4t(bh, pb2h + off);
                ldm_x4t(bl, pb2l + off);
                mma_bf16(acc2[0][2 * jp],     ah0, bh);
                mma_bf16(acc2[0][2 * jp],     ah0, bl);
                mma_bf16(acc2[0][2 * jp],     al0, bh);
                mma_bf16(acc2[0][2 * jp + 1], ah0, bh + 2);
                mma_bf16(acc2[0][2 * jp + 1], ah0, bl + 2);
                mma_bf16(acc2[0][2 * jp + 1], al0, bh + 2);
                mma_bf16(acc2[1][2 * jp],     ah1, bh);
                mma_bf16(acc2[1][2 * jp],     ah1, bl);
                mma_bf16(acc2[1][2 * jp],     al1, bh);
                mma_bf16(acc2[1][2 * jp + 1], ah1, bh + 2);
                mma_bf16(acc2[1][2 * jp + 1], ah1, bl + 2);
                mma_bf16(acc2[1][2 * jp + 1], al1, bh + 2);
            }
        }

        const float* mrow = mask + (size_t)b * TT + t0;
        float* yb = y + (size_t)b * DD * TT + t0;
#pragma unroll
        for (int mt = 0; mt < 2; mt++) {
            const int o = mw2 + mt * 16 + g;
            const float bo0 = bo[o], bo1 = bo[o + 8];
#pragma unroll
            for (int j = 0; j < 4; j++) {
                int t = nw2 + 8 * j + 2 * tg;
                float2 mk = *reinterpret_cast<const float2*>(mrow + t);
                float2 y0, y1;
                y0.x = (acc2[mt][j][0] + bo0) * mk.x;
                y0.y = (acc2[mt][j][1] + bo0) * mk.y;
                y1.x = (acc2[mt][j][2] + bo1) * mk.x;
                y1.y = (acc2[mt][j][3] + bo1) * mk.y;
                *reinterpret_cast<float2*>(yb + (size_t)o * TT + t)       = y0;
                *reinterpret_cast<float2*>(yb + (size_t)(o + 8) * TT + t) = y1;
            }
        }
    }
}

static const int SMEM_K2C = (DD * KPAD + CC * KPAD * 2 + 8 * KPAD * 2 + 8 * CC +
                             DD + 3 * CC + 16) * (int)sizeof(float);

extern "C" void kernel_launch(void* const* d_in, const int* in_sizes, int n_in,
                              void* d_out, int out_size) {
    const float* x1   = (const float*)d_in[0];
    const float* mask = (const float*)d_in[2];
    const float* wq   = (const float*)d_in[3];
    const float* bq   = (const float*)d_in[4];
    const float* wk   = (const float*)d_in[5];
    const float* bk   = (const float*)d_in[6];
    const float* wv   = (const float*)d_in[7];
    const float* bv   = (const float*)d_in[8];
    const float* we   = (const float*)d_in[9];
    const float* be   = (const float*)d_in[10];
    const float* wf   = (const float*)d_in[11];
    const float* bf   = (const float*)d_in[12];
    const float* wo   = (const float*)d_in[13];
    const float* bo   = (const float*)d_in[14];
    float* y = (float*)d_out;

    cudaFuncSetAttribute(k1_mma,   cudaFuncAttributeMaxDynamicSharedMemorySize, SMEM_K1);
    cudaFuncSetAttribute(k2c_attn, cudaFuncAttributeMaxDynamicSharedMemorySize, SMEM_K2C);
    cudaFuncSetAttribute(k3f,      cudaFuncAttributeMaxDynamicSharedMemorySize, SMEM_K3F);

    k2a_weights<<<16, 256>>>(we, wk, bk, be, wf, wv, bv, bf, wo);   // launch 0 (zeros G/s)
    k1_mma<<<dim3(K1GX, 8), 512, SMEM_K1>>>(x1);                     // launch 1 (144 CTAs)
    k2c_attn<<<dim3(8, 8), 256, SMEM_K2C>>>(wq, bq);                 // launch 2
    k3f<<<dim3(512, 8), 256, SMEM_K3F>>>(x1, bo, mask, y);           // launch 3
}

// round 16
// speedup vs baseline: 4.1734x; 1.1337x over previous
#include <cuda_runtime.h>
#include <cuda_bf16.h>
#include <cuda_fp16.h>
#include <cstdint>

#define BB 8
#define DD 128
#define TT 32768
#define CC 64

typedef unsigned short ushort_t;

// ---------------- warp-level MMA + ldmatrix ----------------
__device__ __forceinline__ void mma_bf16(float* d, const uint32_t* a, const uint32_t* b) {
    asm volatile(
        "mma.sync.aligned.m16n8k16.row.col.f32.bf16.bf16.f32 "
        "{%0,%1,%2,%3}, {%4,%5,%6,%7}, {%8,%9}, {%0,%1,%2,%3};"
        : "+f"(d[0]), "+f"(d[1]), "+f"(d[2]), "+f"(d[3])
        : "r"(a[0]), "r"(a[1]), "r"(a[2]), "r"(a[3]), "r"(b[0]), "r"(b[1]));
}
__device__ __forceinline__ void mma_f16(float* d, const uint32_t* a, const uint32_t* b) {
    asm volatile(
        "mma.sync.aligned.m16n8k16.row.col.f32.f16.f16.f32 "
        "{%0,%1,%2,%3}, {%4,%5,%6,%7}, {%8,%9}, {%0,%1,%2,%3};"
        : "+f"(d[0]), "+f"(d[1]), "+f"(d[2]), "+f"(d[3])
        : "r"(a[0]), "r"(a[1]), "r"(a[2]), "r"(a[3]), "r"(b[0]), "r"(b[1]));
}
__device__ __forceinline__ void ldm_x4(uint32_t* r, uint32_t addr) {
    asm volatile("ldmatrix.sync.aligned.m8n8.x4.shared.b16 {%0,%1,%2,%3}, [%4];"
        : "=r"(r[0]), "=r"(r[1]), "=r"(r[2]), "=r"(r[3]) : "r"(addr));
}
__device__ __forceinline__ void ldm_x4t(uint32_t* r, uint32_t addr) {
    asm volatile("ldmatrix.sync.aligned.m8n8.x4.trans.shared.b16 {%0,%1,%2,%3}, [%4];"
        : "=r"(r[0]), "=r"(r[1]), "=r"(r[2]), "=r"(r[3]) : "r"(addr));
}
__device__ __forceinline__ uint32_t pkbf(float v0, float v1) {
    uint32_t r; asm("cvt.rn.bf16x2.f32 %0, %1, %2;" : "=r"(r) : "f"(v1), "f"(v0)); return r;
}
__device__ __forceinline__ uint32_t pkhf(float v0, float v1) {
    uint32_t r; asm("cvt.rn.f16x2.f32 %0, %1, %2;" : "=r"(r) : "f"(v1), "f"(v0)); return r;
}
__device__ __forceinline__ uint32_t smem_u32(const void* p) {
    uint32_t a;
    asm("{ .reg .u64 t; cvta.to.shared.u64 t, %1; cvt.u32.u64 %0, t; }" : "=r"(a) : "l"(p));
    return a;
}
// split float4 -> bf16 hi pair + lo (residual) pair  (k1 only)
__device__ __forceinline__ void cvt4(const float4 v, uint2& h, uint2& lo) {
    h.x = pkbf(v.x, v.y); h.y = pkbf(v.z, v.w);
    float r0 = v.x - __uint_as_float(h.x << 16);
    float r1 = v.y - __uint_as_float(h.x & 0xFFFF0000u);
    float r2 = v.z - __uint_as_float(h.y << 16);
    float r3 = v.w - __uint_as_float(h.y & 0xFFFF0000u);
    lo.x = pkbf(r0, r1); lo.y = pkbf(r2, r3);
}
// split scalar -> fp16 hi/lo  (M, W)
__device__ __forceinline__ void cvt1h(float v, ushort_t& h, ushort_t& lo) {
    __half hb = __float2half_rn(v);
    h = __half_as_ushort(hb);
    lo = __half_as_ushort(__float2half_rn(v - __half2float(hb)));
}

// ---------------- scratch (static device globals) ----------------
__device__ float g_G[BB * DD * DD];
__device__ float g_s[BB * DD];
__device__ float g_Bm[CC * DD];
__device__ float g_F[CC * DD];
__device__ float g_k0[CC];
__device__ float g_v0[CC];
__device__ float g_cv[BB * CC];
__device__ ushort_t g_Mh[BB * CC * DD];   // fp16 hi
__device__ ushort_t g_Ml[BB * CC * DD];   // fp16 lo
__device__ ushort_t g_Wh[DD * CC];        // fp16 hi
__device__ ushort_t g_Wl[DD * CC];        // fp16 lo

// ================= K1 (bf16 split 3-product, unchanged from R15) =================
#define TCH  64
#define NCHB 512
#define K1GX 18
#define KSTR 72
#define A2OFF (16 * KSTR * 2)
#define K1BUF (2 * DD * KSTR * 2)
#define K1LO  (DD * KSTR * 2)
#define SMEM_K1 (2 * K1BUF)

__global__ __launch_bounds__(512, 1) void k1_mma(const float* __restrict__ x) {
    extern __shared__ __align__(16) char sm1[];
    const int tid = threadIdx.x;
    const int w   = tid >> 5, l = tid & 31;
    const int g   = l >> 2, tg = l & 3;
    const int q   = l >> 3, i5 = l & 7;
    const int b   = blockIdx.y;
    const int bx  = blockIdx.x;
    const int cs  = (bx * NCHB) / K1GX;
    const int ce  = ((bx + 1) * NCHB) / K1GX;
    const int d   = tid >> 2;
    const int kh  = (tid & 3) * 16;
    const float* xp = x + ((size_t)b * DD + d) * TT + cs * TCH + kh;

    float accP[2][4][4], accC[2][4][4];
#pragma unroll
    for (int mt = 0; mt < 2; mt++)
#pragma unroll
        for (int j = 0; j < 4; j++)
#pragma unroll
            for (int qq = 0; qq < 4; qq++) { accP[mt][j][qq] = 0.f; accC[mt][j][qq] = 0.f; }
    float srow = 0.f;

    const int m0 = (w & 3) * 32;
    const int n0 = (w >> 2) * 32;
    const uint32_t sb0 = smem_u32(sm1);
    const uint32_t aoff = (uint32_t)(((m0 + (q & 1) * 8 + i5) * KSTR + (q >> 1) * 8) * 2);
    const uint32_t boff = (uint32_t)(((n0 + (q >> 1) * 8 + i5) * KSTR + (q & 1) * 8) * 2);
    uint32_t pa[2], pbh[2], pbl[2];
#pragma unroll
    for (int bu = 0; bu < 2; bu++) {
        pa[bu]  = sb0 + bu * K1BUF + aoff;
        pbh[bu] = sb0 + bu * K1BUF + boff;
        pbl[bu] = sb0 + bu * K1BUF + K1LO + boff;
    }
    char* stH[2]; char* stL[2];
#pragma unroll
    for (int bu = 0; bu < 2; bu++) {
        stH[bu] = sm1 + bu * K1BUF + (d * KSTR + kh) * 2;
        stL[bu] = stH[bu] + K1LO;
    }

    const int ncount = ce - cs;
    {
        float4 v[4];
#pragma unroll
        for (int ii = 0; ii < 4; ii++) v[ii] = *reinterpret_cast<const float4*>(xp + 4 * ii);
#pragma unroll
        for (int it = 0; it < 4; it++) {
            srow += (v[it].x + v[it].y) + (v[it].z + v[it].w);
            uint2 hv, lv; cvt4(v[it], hv, lv);
            *reinterpret_cast<uint2*>(stH[0] + it * 8) = hv;
            *reinterpret_cast<uint2*>(stL[0] + it * 8) = lv;
        }
    }
    __syncthreads();

    for (int c = 0; c < ncount; c++) {
        const int cur = c & 1, nxt = cur ^ 1;
        float4 r2[4];
        if (c + 1 < ncount) {
            const float* xn = xp + (c + 1) * TCH;
#pragma unroll
            for (int ii = 0; ii < 4; ii++) r2[ii] = *reinterpret_cast<const float4*>(xn + 4 * ii);
        }
#pragma unroll
        for (int ks = 0; ks < 4; ks++) {
            uint32_t ah0[4], ah1[4];
            ldm_x4(ah0, pa[cur] + ks * 32);
            ldm_x4(ah1, pa[cur] + A2OFF + ks * 32);
#pragma unroll
            for (int jp = 0; jp < 2; jp++) {
                const uint32_t bo2 = (uint32_t)(jp * 16 * KSTR * 2 + ks * 32);
                uint32_t bh[4], bl[4];
                ldm_x4(bh, pbh[cur] + bo2);
                ldm_x4(bl, pbl[cur] + bo2);
                mma_bf16(accP[0][2 * jp],     ah0, bh);
                mma_bf16(accP[0][2 * jp + 1], ah0, bh + 2);
                mma_bf16(accP[1][2 * jp],     ah1, bh);
                mma_bf16(accP[1][2 * jp + 1], ah1, bh + 2);
                mma_bf16(accC[0][2 * jp],     ah0, bl);
                mma_bf16(accC[0][2 * jp + 1], ah0, bl + 2);
                mma_bf16(accC[1][2 * jp],     ah1, bl);
                mma_bf16(accC[1][2 * jp + 1], ah1, bl + 2);
            }
        }
        if (c + 1 < ncount) {
#pragma unroll
            for (int it = 0; it < 4; it++) {
                srow += (r2[it].x + r2[it].y) + (r2[it].z + r2[it].w);
                uint2 hv, lv; cvt4(r2[it], hv, lv);
                *reinterpret_cast<uint2*>(stH[nxt] + it * 8) = hv;
                *reinterpret_cast<uint2*>(stL[nxt] + it * 8) = lv;
            }
        }
        __syncthreads();
    }

    float* Gb = g_G + b * DD * DD;
#pragma unroll
    for (int mt = 0; mt < 2; mt++) {
        const int row = m0 + mt * 16 + g;
#pragma unroll
        for (int j = 0; j < 4; j++) {
            const int col = n0 + j * 8 + tg * 2;
            atomicAdd(&Gb[row * DD + col],           accP[mt][j][0] + accC[mt][j][0]);
            atomicAdd(&Gb[row * DD + col + 1],       accP[mt][j][1] + accC[mt][j][1]);
            atomicAdd(&Gb[(row + 8) * DD + col],     accP[mt][j][2] + accC[mt][j][2]);
            atomicAdd(&Gb[(row + 8) * DD + col + 1], accP[mt][j][3] + accC[mt][j][3]);
            atomicAdd(&Gb[col * DD + row],           accC[mt][j][0]);
            atomicAdd(&Gb[(col + 1) * DD + row],     accC[mt][j][1]);
            atomicAdd(&Gb[col * DD + row + 8],       accC[mt][j][2]);
            atomicAdd(&Gb[(col + 1) * DD + row + 8], accC[mt][j][3]);
        }
    }
    atomicAdd(&g_s[b * DD + d], srow);
}

// ============ K2a: zero G/s + weight products + wo fp16 split (grid 16) ============
__global__ void k2a_weights(const float* __restrict__ we, const float* __restrict__ wk,
                            const float* __restrict__ bk, const float* __restrict__ be,
                            const float* __restrict__ wf, const float* __restrict__ wv,
                            const float* __restrict__ bv, const float* __restrict__ bf,
                            const float* __restrict__ wo) {
    const int j = blockIdx.x, tid = threadIdx.x;
    {
        const int gi = j * 256 + tid;
        float4 z = {0.f, 0.f, 0.f, 0.f};
        float4* G4 = reinterpret_cast<float4*>(g_G);
#pragma unroll
        for (int it = 0; it < 8; it++) G4[gi + 4096 * it] = z;
        if (gi < BB * DD) g_s[gi] = 0.f;
    }
    if (j < 8) {
#pragma unroll
        for (int it = 0; it < 4; it++) {
            int idx = tid + 256 * it;
            int o = j * 8 + (idx >> 7);
            int d = idx & 127;
            float acc = 0.f;
            for (int c = 0; c < CC; c++) acc = fmaf(we[o * CC + c], wk[c * DD + d], acc);
            g_Bm[o * DD + d] = acc;
        }
        if (j == 0 && tid < CC) {
            float acc = be[tid];
            for (int c = 0; c < CC; c++) acc = fmaf(we[tid * CC + c], bk[c], acc);
            g_k0[tid] = acc;
        }
        if (j == 1) {
#pragma unroll
            for (int it = 0; it < 32; it++) {
                int idx = tid + 256 * it;
                float v = wo[idx];
                ushort_t h, lo; cvt1h(v, h, lo);
                g_Wh[idx] = h; g_Wl[idx] = lo;
            }
        }
    } else {
        int jj = j - 8;
#pragma unroll
        for (int it = 0; it < 4; it++) {
            int idx = tid + 256 * it;
            int o = jj * 8 + (idx >> 7);
            int d = idx & 127;
            float acc = 0.f;
            for (int c = 0; c < CC; c++) acc = fmaf(wf[o * CC + c], wv[c * DD + d], acc);
            g_F[o * DD + d] = acc;
        }
        if (j == 8 && tid < CC) {
            float acc = bf[tid];
            for (int c = 0; c < CC; c++) acc = fmaf(wf[tid * CC + c], bv[c], acc);
            g_v0[tid] = acc;
        }
    }
}

// ============ K2c: AG + S + softmax + M(fp16 split) + cv. grid (8, 8) ============
#define KPAD 132
__global__ void k2c_attn(const float* __restrict__ wq, const float* __restrict__ bq) {
    extern __shared__ float sm2[];
    float* Gs  = sm2;
    float* Bms = Gs  + DD * KPAD;
    float* Fs  = Bms + CC * KPAD;
    float* wqs = Fs  + CC * KPAD;
    float* AGs = wqs + 8 * KPAD;
    float* Ps  = AGs + 8 * KPAD;
    float* ss  = Ps  + 8 * CC;
    float* bs  = ss  + DD;
    float* k0s = bs  + CC;
    float* v0s = k0s + CC;
    float* qs  = v0s + CC;
    float* bqs = qs  + 8;
    const int cg = blockIdx.x, b = blockIdx.y, tid = threadIdx.x;

    const float* Gb = g_G + b * DD * DD;
    for (int i = tid; i < DD * 32; i += 256) {
        int r = i >> 5, c4 = (i & 31) << 2;
        *reinterpret_cast<float4*>(&Gs[r * KPAD + c4]) =
            *reinterpret_cast<const float4*>(&Gb[r * DD + c4]);
    }
    for (int i = tid; i < CC * 32; i += 256) {
        int r = i >> 5, c4 = (i & 31) << 2;
        *reinterpret_cast<float4*>(&Bms[r * KPAD + c4]) =
            *reinterpret_cast<const float4*>(&g_Bm[r * DD + c4]);
        *reinterpret_cast<float4*>(&Fs[r * KPAD + c4]) =
            *reinterpret_cast<const float4*>(&g_F[r * DD + c4]);
    }
    for (int i = tid; i < 8 * 32; i += 256) {
        int r = i >> 5, c4 = (i & 31) << 2;
        *reinterpret_cast<float4*>(&wqs[r * KPAD + c4]) =
            *reinterpret_cast<const float4*>(&wq[(cg * 8 + r) * DD + c4]);
    }
    if (tid < DD) ss[tid] = g_s[b * DD + tid];
    if (tid < CC) { k0s[tid] = g_k0[tid]; v0s[tid] = g_v0[tid]; }
    if (tid < 8)  bqs[tid] = bq[cg * 8 + tid];
    __syncthreads();

    if (tid < CC) {
        float a = 0.f;
        const float* r = &Bms[tid * KPAD];
        for (int d = 0; d < DD; d++) a = fmaf(r[d], ss[d], a);
        bs[tid] = a;
    } else if (tid < CC + 8) {
        int ci = tid - CC;
        float a = 0.f;
        const float* r = &wqs[ci * KPAD];
        for (int d = 0; d < DD; d++) a = fmaf(r[d], ss[d], a);
        qs[ci] = a;
    }
    {
        const int d = tid >> 1, cb = (tid & 1) * 4;
        float a0 = 0.f, a1 = 0.f, a2 = 0.f, a3 = 0.f;
        for (int d1 = 0; d1 < DD; d1++) {
            float g = Gs[d1 * KPAD + d];
            a0 = fmaf(g, wqs[(cb + 0) * KPAD + d1], a0);
            a1 = fmaf(g, wqs[(cb + 1) * KPAD + d1], a1);
            a2 = fmaf(g, wqs[(cb + 2) * KPAD + d1], a2);
            a3 = fmaf(g, wqs[(cb + 3) * KPAD + d1], a3);
        }
        AGs[(cb + 0) * KPAD + d] = a0;
        AGs[(cb + 1) * KPAD + d] = a1;
        AGs[(cb + 2) * KPAD + d] = a2;
        AGs[(cb + 3) * KPAD + d] = a3;
    }
    __syncthreads();

    {
        const int ci = tid >> 5, k = tid & 31;
#pragma unroll
        for (int rep = 0; rep < 2; rep++) {
            int kk = k + rep * 32;
            float acc = 0.f;
            for (int d4 = 0; d4 < 32; d4++) {
                float4 ag = *reinterpret_cast<const float4*>(&AGs[ci * KPAD + d4 * 4]);
                float4 bm = *reinterpret_cast<const float4*>(&Bms[kk * KPAD + d4 * 4]);
                acc = fmaf(ag.x, bm.x, acc); acc = fmaf(ag.y, bm.y, acc);
                acc = fmaf(ag.z, bm.z, acc); acc = fmaf(ag.w, bm.w, acc);
            }
            acc += qs[ci] * k0s[kk] + bqs[ci] * bs[kk] + (float)TT * bqs[ci] * k0s[kk];
            Ps[ci * CC + kk] = acc * 0.125f;
        }
    }
    __syncthreads();

    {
        const int w = tid >> 5, lane = tid & 31;
        float v0 = Ps[w * CC + lane], v1 = Ps[w * CC + lane + 32];
        float m = fmaxf(v0, v1);
#pragma unroll
        for (int off = 16; off; off >>= 1) m = fmaxf(m, __shfl_xor_sync(~0u, m, off));
        float e0 = expf(v0 - m), e1 = expf(v1 - m);
        float sum = e0 + e1;
#pragma unroll
        for (int off = 16; off; off >>= 1) sum += __shfl_xor_sync(~0u, sum, off);
        float inv = 1.f / sum;
        Ps[w * CC + lane]      = e0 * inv;
        Ps[w * CC + lane + 32] = e1 * inv;
    }
    __syncthreads();

    {
        const int d = tid >> 1, cb = (tid & 1) * 4;
        float a[4] = {0.f, 0.f, 0.f, 0.f};
        for (int k = 0; k < CC; k++) {
            float f = Fs[k * KPAD + d];
            a[0] = fmaf(Ps[(cb + 0) * CC + k], f, a[0]);
            a[1] = fmaf(Ps[(cb + 1) * CC + k], f, a[1]);
            a[2] = fmaf(Ps[(cb + 2) * CC + k], f, a[2]);
            a[3] = fmaf(Ps[(cb + 3) * CC + k], f, a[3]);
        }
#pragma unroll
        for (int i = 0; i < 4; i++) {
            ushort_t h, lo; cvt1h(a[i], h, lo);
            int idx = b * CC * DD + (cg * 8 + cb + i) * DD + d;
            g_Mh[idx] = h; g_Ml[idx] = lo;
        }
    }
    if (tid < 8) {
        float acc = 0.f;
        for (int k = 0; k < CC; k++) acc = fmaf(Ps[tid * CC + k], v0s[k], acc);
        g_cv[b * CC + cg * 8 + tid] = acc;
    }
}

// ============ K3f (fp16 2-product, 3 CTA/SM): y = mask*(wo@relu(M X + cv) + bo) ============
// B-side lo operands dropped (X, U hi-only). A-side (M, W) keeps hi+lo.
#define TPX 72
#define DPM 136
#define OX_H 0u                 // X hi: 128 x 72 fp16 = 18432 B (reused for U)
#define OU_H 0u                 // U hi:  64 x 72 fp16 = 9216 B
#define OM_H 18432u             // M hi:  64 x 136 fp16 = 17408 B
#define OM_L 35840u             // M lo
#define OW_H 18432u             // W hi: 128 x 72 fp16 = 18432 B (overwrites M)
#define OW_L 36864u             // W lo
#define SMEM_K3F 55296

__global__ __launch_bounds__(256, 3) void k3f(const float* __restrict__ x,
                                              const float* __restrict__ bo,
                                              const float* __restrict__ mask,
                                              float* __restrict__ y) {
    extern __shared__ __align__(16) char smem[];
    const uint32_t sb = smem_u32(smem);
    const int tid = threadIdx.x;
    const int w = tid >> 5, l = tid & 31;
    const int g = l >> 2, tg = l & 3;
    const int q = l >> 3, i5 = l & 7;
    const int b  = blockIdx.y;
    const int t0 = blockIdx.x * 64;

    // ---- phase 1: convert X hi-only; copy M hi/lo (pre-split fp16) ----
    {
        const float* xb = x + (size_t)b * DD * TT + t0;
#pragma unroll
        for (int i = 0; i < 8; i++) {
            int f4 = tid + 256 * i;
            int d = f4 >> 4, t4 = (f4 & 15) << 2;
            float4 v = *reinterpret_cast<const float4*>(xb + (size_t)d * TT + t4);
            uint2 hv;
            hv.x = pkhf(v.x, v.y); hv.y = pkhf(v.z, v.w);
            *reinterpret_cast<uint2*>(smem + OX_H + (d * TPX + t4) * 2) = hv;
        }
        const uint4* Mh = reinterpret_cast<const uint4*>(g_Mh + b * CC * DD);
        const uint4* Ml = reinterpret_cast<const uint4*>(g_Ml + b * CC * DD);
#pragma unroll
        for (int i = 0; i < 4; i++) {
            int f8 = tid + 256 * i;
            int c = f8 >> 4, d8 = (f8 & 15) << 3;
            *reinterpret_cast<uint4*>(smem + OM_H + (c * DPM + d8) * 2) = Mh[f8];
            *reinterpret_cast<uint4*>(smem + OM_L + (c * DPM + d8) * 2) = Ml[f8];
        }
    }
    __syncthreads();

    // ---- stage 1: accU = (Mh + Ml) Xh ----
    float accU[4][4];
    const int mw = (w & 3) * 16;
    const int nw = (w >> 2) * 32;
    {
#pragma unroll
        for (int j = 0; j < 4; j++)
#pragma unroll
            for (int qq = 0; qq < 4; qq++) accU[j][qq] = 0.f;

        const uint32_t aoff = (uint32_t)(((mw + (q & 1) * 8 + i5) * DPM + (q >> 1) * 8) * 2);
        const uint32_t pa_h = sb + OM_H + aoff, pa_l = sb + OM_L + aoff;
        const uint32_t boff = (uint32_t)((((q & 1) * 8 + i5) * TPX + nw + (q >> 1) * 8) * 2);
        const uint32_t pb_h = sb + OX_H + boff;

#pragma unroll
        for (int ks = 0; ks < 8; ks++) {
            uint32_t ah[4], al[4];
            ldm_x4(ah, pa_h + ks * 32);
            ldm_x4(al, pa_l + ks * 32);
#pragma unroll
            for (int jp = 0; jp < 2; jp++) {
                uint32_t off = (uint32_t)(ks * 16 * TPX * 2 + jp * 32);
                uint32_t bh[4];
                ldm_x4t(bh, pb_h + off);
                mma_f16(accU[2 * jp],     ah, bh);
                mma_f16(accU[2 * jp],     al, bh);
                mma_f16(accU[2 * jp + 1], ah, bh + 2);
                mma_f16(accU[2 * jp + 1], al, bh + 2);
            }
        }
    }
    __syncthreads();

    // ---- phase 3: write U hi-only into region A; copy W hi/lo into region B ----
    {
        const float cv0 = g_cv[b * CC + mw + g];
        const float cv1 = g_cv[b * CC + mw + g + 8];
#pragma unroll
        for (int j = 0; j < 4; j++) {
            int t = nw + 8 * j + 2 * tg;
            float u00 = fmaxf(accU[j][0] + cv0, 0.f);
            float u01 = fmaxf(accU[j][1] + cv0, 0.f);
            float u10 = fmaxf(accU[j][2] + cv1, 0.f);
            float u11 = fmaxf(accU[j][3] + cv1, 0.f);
            *reinterpret_cast<uint32_t*>(smem + OU_H + ((mw + g) * TPX + t) * 2)     = pkhf(u00, u01);
            *reinterpret_cast<uint32_t*>(smem + OU_H + ((mw + g + 8) * TPX + t) * 2) = pkhf(u10, u11);
        }
        const uint4* Wh = reinterpret_cast<const uint4*>(g_Wh);
        const uint4* Wl = reinterpret_cast<const uint4*>(g_Wl);
#pragma unroll
        for (int i = 0; i < 4; i++) {
            int f8 = tid + 256 * i;
            int o = f8 >> 3, c8 = (f8 & 7) << 3;
            *reinterpret_cast<uint4*>(smem + OW_H + (o * TPX + c8) * 2) = Wh[f8];
            *reinterpret_cast<uint4*>(smem + OW_L + (o * TPX + c8) * 2) = Wl[f8];
        }
    }
    __syncthreads();

    // ---- stage 2: y = mask*((Wh + Wl) Uh + bo). 4m x 2n warp grid ----
    {
        const int mw2 = (w & 3) * 32;
        const int nw2 = (w >> 2) * 32;
        float acc2[2][4][4];
#pragma unroll
        for (int mt = 0; mt < 2; mt++)
#pragma unroll
            for (int j = 0; j < 4; j++)
#pragma unroll
                for (int qq = 0; qq < 4; qq++) acc2[mt][j][qq] = 0.f;

        const uint32_t aoff2 = (uint32_t)(((mw2 + (q & 1) * 8 + i5) * TPX + (q >> 1) * 8) * 2);
        const uint32_t pa2h = sb + OW_H + aoff2, pa2l = sb + OW_L + aoff2;
        const uint32_t A2 = (uint32_t)(16 * TPX * 2);
        const uint32_t boff2 = (uint32_t)((((q & 1) * 8 + i5) * TPX + nw2 + (q >> 1) * 8) * 2);
        const uint32_t pb2h = sb + OU_H + boff2;

#pragma unroll
        for (int ks = 0; ks < 4; ks++) {
            uint32_t ah0[4], al0[4], ah1[4], al1[4];
            ldm_x4(ah0, pa2h + ks * 32);
            ldm_x4(al0, pa2l + ks * 32);
            ldm_x4(ah1, pa2h + A2 + ks * 32);
            ldm_x4(al1, pa2l + A2 + ks * 32);
#pragma unroll
            for (int jp = 0; jp < 2; jp++) {
                uint32_t off = (uint32_t)(ks * 16 * TPX * 2 + jp * 32);
                uint32_t bh[4];
                ldm_x4t(bh, pb2h + off);
                mma_f16(acc2[0][2 * jp],     ah0, bh);
                mma_f16(acc2[0][2 * jp],     al0, bh);
                mma_f16(acc2[0][2 * jp + 1], ah0, bh + 2);
                mma_f16(acc2[0][2 * jp + 1], al0, bh + 2);
                mma_f16(acc2[1][2 * jp],     ah1, bh);
                mma_f16(acc2[1][2 * jp],     al1, bh);
                mma_f16(acc2[1][2 * jp + 1], ah1, bh + 2);
                mma_f16(acc2[1][2 * jp + 1], al1, bh + 2);
            }
        }

        const float* mrow = mask + (size_t)b * TT + t0;
        float* yb = y + (size_t)b * DD * TT + t0;
#pragma unroll
        for (int mt = 0; mt < 2; mt++) {
            const int o = mw2 + mt * 16 + g;
            const float bo0 = bo[o], bo1 = bo[o + 8];
#pragma unroll
            for (int j = 0; j < 4; j++) {
                int t = nw2 + 8 * j + 2 * tg;
                float2 mk = *reinterpret_cast<const float2*>(mrow + t);
                float2 y0, y1;
                y0.x = (acc2[mt][j][0] + bo0) * mk.x;
                y0.y = (acc2[mt][j][1] + bo0) * mk.y;
                y1.x = (acc2[mt][j][2] + bo1) * mk.x;
                y1.y = (acc2[mt][j][3] + bo1) * mk.y;
                *reinterpret_cast<float2*>(yb + (size_t)o * TT + t)       = y0;
                *reinterpret_cast<float2*>(yb + (size_t)(o + 8) * TT + t) = y1;
            }
        }
    }
}

static const int SMEM_K2C = (DD * KPAD + CC * KPAD * 2 + 8 * KPAD * 2 + 8 * CC +
                             DD + 3 * CC + 16) * (int)sizeof(float);

extern "C" void kernel_launch(void* const* d_in, const int* in_sizes, int n_in,
                              void* d_out, int out_size) {
    const float* x1   = (const float*)d_in[0];
    const float* mask = (const float*)d_in[2];
    const float* wq   = (const float*)d_in[3];
    const float* bq   = (const float*)d_in[4];
    const float* wk   = (const float*)d_in[5];
    const float* bk   = (const float*)d_in[6];
    const float* wv   = (const float*)d_in[7];
    const float* bv   = (const float*)d_in[8];
    const float* we   = (const float*)d_in[9];
    const float* be   = (const float*)d_in[10];
    const float* wf   = (const float*)d_in[11];
    const float* bf   = (const float*)d_in[12];
    const float* wo   = (const float*)d_in[13];
    const float* bo   = (const float*)d_in[14];
    float* y = (float*)d_out;

    cudaFuncSetAttribute(k1_mma,   cudaFuncAttributeMaxDynamicSharedMemorySize, SMEM_K1);
    cudaFuncSetAttribute(k2c_attn, cudaFuncAttributeMaxDynamicSharedMemorySize, SMEM_K2C);
    cudaFuncSetAttribute(k3f,      cudaFuncAttributeMaxDynamicSharedMemorySize, SMEM_K3F);

    k2a_weights<<<16, 256>>>(we, wk, bk, be, wf, wv, bv, bf, wo);   // launch 0 (zeros G/s)
    k1_mma<<<dim3(K1GX, 8), 512, SMEM_K1>>>(x1);                     // launch 1
    k2c_attn<<<dim3(8, 8), 256, SMEM_K2C>>>(wq, bq);                 // launch 2
    k3f<<<dim3(512, 8), 256, SMEM_K3F>>>(x1, bo, mask, y);           // launch 3
}

// round 17
// speedup vs baseline: 4.5506x; 1.0904x over previous
#include <cuda_runtime.h>
#include <cuda_bf16.h>
#include <cuda_fp16.h>
#include <cstdint>

#define BB 8
#define DD 128
#define TT 32768
#define CC 64

typedef unsigned short ushort_t;

// ---------------- warp-level MMA + ldmatrix ----------------
__device__ __forceinline__ void mma_f16(float* d, const uint32_t* a, const uint32_t* b) {
    asm volatile(
        "mma.sync.aligned.m16n8k16.row.col.f32.f16.f16.f32 "
        "{%0,%1,%2,%3}, {%4,%5,%6,%7}, {%8,%9}, {%0,%1,%2,%3};"
        : "+f"(d[0]), "+f"(d[1]), "+f"(d[2]), "+f"(d[3])
        : "r"(a[0]), "r"(a[1]), "r"(a[2]), "r"(a[3]), "r"(b[0]), "r"(b[1]));
}
__device__ __forceinline__ void ldm_x4(uint32_t* r, uint32_t addr) {
    asm volatile("ldmatrix.sync.aligned.m8n8.x4.shared.b16 {%0,%1,%2,%3}, [%4];"
        : "=r"(r[0]), "=r"(r[1]), "=r"(r[2]), "=r"(r[3]) : "r"(addr));
}
__device__ __forceinline__ void ldm_x4t(uint32_t* r, uint32_t addr) {
    asm volatile("ldmatrix.sync.aligned.m8n8.x4.trans.shared.b16 {%0,%1,%2,%3}, [%4];"
        : "=r"(r[0]), "=r"(r[1]), "=r"(r[2]), "=r"(r[3]) : "r"(addr));
}
__device__ __forceinline__ uint32_t pkhf(float v0, float v1) {
    uint32_t r; asm("cvt.rn.f16x2.f32 %0, %1, %2;" : "=r"(r) : "f"(v1), "f"(v0)); return r;
}
__device__ __forceinline__ uint32_t smem_u32(const void* p) {
    uint32_t a;
    asm("{ .reg .u64 t; cvta.to.shared.u64 t, %1; cvt.u32.u64 %0, t; }" : "=r"(a) : "l"(p));
    return a;
}
// split scalar -> fp16 hi/lo  (M, W)
__device__ __forceinline__ void cvt1h(float v, ushort_t& h, ushort_t& lo) {
    __half hb = __float2half_rn(v);
    h = __half_as_ushort(hb);
    lo = __half_as_ushort(__float2half_rn(v - __half2float(hb)));
}

// ---------------- scratch (static device globals) ----------------
__device__ float g_G[BB * DD * DD];
__device__ float g_s[BB * DD];
__device__ float g_Bm[CC * DD];
__device__ float g_F[CC * DD];
__device__ float g_k0[CC];
__device__ float g_v0[CC];
__device__ float g_cv[BB * CC];
__device__ ushort_t g_Mh[BB * CC * DD];   // fp16 hi
__device__ ushort_t g_Ml[BB * CC * DD];   // fp16 lo
__device__ ushort_t g_Wh[DD * CC];        // fp16 hi
__device__ ushort_t g_Wl[DD * CC];        // fp16 lo

// ================= K1 (fp16 hi-only, 1 product, 4m x 4n, double-buffered) =================
#define TCH  64
#define NCHB 512
#define K1GX 18
#define KSTR 72
#define A2OFF (16 * KSTR * 2)
#define K1BUF (DD * KSTR * 2)       // one buffer = hi only = 18432 B
#define SMEM_K1 (2 * K1BUF)         // 36864 B

__global__ __launch_bounds__(512, 1) void k1_mma(const float* __restrict__ x) {
    extern __shared__ __align__(16) char sm1[];
    const int tid = threadIdx.x;
    const int w   = tid >> 5, l = tid & 31;
    const int g   = l >> 2, tg = l & 3;
    const int q   = l >> 3, i5 = l & 7;
    const int b   = blockIdx.y;
    const int bx  = blockIdx.x;
    const int cs  = (bx * NCHB) / K1GX;
    const int ce  = ((bx + 1) * NCHB) / K1GX;
    const int d   = tid >> 2;
    const int kh  = (tid & 3) * 16;
    const float* xp = x + ((size_t)b * DD + d) * TT + cs * TCH + kh;

    float accP[2][4][4];
#pragma unroll
    for (int mt = 0; mt < 2; mt++)
#pragma unroll
        for (int j = 0; j < 4; j++)
#pragma unroll
            for (int qq = 0; qq < 4; qq++) accP[mt][j][qq] = 0.f;
    float srow = 0.f;

    const int m0 = (w & 3) * 32;
    const int n0 = (w >> 2) * 32;
    const uint32_t sb0 = smem_u32(sm1);
    const uint32_t aoff = (uint32_t)(((m0 + (q & 1) * 8 + i5) * KSTR + (q >> 1) * 8) * 2);
    const uint32_t boff = (uint32_t)(((n0 + (q >> 1) * 8 + i5) * KSTR + (q & 1) * 8) * 2);
    uint32_t pa[2], pb[2];
#pragma unroll
    for (int bu = 0; bu < 2; bu++) {
        pa[bu] = sb0 + bu * K1BUF + aoff;
        pb[bu] = sb0 + bu * K1BUF + boff;
    }
    char* stH[2];
#pragma unroll
    for (int bu = 0; bu < 2; bu++)
        stH[bu] = sm1 + bu * K1BUF + (d * KSTR + kh) * 2;

    const int ncount = ce - cs;
    // prologue: chunk 0 into buffer 0
    {
        float4 v[4];
#pragma unroll
        for (int ii = 0; ii < 4; ii++) v[ii] = *reinterpret_cast<const float4*>(xp + 4 * ii);
#pragma unroll
        for (int it = 0; it < 4; it++) {
            srow += (v[it].x + v[it].y) + (v[it].z + v[it].w);
            uint2 hv;
            hv.x = pkhf(v[it].x, v[it].y);
            hv.y = pkhf(v[it].z, v[it].w);
            *reinterpret_cast<uint2*>(stH[0] + it * 8) = hv;
        }
    }
    __syncthreads();

    for (int c = 0; c < ncount; c++) {
        const int cur = c & 1, nxt = cur ^ 1;
        float4 r2[4];
        if (c + 1 < ncount) {
            const float* xn = xp + (c + 1) * TCH;
#pragma unroll
            for (int ii = 0; ii < 4; ii++) r2[ii] = *reinterpret_cast<const float4*>(xn + 4 * ii);
        }
#pragma unroll
        for (int ks = 0; ks < 4; ks++) {
            uint32_t ah0[4], ah1[4];
            ldm_x4(ah0, pa[cur] + ks * 32);
            ldm_x4(ah1, pa[cur] + A2OFF + ks * 32);
#pragma unroll
            for (int jp = 0; jp < 2; jp++) {
                const uint32_t bo2 = (uint32_t)(jp * 16 * KSTR * 2 + ks * 32);
                uint32_t bh[4];
                ldm_x4(bh, pb[cur] + bo2);
                mma_f16(accP[0][2 * jp],     ah0, bh);
                mma_f16(accP[0][2 * jp + 1], ah0, bh + 2);
                mma_f16(accP[1][2 * jp],     ah1, bh);
                mma_f16(accP[1][2 * jp + 1], ah1, bh + 2);
            }
        }
        if (c + 1 < ncount) {
#pragma unroll
            for (int it = 0; it < 4; it++) {
                srow += (r2[it].x + r2[it].y) + (r2[it].z + r2[it].w);
                uint2 hv;
                hv.x = pkhf(r2[it].x, r2[it].y);
                hv.y = pkhf(r2[it].z, r2[it].w);
                *reinterpret_cast<uint2*>(stH[nxt] + it * 8) = hv;
            }
        }
        __syncthreads();
    }

    float* Gb = g_G + b * DD * DD;
#pragma unroll
    for (int mt = 0; mt < 2; mt++) {
        const int row = m0 + mt * 16 + g;
#pragma unroll
        for (int j = 0; j < 4; j++) {
            const int col = n0 + j * 8 + tg * 2;
            atomicAdd(&Gb[row * DD + col],           accP[mt][j][0]);
            atomicAdd(&Gb[row * DD + col + 1],       accP[mt][j][1]);
            atomicAdd(&Gb[(row + 8) * DD + col],     accP[mt][j][2]);
            atomicAdd(&Gb[(row + 8) * DD + col + 1], accP[mt][j][3]);
        }
    }
    atomicAdd(&g_s[b * DD + d], srow);
}

// ============ K2a: zero G/s + weight products + wo fp16 split (grid 16) ============
__global__ void k2a_weights(const float* __restrict__ we, const float* __restrict__ wk,
                            const float* __restrict__ bk, const float* __restrict__ be,
                            const float* __restrict__ wf, const float* __restrict__ wv,
                            const float* __restrict__ bv, const float* __restrict__ bf,
                            const float* __restrict__ wo) {
    const int j = blockIdx.x, tid = threadIdx.x;
    {
        const int gi = j * 256 + tid;
        float4 z = {0.f, 0.f, 0.f, 0.f};
        float4* G4 = reinterpret_cast<float4*>(g_G);
#pragma unroll
        for (int it = 0; it < 8; it++) G4[gi + 4096 * it] = z;
        if (gi < BB * DD) g_s[gi] = 0.f;
    }
    if (j < 8) {
#pragma unroll
        for (int it = 0; it < 4; it++) {
            int idx = tid + 256 * it;
            int o = j * 8 + (idx >> 7);
            int d = idx & 127;
            float acc = 0.f;
            for (int c = 0; c < CC; c++) acc = fmaf(we[o * CC + c], wk[c * DD + d], acc);
            g_Bm[o * DD + d] = acc;
        }
        if (j == 0 && tid < CC) {
            float acc = be[tid];
            for (int c = 0; c < CC; c++) acc = fmaf(we[tid * CC + c], bk[c], acc);
            g_k0[tid] = acc;
        }
        if (j == 1) {
#pragma unroll
            for (int it = 0; it < 32; it++) {
                int idx = tid + 256 * it;
                float v = wo[idx];
                ushort_t h, lo; cvt1h(v, h, lo);
                g_Wh[idx] = h; g_Wl[idx] = lo;
            }
        }
    } else {
        int jj = j - 8;
#pragma unroll
        for (int it = 0; it < 4; it++) {
            int idx = tid + 256 * it;
            int o = jj * 8 + (idx >> 7);
            int d = idx & 127;
            float acc = 0.f;
            for (int c = 0; c < CC; c++) acc = fmaf(wf[o * CC + c], wv[c * DD + d], acc);
            g_F[o * DD + d] = acc;
        }
        if (j == 8 && tid < CC) {
            float acc = bf[tid];
            for (int c = 0; c < CC; c++) acc = fmaf(wf[tid * CC + c], bv[c], acc);
            g_v0[tid] = acc;
        }
    }
}

// ============ K2c: AG + S + softmax + M(fp16 split) + cv. grid (8, 8) ============
#define KPAD 132
__global__ void k2c_attn(const float* __restrict__ wq, const float* __restrict__ bq) {
    extern __shared__ float sm2[];
    float* Gs  = sm2;
    float* Bms = Gs  + DD * KPAD;
    float* Fs  = Bms + CC * KPAD;
    float* wqs = Fs  + CC * KPAD;
    float* AGs = wqs + 8 * KPAD;
    float* Ps  = AGs + 8 * KPAD;
    float* ss  = Ps  + 8 * CC;
    float* bs  = ss  + DD;
    float* k0s = bs  + CC;
    float* v0s = k0s + CC;
    float* qs  = v0s + CC;
    float* bqs = qs  + 8;
    const int cg = blockIdx.x, b = blockIdx.y, tid = threadIdx.x;

    const float* Gb = g_G + b * DD * DD;
    for (int i = tid; i < DD * 32; i += 256) {
        int r = i >> 5, c4 = (i & 31) << 2;
        *reinterpret_cast<float4*>(&Gs[r * KPAD + c4]) =
            *reinterpret_cast<const float4*>(&Gb[r * DD + c4]);
    }
    for (int i = tid; i < CC * 32; i += 256) {
        int r = i >> 5, c4 = (i & 31) << 2;
        *reinterpret_cast<float4*>(&Bms[r * KPAD + c4]) =
            *reinterpret_cast<const float4*>(&g_Bm[r * DD + c4]);
        *reinterpret_cast<float4*>(&Fs[r * KPAD + c4]) =
            *reinterpret_cast<const float4*>(&g_F[r * DD + c4]);
    }
    for (int i = tid; i < 8 * 32; i += 256) {
        int r = i >> 5, c4 = (i & 31) << 2;
        *reinterpret_cast<float4*>(&wqs[r * KPAD + c4]) =
            *reinterpret_cast<const float4*>(&wq[(cg * 8 + r) * DD + c4]);
    }
    if (tid < DD) ss[tid] = g_s[b * DD + tid];
    if (tid < CC) { k0s[tid] = g_k0[tid]; v0s[tid] = g_v0[tid]; }
    if (tid < 8)  bqs[tid] = bq[cg * 8 + tid];
    __syncthreads();

    if (tid < CC) {
        float a = 0.f;
        const float* r = &Bms[tid * KPAD];
        for (int d = 0; d < DD; d++) a = fmaf(r[d], ss[d], a);
        bs[tid] = a;
    } else if (tid < CC + 8) {
        int ci = tid - CC;
        float a = 0.f;
        const float* r = &wqs[ci * KPAD];
        for (int d = 0; d < DD; d++) a = fmaf(r[d], ss[d], a);
        qs[ci] = a;
    }
    {
        const int d = tid >> 1, cb = (tid & 1) * 4;
        float a0 = 0.f, a1 = 0.f, a2 = 0.f, a3 = 0.f;
        for (int d1 = 0; d1 < DD; d1++) {
            float g = Gs[d1 * KPAD + d];
            a0 = fmaf(g, wqs[(cb + 0) * KPAD + d1], a0);
            a1 = fmaf(g, wqs[(cb + 1) * KPAD + d1], a1);
            a2 = fmaf(g, wqs[(cb + 2) * KPAD + d1], a2);
            a3 = fmaf(g, wqs[(cb + 3) * KPAD + d1], a3);
        }
        AGs[(cb + 0) * KPAD + d] = a0;
        AGs[(cb + 1) * KPAD + d] = a1;
        AGs[(cb + 2) * KPAD + d] = a2;
        AGs[(cb + 3) * KPAD + d] = a3;
    }
    __syncthreads();

    {
        const int ci = tid >> 5, k = tid & 31;
#pragma unroll
        for (int rep = 0; rep < 2; rep++) {
            int kk = k + rep * 32;
            float acc = 0.f;
            for (int d4 = 0; d4 < 32; d4++) {
                float4 ag = *reinterpret_cast<const float4*>(&AGs[ci * KPAD + d4 * 4]);
                float4 bm = *reinterpret_cast<const float4*>(&Bms[kk * KPAD + d4 * 4]);
                acc = fmaf(ag.x, bm.x, acc); acc = fmaf(ag.y, bm.y, acc);
                acc = fmaf(ag.z, bm.z, acc); acc = fmaf(ag.w, bm.w, acc);
            }
            acc += qs[ci] * k0s[kk] + bqs[ci] * bs[kk] + (float)TT * bqs[ci] * k0s[kk];
            Ps[ci * CC + kk] = acc * 0.125f;
        }
    }
    __syncthreads();

    {
        const int w = tid >> 5, lane = tid & 31;
        float v0 = Ps[w * CC + lane], v1 = Ps[w * CC + lane + 32];
        float m = fmaxf(v0, v1);
#pragma unroll
        for (int off = 16; off; off >>= 1) m = fmaxf(m, __shfl_xor_sync(~0u, m, off));
        float e0 = expf(v0 - m), e1 = expf(v1 - m);
        float sum = e0 + e1;
#pragma unroll
        for (int off = 16; off; off >>= 1) sum += __shfl_xor_sync(~0u, sum, off);
        float inv = 1.f / sum;
        Ps[w * CC + lane]      = e0 * inv;
        Ps[w * CC + lane + 32] = e1 * inv;
    }
    __syncthreads();

    {
        const int d = tid >> 1, cb = (tid & 1) * 4;
        float a[4] = {0.f, 0.f, 0.f, 0.f};
        for (int k = 0; k < CC; k++) {
            float f = Fs[k * KPAD + d];
            a[0] = fmaf(Ps[(cb + 0) * CC + k], f, a[0]);
            a[1] = fmaf(Ps[(cb + 1) * CC + k], f, a[1]);
            a[2] = fmaf(Ps[(cb + 2) * CC + k], f, a[2]);
            a[3] = fmaf(Ps[(cb + 3) * CC + k], f, a[3]);
        }
#pragma unroll
        for (int i = 0; i < 4; i++) {
            ushort_t h, lo; cvt1h(a[i], h, lo);
            int idx = b * CC * DD + (cg * 8 + cb + i) * DD + d;
            g_Mh[idx] = h; g_Ml[idx] = lo;
        }
    }
    if (tid < 8) {
        float acc = 0.f;
        for (int k = 0; k < CC; k++) acc = fmaf(Ps[tid * CC + k], v0s[k], acc);
        g_cv[b * CC + cg * 8 + tid] = acc;
    }
}

// ============ K3f (fp16 2-product, 3 CTA/SM): y = mask*(wo@relu(M X + cv) + bo) ============
#define TPX 72
#define DPM 136
#define OX_H 0u
#define OU_H 0u
#define OM_H 18432u
#define OM_L 35840u
#define OW_H 18432u
#define OW_L 36864u
#define SMEM_K3F 55296

__global__ __launch_bounds__(256, 3) void k3f(const float* __restrict__ x,
                                              const float* __restrict__ bo,
                                              const float* __restrict__ mask,
                                              float* __restrict__ y) {
    extern __shared__ __align__(16) char smem[];
    const uint32_t sb = smem_u32(smem);
    const int tid = threadIdx.x;
    const int w = tid >> 5, l = tid & 31;
    const int g = l >> 2, tg = l & 3;
    const int q = l >> 3, i5 = l & 7;
    const int b  = blockIdx.y;
    const int t0 = blockIdx.x * 64;

    {
        const float* xb = x + (size_t)b * DD * TT + t0;
#pragma unroll
        for (int i = 0; i < 8; i++) {
            int f4 = tid + 256 * i;
            int d = f4 >> 4, t4 = (f4 & 15) << 2;
            float4 v = *reinterpret_cast<const float4*>(xb + (size_t)d * TT + t4);
            uint2 hv;
            hv.x = pkhf(v.x, v.y); hv.y = pkhf(v.z, v.w);
            *reinterpret_cast<uint2*>(smem + OX_H + (d * TPX + t4) * 2) = hv;
        }
        const uint4* Mh = reinterpret_cast<const uint4*>(g_Mh + b * CC * DD);
        const uint4* Ml = reinterpret_cast<const uint4*>(g_Ml + b * CC * DD);
#pragma unroll
        for (int i = 0; i < 4; i++) {
            int f8 = tid + 256 * i;
            int c = f8 >> 4, d8 = (f8 & 15) << 3;
            *reinterpret_cast<uint4*>(smem + OM_H + (c * DPM + d8) * 2) = Mh[f8];
            *reinterpret_cast<uint4*>(smem + OM_L + (c * DPM + d8) * 2) = Ml[f8];
        }
    }
    __syncthreads();

    float accU[4][4];
    const int mw = (w & 3) * 16;
    const int nw = (w >> 2) * 32;
    {
#pragma unroll
        for (int j = 0; j < 4; j++)
#pragma unroll
            for (int qq = 0; qq < 4; qq++) accU[j][qq] = 0.f;

        const uint32_t aoff = (uint32_t)(((mw + (q & 1) * 8 + i5) * DPM + (q >> 1) * 8) * 2);
        const uint32_t pa_h = sb + OM_H + aoff, pa_l = sb + OM_L + aoff;
        const uint32_t boff = (uint32_t)((((q & 1) * 8 + i5) * TPX + nw + (q >> 1) * 8) * 2);
        const uint32_t pb_h = sb + OX_H + boff;

#pragma unroll
        for (int ks = 0; ks < 8; ks++) {
            uint32_t ah[4], al[4];
            ldm_x4(ah, pa_h + ks * 32);
            ldm_x4(al, pa_l + ks * 32);
#pragma unroll
            for (int jp = 0; jp < 2; jp++) {
                uint32_t off = (uint32_t)(ks * 16 * TPX * 2 + jp * 32);
                uint32_t bh[4];
                ldm_x4t(bh, pb_h + off);
                mma_f16(accU[2 * jp],     ah, bh);
                mma_f16(accU[2 * jp],     al, bh);
                mma_f16(accU[2 * jp + 1], ah, bh + 2);
                mma_f16(accU[2 * jp + 1], al, bh + 2);
            }
        }
    }
    __syncthreads();

    {
        const float cv0 = g_cv[b * CC + mw + g];
        const float cv1 = g_cv[b * CC + mw + g + 8];
#pragma unroll
        for (int j = 0; j < 4; j++) {
            int t = nw + 8 * j + 2 * tg;
            float u00 = fmaxf(accU[j][0] + cv0, 0.f);
            float u01 = fmaxf(accU[j][1] + cv0, 0.f);
            float u10 = fmaxf(accU[j][2] + cv1, 0.f);
            float u11 = fmaxf(accU[j][3] + cv1, 0.f);
            *reinterpret_cast<uint32_t*>(smem + OU_H + ((mw + g) * TPX + t) * 2)     = pkhf(u00, u01);
            *reinterpret_cast<uint32_t*>(smem + OU_H + ((mw + g + 8) * TPX + t) * 2) = pkhf(u10, u11);
        }
        const uint4* Wh = reinterpret_cast<const uint4*>(g_Wh);
        const uint4* Wl = reinterpret_cast<const uint4*>(g_Wl);
#pragma unroll
        for (int i = 0; i < 4; i++) {
            int f8 = tid + 256 * i;
            int o = f8 >> 3, c8 = (f8 & 7) << 3;
            *reinterpret_cast<uint4*>(smem + OW_H + (o * TPX + c8) * 2) = Wh[f8];
            *reinterpret_cast<uint4*>(smem + OW_L + (o * TPX + c8) * 2) = Wl[f8];
        }
    }
    __syncthreads();

    {
        const int mw2 = (w & 3) * 32;
        const int nw2 = (w >> 2) * 32;
        float acc2[2][4][4];
#pragma unroll
        for (int mt = 0; mt < 2; mt++)
#pragma unroll
            for (int j = 0; j < 4; j++)
#pragma unroll
                for (int qq = 0; qq < 4; qq++) acc2[mt][j][qq] = 0.f;

        const uint32_t aoff2 = (uint32_t)(((mw2 + (q & 1) * 8 + i5) * TPX + (q >> 1) * 8) * 2);
        const uint32_t pa2h = sb + OW_H + aoff2, pa2l = sb + OW_L + aoff2;
        const uint32_t A2 = (uint32_t)(16 * TPX * 2);
        const uint32_t boff2 = (uint32_t)((((q & 1) * 8 + i5) * TPX + nw2 + (q >> 1) * 8) * 2);
        const uint32_t pb2h = sb + OU_H + boff2;

#pragma unroll
        for (int ks = 0; ks < 4; ks++) {
            uint32_t ah0[4], al0[4], ah1[4], al1[4];
            ldm_x4(ah0, pa2h + ks * 32);
            ldm_x4(al0, pa2l + ks * 32);
            ldm_x4(ah1, pa2h + A2 + ks * 32);
            ldm_x4(al1, pa2l + A2 + ks * 32);
#pragma unroll
            for (int jp = 0; jp < 2; jp++) {
                uint32_t off = (uint32_t)(ks * 16 * TPX * 2 + jp * 32);
                uint32_t bh[4];
                ldm_x4t(bh, pb2h + off);
                mma_f16(acc2[0][2 * jp],     ah0, bh);
                mma_f16(acc2[0][2 * jp],     al0, bh);
                mma_f16(acc2[0][2 * jp + 1], ah0, bh + 2);
                mma_f16(acc2[0][2 * jp + 1], al0, bh + 2);
                mma_f16(acc2[1][2 * jp],     ah1, bh);
                mma_f16(acc2[1][2 * jp],     al1, bh);
                mma_f16(acc2[1][2 * jp + 1], ah1, bh + 2);
                mma_f16(acc2[1][2 * jp + 1], al1, bh + 2);
            }
        }

        const float* mrow = mask + (size_t)b * TT + t0;
        float* yb = y + (size_t)b * DD * TT + t0;
#pragma unroll
        for (int mt = 0; mt < 2; mt++) {
            const int o = mw2 + mt * 16 + g;
            const float bo0 = bo[o], bo1 = bo[o + 8];
#pragma unroll
            for (int j = 0; j < 4; j++) {
                int t = nw2 + 8 * j + 2 * tg;
                float2 mk = *reinterpret_cast<const float2*>(mrow + t);
                float2 y0, y1;
                y0.x = (acc2[mt][j][0] + bo0) * mk.x;
                y0.y = (acc2[mt][j][1] + bo0) * mk.y;
                y1.x = (acc2[mt][j][2] + bo1) * mk.x;
                y1.y = (acc2[mt][j][3] + bo1) * mk.y;
                *reinterpret_cast<float2*>(yb + (size_t)o * TT + t)       = y0;
                *reinterpret_cast<float2*>(yb + (size_t)(o + 8) * TT + t) = y1;
            }
        }
    }
}

static const int SMEM_K2C = (DD * KPAD + CC * KPAD * 2 + 8 * KPAD * 2 + 8 * CC +
                             DD + 3 * CC + 16) * (int)sizeof(float);

extern "C" void kernel_launch(void* const* d_in, const int* in_sizes, int n_in,
                              void* d_out, int out_size) {
    const float* x1   = (const float*)d_in[0];
    const float* mask = (const float*)d_in[2];
    const float* wq   = (const float*)d_in[3];
    const float* bq   = (const float*)d_in[4];
    const float* wk   = (const float*)d_in[5];
    const float* bk   = (const float*)d_in[6];
    const float* wv   = (const float*)d_in[7];
    const float* bv   = (const float*)d_in[8];
    const float* we   = (const float*)d_in[9];
    const float* be   = (const float*)d_in[10];
    const float* wf   = (const float*)d_in[11];
    const float* bf   = (const float*)d_in[12];
    const float* wo   = (const float*)d_in[13];
    const float* bo   = (const float*)d_in[14];
    float* y = (float*)d_out;

    cudaFuncSetAttribute(k1_mma,   cudaFuncAttributeMaxDynamicSharedMemorySize, SMEM_K1);
    cudaFuncSetAttribute(k2c_attn, cudaFuncAttributeMaxDynamicSharedMemorySize, SMEM_K2C);
    cudaFuncSetAttribute(k3f,      cudaFuncAttributeMaxDynamicSharedMemorySize, SMEM_K3F);

    k2a_weights<<<16, 256>>>(we, wk, bk, be, wf, wv, bv, bf, wo);   // launch 0 (zeros G/s)
    k1_mma<<<dim3(K1GX, 8), 512, SMEM_K1>>>(x1);                     // launch 1
    k2c_attn<<<dim3(8, 8), 256, SMEM_K2C>>>(wq, bq);                 // launch 2
    k3f<<<dim3(512, 8), 256, SMEM_K3F>>>(x1, bo, mask, y);           // launch 3
}